// round 6
// baseline (speedup 1.0000x reference)
#include <cuda_runtime.h>
#include <cuda_bf16.h>
#include <math.h>

// ---------------------------------------------------------------------------
// Problem constants (fixed by dataset)
// ---------------------------------------------------------------------------
#define MAXN 100000
#define MAXE 400000
#define FMAX 1024

// ---------------------------------------------------------------------------
// Device scratch (__device__ globals; never touched from host APIs)
// ---------------------------------------------------------------------------
__device__ int   g_is64;               // edge_index dtype flag (1 = int64)
__device__ int   g_src[MAXE];
__device__ int   g_dst[MAXE];
__device__ float g_deg[MAXN];
__device__ float g_dis[MAXN];          // deg^-1/2
__device__ float g_dinv[MAXN];         // 1/deg
__device__ float g_norm[MAXE];         // dis[src]*dis[dst]
__device__ float g_H[MAXN * FMAX];     // post-GEMM features
__device__ float g_A[MAXN * FMAX];     // aggregation / next-layer input
__device__ float g_outpad[MAXN * 128]; // padded classifier output
__device__ float g_Wcp[128 * 128];     // Wc padded 128x100 -> 128x128
__device__ float g_bcp[128];

// ---------------------------------------------------------------------------
// Edge-index dtype sniff + decode (robust to int32 OR int64 edge_index)
// Under int64 layout, every odd int32 word is a zero high-half (values<2^31).
// ---------------------------------------------------------------------------
__global__ void k_sniff(const int* __restrict__ ei) {
    if (threadIdx.x == 0 && blockIdx.x == 0) {
        int acc = 0;
#pragma unroll
        for (int i = 0; i < 64; i++) acc |= ei[2 * i + 1];
        g_is64 = (acc == 0) ? 1 : 0;
    }
}

__global__ void k_decode(const int* __restrict__ ei, int E) {
    int e = blockIdx.x * blockDim.x + threadIdx.x;
    if (e >= E) return;
    if (g_is64) {
        g_src[e] = ei[2 * e];            // low word of src[e]
        g_dst[e] = ei[2 * (E + e)];      // low word of dst[e]
    } else {
        g_src[e] = ei[e];
        g_dst[e] = ei[E + e];
    }
}

// ---------------------------------------------------------------------------
// Degree / norm kernels (int32 src/dst from scratch)
// ---------------------------------------------------------------------------
__global__ void k_deg_init(int n) {
    int i = blockIdx.x * blockDim.x + threadIdx.x;
    if (i < n) g_deg[i] = 1.0f;  // self loop
}

__global__ void k_deg_acc(int E) {
    int e = blockIdx.x * blockDim.x + threadIdx.x;
    if (e < E) atomicAdd(&g_deg[g_dst[e]], 1.0f);
}

__global__ void k_deg_fin(int n) {
    int i = blockIdx.x * blockDim.x + threadIdx.x;
    if (i < n) {
        float d = g_deg[i];
        g_dis[i]  = rsqrtf(d);
        g_dinv[i] = 1.0f / d;
    }
}

__global__ void k_norm(int E) {
    int e = blockIdx.x * blockDim.x + threadIdx.x;
    if (e < E) g_norm[e] = g_dis[g_src[e]] * g_dis[g_dst[e]];
}

// ---------------------------------------------------------------------------
// SGEMM: C[N,M] = A[N,K] @ B[K,M]   (fp32, 128x128x8, TM=TN=8, 256 threads)
// ASEL: 0 = Aext, 1 = g_A
// BSEL: 0 = Bext, 1 = g_Wcp
// EPI : 0 = store g_H and g_A = v*dinv[row] (fused self-loop init)
//       1 = store sigmoid(v + g_bcp) into g_outpad (classifier)
// Requirements: K % 8 == 0, M % 128 == 0
// ---------------------------------------------------------------------------
template <int ASEL, int BSEL, int EPI>
__global__ __launch_bounds__(256) void sgemm_k(
    const float* __restrict__ Aext, const float* __restrict__ Bext,
    int N, int K, int M)
{
    const float* A = (ASEL == 0) ? Aext : (const float*)g_A;
    const float* B = (BSEL == 0) ? Bext : (const float*)g_Wcp;

    __shared__ float As[8][128];
    __shared__ float Bs[8][128];

    const int tid = threadIdx.x;
    const int tx = tid & 15;        // 0..15  -> col group
    const int ty = tid >> 4;        // 0..15  -> row group
    const int rBase = blockIdx.y * 128;
    const int cBase = blockIdx.x * 128;

    const int aRow = tid >> 1;          // 0..127
    const int aCol = (tid & 1) * 4;     // 0 or 4
    const int bRow = tid >> 5;          // 0..7
    const int bCol = (tid & 31) * 4;    // 0..124

    float acc[8][8];
#pragma unroll
    for (int i = 0; i < 8; i++)
#pragma unroll
        for (int j = 0; j < 8; j++) acc[i][j] = 0.0f;

    const int gr_a = rBase + aRow;
    const bool aOK = (gr_a < N);
    const float* Aptr = A + (size_t)gr_a * K + aCol;
    const float* Bptr = B + (size_t)bRow * M + cBase + bCol;

    for (int k0 = 0; k0 < K; k0 += 8) {
        float4 av = make_float4(0.f, 0.f, 0.f, 0.f);
        if (aOK) av = *(const float4*)(Aptr + k0);
        As[aCol + 0][aRow] = av.x;
        As[aCol + 1][aRow] = av.y;
        As[aCol + 2][aRow] = av.z;
        As[aCol + 3][aRow] = av.w;

        float4 bv = *(const float4*)(Bptr + (size_t)k0 * M);
        *(float4*)&Bs[bRow][bCol] = bv;

        __syncthreads();

#pragma unroll
        for (int kk = 0; kk < 8; kk++) {
            float ar[8], br[8];
#pragma unroll
            for (int i = 0; i < 8; i++) ar[i] = As[kk][ty * 8 + i];
#pragma unroll
            for (int j = 0; j < 8; j++) br[j] = Bs[kk][tx * 8 + j];
#pragma unroll
            for (int i = 0; i < 8; i++)
#pragma unroll
                for (int j = 0; j < 8; j++)
                    acc[i][j] = fmaf(ar[i], br[j], acc[i][j]);
        }
        __syncthreads();
    }

#pragma unroll
    for (int i = 0; i < 8; i++) {
        int gr = rBase + ty * 8 + i;
        if (gr >= N) continue;
        float s = (EPI == 0) ? g_dinv[gr] : 0.0f;
#pragma unroll
        for (int j = 0; j < 8; j += 4) {
            int gc = cBase + tx * 8 + j;
            float4 v;
            v.x = acc[i][j + 0];
            v.y = acc[i][j + 1];
            v.z = acc[i][j + 2];
            v.w = acc[i][j + 3];
            if (EPI == 0) {
                *(float4*)((float*)g_H + (size_t)gr * M + gc) = v;
                float4 w;
                w.x = v.x * s; w.y = v.y * s; w.z = v.z * s; w.w = v.w * s;
                *(float4*)((float*)g_A + (size_t)gr * M + gc) = w;
            } else {
                v.x = 1.0f / (1.0f + expf(-(v.x + g_bcp[gc + 0])));
                v.y = 1.0f / (1.0f + expf(-(v.y + g_bcp[gc + 1])));
                v.z = 1.0f / (1.0f + expf(-(v.z + g_bcp[gc + 2])));
                v.w = 1.0f / (1.0f + expf(-(v.w + g_bcp[gc + 3])));
                *(float4*)((float*)g_outpad + (size_t)gr * 128 + gc) = v;
            }
        }
    }
}

// ---------------------------------------------------------------------------
// Edge scatter: g_A[dst] += g_H[src] * g_norm[e], float4/thread, f fastest
// ---------------------------------------------------------------------------
__global__ void k_scatter(int E, int F) {
    size_t idx = (size_t)blockIdx.x * blockDim.x + threadIdx.x;
    int f4 = F >> 2;
    size_t tot = (size_t)E * f4;
    if (idx >= tot) return;
    int e = (int)(idx / f4);
    int f = (int)(idx - (size_t)e * f4) * 4;
    int s = g_src[e];
    int d = g_dst[e];
    float w = g_norm[e];
    float4 v = *(const float4*)((const float*)g_H + (size_t)s * F + f);
    float* a = (float*)g_A + (size_t)d * F + f;
    atomicAdd(a + 0, v.x * w);
    atomicAdd(a + 1, v.y * w);
    atomicAdd(a + 2, v.z * w);
    atomicAdd(a + 3, v.w * w);
}

// ---------------------------------------------------------------------------
// Finalize: O = tanh(g_A + bias).  OSEL: 0 = in-place g_A, 1 = Oext
// ---------------------------------------------------------------------------
template <int OSEL>
__global__ void k_final(const float* __restrict__ bias, float* __restrict__ Oext,
                        int N, int F) {
    size_t idx = (size_t)blockIdx.x * blockDim.x + threadIdx.x;
    int f4 = F >> 2;
    size_t tot = (size_t)N * f4;
    if (idx >= tot) return;
    int f = (int)(idx % f4) * 4;
    float4 v = ((const float4*)g_A)[idx];
    v.x = tanhf(v.x + bias[f + 0]);
    v.y = tanhf(v.y + bias[f + 1]);
    v.z = tanhf(v.z + bias[f + 2]);
    v.w = tanhf(v.w + bias[f + 3]);
    float* O = (OSEL == 0) ? (float*)g_A : Oext;
    ((float4*)O)[idx] = v;
}

// ---------------------------------------------------------------------------
// Classifier helpers: pad Wc/bc to 128 cols; strip padded output
// ---------------------------------------------------------------------------
__global__ void k_pad_wc(const float* __restrict__ Wc, const float* __restrict__ bc) {
    int idx = blockIdx.x * blockDim.x + threadIdx.x;  // 128*128
    if (idx < 128 * 128) {
        int k = idx >> 7, j = idx & 127;
        g_Wcp[idx] = (j < 100) ? Wc[k * 100 + j] : 0.0f;
    }
    if (idx < 128) g_bcp[idx] = (idx < 100) ? bc[idx] : 0.0f;
}

__global__ void k_strip(float* __restrict__ O, int N) {
    size_t idx = (size_t)blockIdx.x * blockDim.x + threadIdx.x;
    size_t tot = (size_t)N * 100;
    if (idx >= tot) return;
    int i = (int)(idx / 100);
    int j = (int)(idx - (size_t)i * 100);
    O[idx] = g_outpad[(size_t)i * 128 + j];
}

// ---------------------------------------------------------------------------
// Launch — pure kernel launches, graph-capturable
// ---------------------------------------------------------------------------
static inline int cdiv(int a, int b) { return (a + b - 1) / b; }

extern "C" void kernel_launch(void* const* d_in, const int* in_sizes, int n_in,
                              void* d_out, int out_size) {
    const float* x  = (const float*)d_in[0];
    const int*   ei = (const int*)d_in[1];   // int32 OR int64 — sniffed on device
    const float* W1 = (const float*)d_in[2];
    const float* b1 = (const float*)d_in[3];
    const float* W2 = (const float*)d_in[4];
    const float* b2 = (const float*)d_in[5];
    const float* W3 = (const float*)d_in[6];
    const float* b3 = (const float*)d_in[7];
    const float* Wc = (const float*)d_in[8];
    const float* bc = (const float*)d_in[9];

    const int N = in_sizes[0] / 256;
    const int E = in_sizes[1] / 2;

    float* out  = (float*)d_out;                    // [N,100]
    float* hout = (float*)d_out + (size_t)N * 100;  // [N,128]

    const int T = 256;

    // --- decode edges (dtype-robust), degrees, per-edge norms ---
    k_sniff<<<1, 32>>>(ei);
    k_decode<<<cdiv(E, T), T>>>(ei, E);
    k_deg_init<<<cdiv(N, T), T>>>(N);
    k_deg_acc<<<cdiv(E, T), T>>>(E);
    k_deg_fin<<<cdiv(N, T), T>>>(N);
    k_norm<<<cdiv(E, T), T>>>(E);
    k_pad_wc<<<cdiv(128 * 128, T), T>>>(Wc, bc);

    // --- layer 1: 256 -> 1024 ---
    {
        const int K = 256, M = 1024;
        dim3 g(M / 128, cdiv(N, 128));
        sgemm_k<0, 0, 0><<<g, T>>>(x, W1, N, K, M);      // g_H, g_A=g_H*dinv
        size_t stot = (size_t)E * (M / 4);
        k_scatter<<<(unsigned)((stot + T - 1) / T), T>>>(E, M);
        size_t tot = (size_t)N * (M / 4);
        k_final<0><<<(unsigned)((tot + T - 1) / T), T>>>(b1, nullptr, N, M);
    }
    // --- layer 2: 1024 -> 512 ---
    {
        const int K = 1024, M = 512;
        dim3 g(M / 128, cdiv(N, 128));
        sgemm_k<1, 0, 0><<<g, T>>>(nullptr, W2, N, K, M);
        size_t stot = (size_t)E * (M / 4);
        k_scatter<<<(unsigned)((stot + T - 1) / T), T>>>(E, M);
        size_t tot = (size_t)N * (M / 4);
        k_final<0><<<(unsigned)((tot + T - 1) / T), T>>>(b2, nullptr, N, M);
    }
    // --- layer 3: 512 -> 128 (finalize writes h into d_out) ---
    {
        const int K = 512, M = 128;
        dim3 g(M / 128, cdiv(N, 128));
        sgemm_k<1, 0, 0><<<g, T>>>(nullptr, W3, N, K, M);
        size_t stot = (size_t)E * (M / 4);
        k_scatter<<<(unsigned)((stot + T - 1) / T), T>>>(E, M);
        size_t tot = (size_t)N * (M / 4);
        k_final<1><<<(unsigned)((tot + T - 1) / T), T>>>(b3, hout, N, M);
    }
    // --- classifier: 128 -> 100 (padded to 128), sigmoid epilogue ---
    {
        const int K = 128, M = 128;
        dim3 g(M / 128, cdiv(N, 128));
        sgemm_k<0, 1, 1><<<g, T>>>(hout, nullptr, N, K, M);   // g_outpad
        size_t tot = (size_t)N * 100;
        k_strip<<<(unsigned)((tot + T - 1) / T), T>>>(out, N);
    }
}

// round 7
// speedup vs baseline: 1.1682x; 1.1682x over previous
#include <cuda_runtime.h>
#include <cuda_bf16.h>
#include <math.h>

// ---------------------------------------------------------------------------
// Problem constants (fixed by dataset)
// ---------------------------------------------------------------------------
#define MAXN 100000
#define MAXE 400000
#define FMAX 1024
#define SCAN_ELEMS 1024   // elements per scan block

// ---------------------------------------------------------------------------
// Device scratch (__device__ globals; never touched from host APIs)
// ---------------------------------------------------------------------------
__device__ int   g_is64;               // edge_index dtype flag (1 = int64)
__device__ int   g_src[MAXE];
__device__ int   g_dst[MAXE];
__device__ int   g_cnt[MAXN];          // in-degree (no self loop)
__device__ int   g_cur[MAXN];          // fill cursors
__device__ int   g_off[MAXN + 1];      // CSR row offsets (by dst)
__device__ int   g_bsum[512];          // scan block sums
__device__ int   g_bsumx[512];         // exclusive-scanned block sums
__device__ int   g_csr_src[MAXE];      // src node per CSR slot
__device__ float g_csr_w[MAXE];        // norm weight per CSR slot
__device__ float g_dis[MAXN];          // deg^-1/2
__device__ float g_dinv[MAXN];         // 1/deg
__device__ float g_H[MAXN * FMAX];     // post-GEMM features
__device__ float g_A[MAXN * FMAX];     // layer output / next-layer input
__device__ float g_outpad[MAXN * 128]; // padded classifier output
__device__ float g_Wcp[128 * 128];     // Wc padded 128x100 -> 128x128
__device__ float g_bcp[128];

// ---------------------------------------------------------------------------
// Edge-index dtype sniff + decode (robust to int32 OR int64 edge_index)
// Under int64 layout, every odd int32 word is a zero high-half (values<2^31).
// ---------------------------------------------------------------------------
__global__ void k_sniff(const int* __restrict__ ei) {
    if (threadIdx.x == 0 && blockIdx.x == 0) {
        int acc = 0;
#pragma unroll
        for (int i = 0; i < 64; i++) acc |= ei[2 * i + 1];
        g_is64 = (acc == 0) ? 1 : 0;
    }
}

__global__ void k_decode(const int* __restrict__ ei, int E) {
    int e = blockIdx.x * blockDim.x + threadIdx.x;
    if (e >= E) return;
    if (g_is64) {
        g_src[e] = ei[2 * e];            // low word of src[e]
        g_dst[e] = ei[2 * (E + e)];      // low word of dst[e]
    } else {
        g_src[e] = ei[e];
        g_dst[e] = ei[E + e];
    }
}

// ---------------------------------------------------------------------------
// Degree / CSR construction
// ---------------------------------------------------------------------------
__global__ void k_zero(int n) {
    int i = blockIdx.x * blockDim.x + threadIdx.x;
    if (i < n) { g_cnt[i] = 0; g_cur[i] = 0; }
}

__global__ void k_cnt(int E) {
    int e = blockIdx.x * blockDim.x + threadIdx.x;
    if (e < E) atomicAdd(&g_cnt[g_dst[e]], 1);
}

__global__ void k_deg_fin(int n) {
    int i = blockIdx.x * blockDim.x + threadIdx.x;
    if (i < n) {
        float d = (float)(g_cnt[i] + 1);   // + self loop
        g_dis[i]  = rsqrtf(d);
        g_dinv[i] = 1.0f / d;
    }
}

// Exclusive scan over g_cnt -> g_off.  3-phase: per-block, block sums, add.
__global__ void k_scan1(int n) {
    __shared__ int sh[256];
    int base = blockIdx.x * SCAN_ELEMS;
    int t = threadIdx.x;
    int v[4];
    int sum = 0;
#pragma unroll
    for (int i = 0; i < 4; i++) {
        int idx = base + t * 4 + i;
        int c = (idx < n) ? g_cnt[idx] : 0;
        v[i] = sum;           // exclusive within thread
        sum += c;
    }
    sh[t] = sum;
    __syncthreads();
#pragma unroll
    for (int o = 1; o < 256; o <<= 1) {
        int x = 0;
        if (t >= o) x = sh[t - o];
        __syncthreads();
        if (t >= o) sh[t] += x;
        __syncthreads();
    }
    int excl = (t > 0) ? sh[t - 1] : 0;
#pragma unroll
    for (int i = 0; i < 4; i++) {
        int idx = base + t * 4 + i;
        if (idx < n) g_off[idx] = excl + v[i];
    }
    if (t == 255) g_bsum[blockIdx.x] = sh[255];
}

__global__ void k_scan2(int G, int n) {
    __shared__ int sh[512];
    int t = threadIdx.x;
    sh[t] = (t < G) ? g_bsum[t] : 0;
    __syncthreads();
#pragma unroll
    for (int o = 1; o < 512; o <<= 1) {
        int x = 0;
        if (t >= o) x = sh[t - o];
        __syncthreads();
        if (t >= o) sh[t] += x;
        __syncthreads();
    }
    if (t < G) g_bsumx[t] = (t > 0) ? sh[t - 1] : 0;
    if (t == 0) g_off[n] = sh[511];   // total edge count
}

__global__ void k_scan3(int n) {
    int idx = blockIdx.x * blockDim.x + threadIdx.x;
    if (idx < n && blockIdx.x / (SCAN_ELEMS / 256) > 0)
        ;  // (handled below with explicit block mapping)
    // map: element idx belongs to scan-block idx / SCAN_ELEMS
    if (idx < n) g_off[idx] += g_bsumx[idx / SCAN_ELEMS];
}

__global__ void k_fill(int E) {
    int e = blockIdx.x * blockDim.x + threadIdx.x;
    if (e >= E) return;
    int s = g_src[e];
    int d = g_dst[e];
    int p = g_off[d] + atomicAdd(&g_cur[d], 1);
    g_csr_src[p] = s;
    g_csr_w[p]   = g_dis[s] * g_dis[d];
}

// ---------------------------------------------------------------------------
// SGEMM: C[N,M] = A[N,K] @ B[K,M]   (fp32, 128x128x8, TM=TN=8, 256 threads)
// ASEL: 0 = Aext, 1 = g_A     BSEL: 0 = Bext, 1 = g_Wcp
// EPI : 0 = store g_H     1 = sigmoid(v + g_bcp) -> g_outpad (classifier)
// ---------------------------------------------------------------------------
template <int ASEL, int BSEL, int EPI>
__global__ __launch_bounds__(256) void sgemm_k(
    const float* __restrict__ Aext, const float* __restrict__ Bext,
    int N, int K, int M)
{
    const float* A = (ASEL == 0) ? Aext : (const float*)g_A;
    const float* B = (BSEL == 0) ? Bext : (const float*)g_Wcp;

    __shared__ float As[8][128];
    __shared__ float Bs[8][128];

    const int tid = threadIdx.x;
    const int tx = tid & 15;
    const int ty = tid >> 4;
    const int rBase = blockIdx.y * 128;
    const int cBase = blockIdx.x * 128;

    const int aRow = tid >> 1;
    const int aCol = (tid & 1) * 4;
    const int bRow = tid >> 5;
    const int bCol = (tid & 31) * 4;

    float acc[8][8];
#pragma unroll
    for (int i = 0; i < 8; i++)
#pragma unroll
        for (int j = 0; j < 8; j++) acc[i][j] = 0.0f;

    const int gr_a = rBase + aRow;
    const bool aOK = (gr_a < N);
    const float* Aptr = A + (size_t)gr_a * K + aCol;
    const float* Bptr = B + (size_t)bRow * M + cBase + bCol;

    for (int k0 = 0; k0 < K; k0 += 8) {
        float4 av = make_float4(0.f, 0.f, 0.f, 0.f);
        if (aOK) av = *(const float4*)(Aptr + k0);
        As[aCol + 0][aRow] = av.x;
        As[aCol + 1][aRow] = av.y;
        As[aCol + 2][aRow] = av.z;
        As[aCol + 3][aRow] = av.w;

        float4 bv = *(const float4*)(Bptr + (size_t)k0 * M);
        *(float4*)&Bs[bRow][bCol] = bv;

        __syncthreads();

#pragma unroll
        for (int kk = 0; kk < 8; kk++) {
            float ar[8], br[8];
#pragma unroll
            for (int i = 0; i < 8; i++) ar[i] = As[kk][ty * 8 + i];
#pragma unroll
            for (int j = 0; j < 8; j++) br[j] = Bs[kk][tx * 8 + j];
#pragma unroll
            for (int i = 0; i < 8; i++)
#pragma unroll
                for (int j = 0; j < 8; j++)
                    acc[i][j] = fmaf(ar[i], br[j], acc[i][j]);
        }
        __syncthreads();
    }

#pragma unroll
    for (int i = 0; i < 8; i++) {
        int gr = rBase + ty * 8 + i;
        if (gr >= N) continue;
#pragma unroll
        for (int j = 0; j < 8; j += 4) {
            int gc = cBase + tx * 8 + j;
            float4 v;
            v.x = acc[i][j + 0];
            v.y = acc[i][j + 1];
            v.z = acc[i][j + 2];
            v.w = acc[i][j + 3];
            if (EPI == 0) {
                *(float4*)((float*)g_H + (size_t)gr * M + gc) = v;
            } else {
                v.x = 1.0f / (1.0f + expf(-(v.x + g_bcp[gc + 0])));
                v.y = 1.0f / (1.0f + expf(-(v.y + g_bcp[gc + 1])));
                v.z = 1.0f / (1.0f + expf(-(v.z + g_bcp[gc + 2])));
                v.w = 1.0f / (1.0f + expf(-(v.w + g_bcp[gc + 3])));
                *(float4*)((float*)g_outpad + (size_t)gr * 128 + gc) = v;
            }
        }
    }
}

// ---------------------------------------------------------------------------
// Fused aggregate: out[d,f] = tanh( sum_in H[s,f]*w + H[d,f]*dinv[d] + b[f] )
// One block per (node, feature chunk).  No atomics.
// OSEL: 0 -> g_A, 1 -> Oext
// ---------------------------------------------------------------------------
template <int OSEL>
__global__ void k_aggregate(const float* __restrict__ bias, float* __restrict__ Oext,
                            int F) {
    const int d = blockIdx.x;
    const int f = blockIdx.y * blockDim.x + threadIdx.x;
    const int beg = g_off[d];
    const int end = g_off[d + 1];
    const float* __restrict__ H = (const float*)g_H;

    float acc0 = 0.0f, acc1 = 0.0f;
    int p = beg;
    for (; p + 1 < end; p += 2) {
        int   s0 = g_csr_src[p];
        int   s1 = g_csr_src[p + 1];
        float w0 = g_csr_w[p];
        float w1 = g_csr_w[p + 1];
        float h0 = H[(size_t)s0 * F + f];
        float h1 = H[(size_t)s1 * F + f];
        acc0 = fmaf(h0, w0, acc0);
        acc1 = fmaf(h1, w1, acc1);
    }
    if (p < end) {
        int   s0 = g_csr_src[p];
        float w0 = g_csr_w[p];
        acc0 = fmaf(H[(size_t)s0 * F + f], w0, acc0);
    }
    float acc = acc0 + acc1;
    acc = fmaf(H[(size_t)d * F + f], g_dinv[d], acc);
    float v = tanhf(acc + bias[f]);
    float* O = (OSEL == 0) ? (float*)g_A : Oext;
    O[(size_t)d * F + f] = v;
}

// ---------------------------------------------------------------------------
// Classifier helpers: pad Wc/bc to 128 cols; strip padded output
// ---------------------------------------------------------------------------
__global__ void k_pad_wc(const float* __restrict__ Wc, const float* __restrict__ bc) {
    int idx = blockIdx.x * blockDim.x + threadIdx.x;
    if (idx < 128 * 128) {
        int k = idx >> 7, j = idx & 127;
        g_Wcp[idx] = (j < 100) ? Wc[k * 100 + j] : 0.0f;
    }
    if (idx < 128) g_bcp[idx] = (idx < 100) ? bc[idx] : 0.0f;
}

__global__ void k_strip(float* __restrict__ O, int N) {
    size_t idx = (size_t)blockIdx.x * blockDim.x + threadIdx.x;
    size_t tot = (size_t)N * 100;
    if (idx >= tot) return;
    int i = (int)(idx / 100);
    int j = (int)(idx - (size_t)i * 100);
    O[idx] = g_outpad[(size_t)i * 128 + j];
}

// ---------------------------------------------------------------------------
// Launch — pure kernel launches, graph-capturable
// ---------------------------------------------------------------------------
static inline int cdiv(int a, int b) { return (a + b - 1) / b; }

extern "C" void kernel_launch(void* const* d_in, const int* in_sizes, int n_in,
                              void* d_out, int out_size) {
    const float* x  = (const float*)d_in[0];
    const int*   ei = (const int*)d_in[1];   // int32 OR int64 — sniffed on device
    const float* W1 = (const float*)d_in[2];
    const float* b1 = (const float*)d_in[3];
    const float* W2 = (const float*)d_in[4];
    const float* b2 = (const float*)d_in[5];
    const float* W3 = (const float*)d_in[6];
    const float* b3 = (const float*)d_in[7];
    const float* Wc = (const float*)d_in[8];
    const float* bc = (const float*)d_in[9];

    const int N = in_sizes[0] / 256;
    const int E = in_sizes[1] / 2;

    float* out  = (float*)d_out;                    // [N,100]
    float* hout = (float*)d_out + (size_t)N * 100;  // [N,128]

    const int T = 256;
    const int G = cdiv(N, SCAN_ELEMS);              // scan blocks (98 for N=100K)

    // --- decode edges (dtype-robust), degrees, CSR by dst ---
    k_sniff<<<1, 32>>>(ei);
    k_decode<<<cdiv(E, T), T>>>(ei, E);
    k_zero<<<cdiv(N, T), T>>>(N);
    k_cnt<<<cdiv(E, T), T>>>(E);
    k_deg_fin<<<cdiv(N, T), T>>>(N);
    k_scan1<<<G, 256>>>(N);
    k_scan2<<<1, 512>>>(G, N);
    k_scan3<<<cdiv(N, T), T>>>(N);
    k_fill<<<cdiv(E, T), T>>>(E);
    k_pad_wc<<<cdiv(128 * 128, T), T>>>(Wc, bc);

    // --- layer 1: 256 -> 1024 ---
    {
        const int K = 256, M = 1024;
        dim3 g(M / 128, cdiv(N, 128));
        sgemm_k<0, 0, 0><<<g, T>>>(x, W1, N, K, M);      // g_H = x @ W1
        dim3 ag(N, M / 256);
        k_aggregate<0><<<ag, 256>>>(b1, nullptr, M);     // g_A = tanh(agg + b1)
    }
    // --- layer 2: 1024 -> 512 ---
    {
        const int K = 1024, M = 512;
        dim3 g(M / 128, cdiv(N, 128));
        sgemm_k<1, 0, 0><<<g, T>>>(nullptr, W2, N, K, M);
        dim3 ag(N, M / 256);
        k_aggregate<0><<<ag, 256>>>(b2, nullptr, M);
    }
    // --- layer 3: 512 -> 128 (aggregate writes h into d_out) ---
    {
        const int K = 512, M = 128;
        dim3 g(M / 128, cdiv(N, 128));
        sgemm_k<1, 0, 0><<<g, T>>>(nullptr, W3, N, K, M);
        dim3 ag(N, 1);
        k_aggregate<1><<<ag, 128>>>(b3, hout, M);
    }
    // --- classifier: 128 -> 100 (padded to 128), sigmoid epilogue ---
    {
        const int K = 128, M = 128;
        dim3 g(M / 128, cdiv(N, 128));
        sgemm_k<0, 1, 1><<<g, T>>>(hout, nullptr, N, K, M);   // g_outpad
        size_t tot = (size_t)N * 100;
        k_strip<<<(unsigned)((tot + T - 1) / T), T>>>(out, N);
    }
}

// round 9
// speedup vs baseline: 2.1902x; 1.8749x over previous
#include <cuda_runtime.h>
#include <cuda_bf16.h>
#include <math.h>
#include <stdint.h>

// ---------------------------------------------------------------------------
// Problem constants
// ---------------------------------------------------------------------------
#define MAXN 100000
#define MAXE 400000
#define FMAX 1024
#define SCAN_ELEMS 1024
#define WMAXE (1024 * 1024)

// ---------------------------------------------------------------------------
// Device scratch
// ---------------------------------------------------------------------------
__device__ int   g_is64;
__device__ int   g_src[MAXE];
__device__ int   g_dst[MAXE];
__device__ int   g_cnt[MAXN];
__device__ int   g_cur[MAXN];
__device__ int   g_off[MAXN + 1];
__device__ int   g_bsum[512];
__device__ int   g_bsumx[512];
__device__ int   g_csr_src[MAXE];
__device__ float g_csr_w[MAXE];
__device__ float g_dis[MAXN];
__device__ float g_dinv[MAXN];
__device__ float g_H[MAXN * FMAX];                              // GEMM out fp32
__device__ __align__(16) __nv_bfloat16 g_Ah[MAXN * FMAX];       // input hi
__device__ __align__(16) __nv_bfloat16 g_Al[MAXN * FMAX];       // input lo
__device__ __align__(16) __nv_bfloat16 g_Bh[WMAXE];             // W^T hi [M,K]
__device__ __align__(16) __nv_bfloat16 g_Bl[WMAXE];             // W^T lo
__device__ float g_outpad[MAXN * 128];
__device__ float g_bcp[128];

// ---------------------------------------------------------------------------
// PTX helpers
// ---------------------------------------------------------------------------
__device__ __forceinline__ uint32_t smem_u32(const void* p) {
    uint32_t a;
    asm("{ .reg .u64 t; cvta.to.shared.u64 t, %1; cvt.u32.u64 %0, t; }"
        : "=r"(a) : "l"(p));
    return a;
}
template <int NW>
__device__ __forceinline__ void cpwait() {
    asm volatile("cp.async.wait_group %0;" :: "n"(NW) : "memory");
}
__device__ __forceinline__ void cpcommit() {
    asm volatile("cp.async.commit_group;" ::: "memory");
}
__device__ __forceinline__ void cpasync16(uint32_t sa, const void* gp, int size) {
    asm volatile("cp.async.cg.shared.global [%0], [%1], 16, %2;"
                 :: "r"(sa), "l"(gp), "r"(size) : "memory");
}
__device__ __forceinline__ void mma16816(float* d, const uint32_t* a, const uint32_t* b) {
    asm volatile(
        "mma.sync.aligned.m16n8k16.row.col.f32.bf16.bf16.f32 "
        "{%0,%1,%2,%3}, {%4,%5,%6,%7}, {%8,%9}, {%0,%1,%2,%3};"
        : "+f"(d[0]), "+f"(d[1]), "+f"(d[2]), "+f"(d[3])
        : "r"(a[0]), "r"(a[1]), "r"(a[2]), "r"(a[3]), "r"(b[0]), "r"(b[1]));
}

// ---------------------------------------------------------------------------
// Edge-index sniff + decode (int32 OR int64)
// ---------------------------------------------------------------------------
__global__ void k_sniff(const int* __restrict__ ei) {
    if (threadIdx.x == 0 && blockIdx.x == 0) {
        int acc = 0;
#pragma unroll
        for (int i = 0; i < 64; i++) acc |= ei[2 * i + 1];
        g_is64 = (acc == 0) ? 1 : 0;
    }
}
__global__ void k_decode(const int* __restrict__ ei, int E) {
    int e = blockIdx.x * blockDim.x + threadIdx.x;
    if (e >= E) return;
    if (g_is64) { g_src[e] = ei[2 * e]; g_dst[e] = ei[2 * (E + e)]; }
    else        { g_src[e] = ei[e];     g_dst[e] = ei[E + e]; }
}

// ---------------------------------------------------------------------------
// Degree / CSR construction
// ---------------------------------------------------------------------------
__global__ void k_zero(int n) {
    int i = blockIdx.x * blockDim.x + threadIdx.x;
    if (i < n) { g_cnt[i] = 0; g_cur[i] = 0; }
}
__global__ void k_cnt(int E) {
    int e = blockIdx.x * blockDim.x + threadIdx.x;
    if (e < E) atomicAdd(&g_cnt[g_dst[e]], 1);
}
__global__ void k_deg_fin(int n) {
    int i = blockIdx.x * blockDim.x + threadIdx.x;
    if (i < n) {
        float d = (float)(g_cnt[i] + 1);
        g_dis[i]  = rsqrtf(d);
        g_dinv[i] = 1.0f / d;
    }
}
__global__ void k_scan1(int n) {
    __shared__ int sh[256];
    int base = blockIdx.x * SCAN_ELEMS;
    int t = threadIdx.x;
    int v[4]; int sum = 0;
#pragma unroll
    for (int i = 0; i < 4; i++) {
        int idx = base + t * 4 + i;
        int c = (idx < n) ? g_cnt[idx] : 0;
        v[i] = sum; sum += c;
    }
    sh[t] = sum; __syncthreads();
#pragma unroll
    for (int o = 1; o < 256; o <<= 1) {
        int x = 0;
        if (t >= o) x = sh[t - o];
        __syncthreads();
        if (t >= o) sh[t] += x;
        __syncthreads();
    }
    int excl = (t > 0) ? sh[t - 1] : 0;
#pragma unroll
    for (int i = 0; i < 4; i++) {
        int idx = base + t * 4 + i;
        if (idx < n) g_off[idx] = excl + v[i];
    }
    if (t == 255) g_bsum[blockIdx.x] = sh[255];
}
__global__ void k_scan2(int G, int n) {
    __shared__ int sh[512];
    int t = threadIdx.x;
    sh[t] = (t < G) ? g_bsum[t] : 0;
    __syncthreads();
#pragma unroll
    for (int o = 1; o < 512; o <<= 1) {
        int x = 0;
        if (t >= o) x = sh[t - o];
        __syncthreads();
        if (t >= o) sh[t] += x;
        __syncthreads();
    }
    if (t < G) g_bsumx[t] = (t > 0) ? sh[t - 1] : 0;
    if (t == 0) g_off[n] = sh[511];
}
__global__ void k_scan3(int n) {
    int idx = blockIdx.x * blockDim.x + threadIdx.x;
    if (idx < n) g_off[idx] += g_bsumx[idx / SCAN_ELEMS];
}
__global__ void k_fill(int E) {
    int e = blockIdx.x * blockDim.x + threadIdx.x;
    if (e >= E) return;
    int s = g_src[e], d = g_dst[e];
    int p = g_off[d] + atomicAdd(&g_cur[d], 1);
    g_csr_src[p] = s;
    g_csr_w[p]   = g_dis[s] * g_dis[d];
}

// ---------------------------------------------------------------------------
// fp32 -> bf16 hi/lo split + conversion kernels
// ---------------------------------------------------------------------------
__device__ __forceinline__ void bsplit(float v, __nv_bfloat16& h, __nv_bfloat16& l) {
    h = __float2bfloat16(v);
    l = __float2bfloat16(v - __bfloat162float(h));
}
__global__ void k_conv_x(const float* __restrict__ x, int tot) {
    int i = blockIdx.x * blockDim.x + threadIdx.x;
    if (i >= tot) return;
    __nv_bfloat16 h, l;
    bsplit(x[i], h, l);
    g_Ah[i] = h; g_Al[i] = l;
}
__global__ void k_conv_w(const float* __restrict__ W, int K, int M) {  // -> W^T [M,K]
    int idx = blockIdx.x * blockDim.x + threadIdx.x;
    if (idx >= K * M) return;
    int k = idx / M, m = idx - k * M;
    __nv_bfloat16 h, l;
    bsplit(W[idx], h, l);
    g_Bh[(size_t)m * K + k] = h;
    g_Bl[(size_t)m * K + k] = l;
}
__global__ void k_conv_wc(const float* __restrict__ Wc, const float* __restrict__ bc) {
    int idx = blockIdx.x * blockDim.x + threadIdx.x;
    if (idx < 128 * 128) {
        int k = idx >> 7, m = idx & 127;
        float v = (m < 100) ? Wc[k * 100 + m] : 0.0f;
        __nv_bfloat16 h, l;
        bsplit(v, h, l);
        g_Bh[m * 128 + k] = h;
        g_Bl[m * 128 + k] = l;
    }
    if (idx < 128) g_bcp[idx] = (idx < 100) ? bc[idx] : 0.0f;
}

// ---------------------------------------------------------------------------
// mma.sync bf16-split GEMM: C[Nrows,M] = A @ B^T, fp32-accurate
// A: g_Ah/g_Al [Nrows,K].  B: g_Bh/g_Bl [M,K].  K % 32 == 0, M % 128 == 0.
// CTA 256 thr (8 warps 2x4), tile 128x128, warp tile 64x32, K-chunk 32,
// cp.async double-buffered.  EPI 0 -> g_H fp32; EPI 1 -> sigmoid -> g_outpad.
// ---------------------------------------------------------------------------
#define SAH 40                    // smem stride in halves (80B, 16B aligned)
#define MAT_B (128 * SAH * 2)     // 10240 B per matrix tile
#define BUF_B (4 * MAT_B)         // Ah, Al, Bh, Bl
#define GEMM_DSM (2 * BUF_B)      // 81920 B

template <int EPI>
__global__ __launch_bounds__(256) void gemm_tc(int Nrows, int K, int M) {
    extern __shared__ char dsm[];
    const uint32_t sb = smem_u32(dsm);

    const int tid  = threadIdx.x;
    const int lane = tid & 31;
    const int w    = tid >> 5;
    const int wr   = w >> 2;         // 0..1
    const int wc   = w & 3;          // 0..3
    const int cBase = blockIdx.x * 128;
    const int rBase = blockIdx.y * 128;

    float acc[4][4][4];
#pragma unroll
    for (int a = 0; a < 4; a++)
#pragma unroll
        for (int b = 0; b < 4; b++)
#pragma unroll
            for (int c = 0; c < 4; c++) acc[a][b][c] = 0.0f;

    const int nch = K / 32;

    auto load_chunk = [&](int c, int buf) {
        const int k0 = c * 32;
#pragma unroll
        for (int i = 0; i < 8; i++) {
            int seg = i * 256 + tid;            // 0..2047
            int mat = seg >> 9;                 // 0..3
            int s   = seg & 511;
            int row = s >> 2;                   // 0..127
            int part = s & 3;                   // 16B part
            uint32_t sa = sb + buf * BUF_B + mat * MAT_B + row * (SAH * 2) + part * 16;
            const __nv_bfloat16* gp;
            int size = 16;
            if (mat < 2) {
                int gr = rBase + row;
                int r2 = (gr < Nrows) ? gr : 0;
                size = (gr < Nrows) ? 16 : 0;
                gp = ((mat == 0) ? g_Ah : g_Al) + (size_t)r2 * K + k0 + part * 8;
            } else {
                int gc = cBase + row;
                gp = ((mat == 2) ? g_Bh : g_Bl) + (size_t)gc * K + k0 + part * 8;
            }
            cpasync16(sa, gp, size);
        }
        cpcommit();
    };

    load_chunk(0, 0);

    for (int c = 0; c < nch; c++) {
        const int buf = c & 1;
        if (c + 1 < nch) { load_chunk(c + 1, (c + 1) & 1); cpwait<1>(); }
        else             { cpwait<0>(); }
        __syncthreads();

        const __nv_bfloat16* Ah_s = (const __nv_bfloat16*)(dsm + buf * BUF_B + 0 * MAT_B);
        const __nv_bfloat16* Al_s = (const __nv_bfloat16*)(dsm + buf * BUF_B + 1 * MAT_B);
        const __nv_bfloat16* Bh_s = (const __nv_bfloat16*)(dsm + buf * BUF_B + 2 * MAT_B);
        const __nv_bfloat16* Bl_s = (const __nv_bfloat16*)(dsm + buf * BUF_B + 3 * MAT_B);

#pragma unroll
        for (int ks = 0; ks < 2; ks++) {
            const int kk = (lane & 3) * 2 + ks * 16;
            uint32_t bh[4][2], bl[4][2];
#pragma unroll
            for (int nt = 0; nt < 4; nt++) {
                int n = wc * 32 + nt * 8 + (lane >> 2);
                bh[nt][0] = *(const uint32_t*)&Bh_s[n * SAH + kk];
                bh[nt][1] = *(const uint32_t*)&Bh_s[n * SAH + kk + 8];
                bl[nt][0] = *(const uint32_t*)&Bl_s[n * SAH + kk];
                bl[nt][1] = *(const uint32_t*)&Bl_s[n * SAH + kk + 8];
            }
#pragma unroll
            for (int mt = 0; mt < 4; mt++) {
                int r0 = wr * 64 + mt * 16 + (lane >> 2);
                uint32_t ah[4], al[4];
                ah[0] = *(const uint32_t*)&Ah_s[r0 * SAH + kk];
                ah[1] = *(const uint32_t*)&Ah_s[(r0 + 8) * SAH + kk];
                ah[2] = *(const uint32_t*)&Ah_s[r0 * SAH + kk + 8];
                ah[3] = *(const uint32_t*)&Ah_s[(r0 + 8) * SAH + kk + 8];
                al[0] = *(const uint32_t*)&Al_s[r0 * SAH + kk];
                al[1] = *(const uint32_t*)&Al_s[(r0 + 8) * SAH + kk];
                al[2] = *(const uint32_t*)&Al_s[r0 * SAH + kk + 8];
                al[3] = *(const uint32_t*)&Al_s[(r0 + 8) * SAH + kk + 8];
#pragma unroll
                for (int nt = 0; nt < 4; nt++) {
                    mma16816(acc[mt][nt], ah, bh[nt]);
                    mma16816(acc[mt][nt], ah, bl[nt]);
                    mma16816(acc[mt][nt], al, bh[nt]);
                }
            }
        }
        __syncthreads();
    }

    // Epilogue: fragment -> global (float2 per half-tile row)
#pragma unroll
    for (int mt = 0; mt < 4; mt++) {
#pragma unroll
        for (int nt = 0; nt < 4; nt++) {
            const int row0 = rBase + wr * 64 + mt * 16 + (lane >> 2);
            const int col  = cBase + wc * 32 + nt * 8 + (lane & 3) * 2;
            float* a = acc[mt][nt];
            if (EPI == 0) {
                if (row0 < Nrows)
                    *(float2*)&g_H[(size_t)row0 * M + col] = make_float2(a[0], a[1]);
                if (row0 + 8 < Nrows)
                    *(float2*)&g_H[(size_t)(row0 + 8) * M + col] = make_float2(a[2], a[3]);
            } else {
                float s0 = 1.0f / (1.0f + expf(-(a[0] + g_bcp[col])));
                float s1 = 1.0f / (1.0f + expf(-(a[1] + g_bcp[col + 1])));
                float s2 = 1.0f / (1.0f + expf(-(a[2] + g_bcp[col])));
                float s3 = 1.0f / (1.0f + expf(-(a[3] + g_bcp[col + 1])));
                if (row0 < Nrows)
                    *(float2*)&g_outpad[(size_t)row0 * 128 + col] = make_float2(s0, s1);
                if (row0 + 8 < Nrows)
                    *(float2*)&g_outpad[(size_t)(row0 + 8) * 128 + col] = make_float2(s2, s3);
            }
        }
    }
}

// ---------------------------------------------------------------------------
// Fused aggregate: v = tanh( sum_in H[s,f]*w + H[d,f]*dinv[d] + b[f] )
// Writes bf16 hi/lo (next GEMM input); optional fp32 to Oext (layer 3).
// ---------------------------------------------------------------------------
template <int WRITE_F32>
__global__ void k_aggregate(const float* __restrict__ bias, float* __restrict__ Oext,
                            int F) {
    const int d = blockIdx.x;
    const int f = blockIdx.y * blockDim.x + threadIdx.x;
    const int beg = g_off[d];
    const int end = g_off[d + 1];
    const float* __restrict__ H = (const float*)g_H;

    float acc0 = 0.0f, acc1 = 0.0f;
    int p = beg;
    for (; p + 1 < end; p += 2) {
        int   s0 = g_csr_src[p],     s1 = g_csr_src[p + 1];
        float w0 = g_csr_w[p],       w1 = g_csr_w[p + 1];
        acc0 = fmaf(H[(size_t)s0 * F + f], w0, acc0);
        acc1 = fmaf(H[(size_t)s1 * F + f], w1, acc1);
    }
    if (p < end) acc0 = fmaf(H[(size_t)g_csr_src[p] * F + f], g_csr_w[p], acc0);
    float acc = acc0 + acc1;
    acc = fmaf(H[(size_t)d * F + f], g_dinv[d], acc);
    float v = tanhf(acc + bias[f]);

    __nv_bfloat16 h, l;
    bsplit(v, h, l);
    g_Ah[(size_t)d * F + f] = h;
    g_Al[(size_t)d * F + f] = l;
    if (WRITE_F32) Oext[(size_t)d * F + f] = v;
}

// ---------------------------------------------------------------------------
// Strip padded classifier output
// ---------------------------------------------------------------------------
__global__ void k_strip(float* __restrict__ O, int N) {
    size_t idx = (size_t)blockIdx.x * blockDim.x + threadIdx.x;
    size_t tot = (size_t)N * 100;
    if (idx >= tot) return;
    int i = (int)(idx / 100);
    int j = (int)(idx - (size_t)i * 100);
    O[idx] = g_outpad[(size_t)i * 128 + j];
}

// ---------------------------------------------------------------------------
// Launch — pure kernel launches, graph-capturable
// ---------------------------------------------------------------------------
static inline int cdiv(int a, int b) { return (a + b - 1) / b; }

extern "C" void kernel_launch(void* const* d_in, const int* in_sizes, int n_in,
                              void* d_out, int out_size) {
    const float* x  = (const float*)d_in[0];
    const int*   ei = (const int*)d_in[1];
    const float* W1 = (const float*)d_in[2];
    const float* b1 = (const float*)d_in[3];
    const float* W2 = (const float*)d_in[4];
    const float* b2 = (const float*)d_in[5];
    const float* W3 = (const float*)d_in[6];
    const float* b3 = (const float*)d_in[7];
    const float* Wc = (const float*)d_in[8];
    const float* bc = (const float*)d_in[9];

    const int N = in_sizes[0] / 256;
    const int E = in_sizes[1] / 2;

    float* out  = (float*)d_out;                    // [N,100]
    float* hout = (float*)d_out + (size_t)N * 100;  // [N,128]

    const int T = 256;
    const int G = cdiv(N, SCAN_ELEMS);
    const int RT = cdiv(N, 128);

    cudaFuncSetAttribute(gemm_tc<0>, cudaFuncAttributeMaxDynamicSharedMemorySize, GEMM_DSM);
    cudaFuncSetAttribute(gemm_tc<1>, cudaFuncAttributeMaxDynamicSharedMemorySize, GEMM_DSM);

    // --- edges -> CSR, degrees ---
    k_sniff<<<1, 32>>>(ei);
    k_decode<<<cdiv(E, T), T>>>(ei, E);
    k_zero<<<cdiv(N, T), T>>>(N);
    k_cnt<<<cdiv(E, T), T>>>(E);
    k_deg_fin<<<cdiv(N, T), T>>>(N);
    k_scan1<<<G, 256>>>(N);
    k_scan2<<<1, 512>>>(G, N);
    k_scan3<<<cdiv(N, T), T>>>(N);
    k_fill<<<cdiv(E, T), T>>>(E);

    // --- layer 1: 256 -> 1024 ---
    k_conv_x<<<cdiv(N * 256, T), T>>>(x, N * 256);
    k_conv_w<<<cdiv(256 * 1024, T), T>>>(W1, 256, 1024);
    gemm_tc<0><<<dim3(1024 / 128, RT), 256, GEMM_DSM>>>(N, 256, 1024);
    k_aggregate<0><<<dim3(N, 1024 / 256), 256>>>(b1, nullptr, 1024);

    // --- layer 2: 1024 -> 512 ---
    k_conv_w<<<cdiv(1024 * 512, T), T>>>(W2, 1024, 512);
    gemm_tc<0><<<dim3(512 / 128, RT), 256, GEMM_DSM>>>(N, 1024, 512);
    k_aggregate<0><<<dim3(N, 512 / 256), 256>>>(b2, nullptr, 512);

    // --- layer 3: 512 -> 128 ---
    k_conv_w<<<cdiv(512 * 128, T), T>>>(W3, 512, 128);
    gemm_tc<0><<<dim3(1, RT), 256, GEMM_DSM>>>(N, 512, 128);
    k_aggregate<1><<<dim3(N, 1), 128>>>(b3, hout, 128);

    // --- classifier: 128 -> 100 (padded 128), sigmoid epilogue ---
    k_conv_wc<<<cdiv(128 * 128, T), T>>>(Wc, bc);
    gemm_tc<1><<<dim3(1, RT), 256, GEMM_DSM>>>(N, 128, 128);
    k_strip<<<cdiv(N * 100, T), T>>>(out, N);
}

// round 10
// speedup vs baseline: 2.8476x; 1.3001x over previous
#include <cuda_runtime.h>
#include <cuda_bf16.h>
#include <math.h>
#include <stdint.h>

// ---------------------------------------------------------------------------
// Problem constants
// ---------------------------------------------------------------------------
#define MAXN 100000
#define MAXE 400000
#define FMAX 1024
#define SCAN_ELEMS 1024
#define WMAXE (1024 * 1024)

// ---------------------------------------------------------------------------
// Device scratch
// ---------------------------------------------------------------------------
__device__ int   g_is64;
__device__ int   g_src[MAXE];
__device__ int   g_dst[MAXE];
__device__ int   g_cnt[MAXN];
__device__ int   g_cur[MAXN];
__device__ int   g_off[MAXN + 1];
__device__ int   g_bsum[512];
__device__ int   g_bsumx[512];
__device__ int2  g_csr[MAXE];                                   // {src, w bits}
__device__ float g_dis[MAXN];
__device__ float g_dinv[MAXN];
__device__ float g_H[MAXN * FMAX];                              // GEMM out fp32
__device__ __align__(16) __nv_bfloat16 g_Ah[MAXN * FMAX];       // input hi
__device__ __align__(16) __nv_bfloat16 g_Al[MAXN * FMAX];       // input lo
__device__ __align__(16) __nv_bfloat16 g_Bh[WMAXE];             // W^T hi [M,K]
__device__ __align__(16) __nv_bfloat16 g_Bl[WMAXE];             // W^T lo
__device__ float g_outpad[MAXN * 128];
__device__ float g_bcp[128];

// ---------------------------------------------------------------------------
// PTX helpers
// ---------------------------------------------------------------------------
__device__ __forceinline__ uint32_t smem_u32(const void* p) {
    uint32_t a;
    asm("{ .reg .u64 t; cvta.to.shared.u64 t, %1; cvt.u32.u64 %0, t; }"
        : "=r"(a) : "l"(p));
    return a;
}
template <int NW>
__device__ __forceinline__ void cpwait() {
    asm volatile("cp.async.wait_group %0;" :: "n"(NW) : "memory");
}
__device__ __forceinline__ void cpcommit() {
    asm volatile("cp.async.commit_group;" ::: "memory");
}
__device__ __forceinline__ void cpasync16(uint32_t sa, const void* gp, int size) {
    asm volatile("cp.async.cg.shared.global [%0], [%1], 16, %2;"
                 :: "r"(sa), "l"(gp), "r"(size) : "memory");
}
__device__ __forceinline__ void mma16816(float* d, const uint32_t* a, const uint32_t* b) {
    asm volatile(
        "mma.sync.aligned.m16n8k16.row.col.f32.bf16.bf16.f32 "
        "{%0,%1,%2,%3}, {%4,%5,%6,%7}, {%8,%9}, {%0,%1,%2,%3};"
        : "+f"(d[0]), "+f"(d[1]), "+f"(d[2]), "+f"(d[3])
        : "r"(a[0]), "r"(a[1]), "r"(a[2]), "r"(a[3]), "r"(b[0]), "r"(b[1]));
}
__device__ __forceinline__ void ldsm_x4(uint32_t* r, uint32_t addr) {
    asm volatile("ldmatrix.sync.aligned.m8n8.x4.shared.b16 {%0,%1,%2,%3}, [%4];"
                 : "=r"(r[0]), "=r"(r[1]), "=r"(r[2]), "=r"(r[3]) : "r"(addr));
}

// ---------------------------------------------------------------------------
// Edge-index sniff + decode (int32 OR int64)
// ---------------------------------------------------------------------------
__global__ void k_sniff(const int* __restrict__ ei) {
    if (threadIdx.x == 0 && blockIdx.x == 0) {
        int acc = 0;
#pragma unroll
        for (int i = 0; i < 64; i++) acc |= ei[2 * i + 1];
        g_is64 = (acc == 0) ? 1 : 0;
    }
}
__global__ void k_decode(const int* __restrict__ ei, int E) {
    int e = blockIdx.x * blockDim.x + threadIdx.x;
    if (e >= E) return;
    if (g_is64) { g_src[e] = ei[2 * e]; g_dst[e] = ei[2 * (E + e)]; }
    else        { g_src[e] = ei[e];     g_dst[e] = ei[E + e]; }
}

// ---------------------------------------------------------------------------
// Degree / CSR construction
// ---------------------------------------------------------------------------
__global__ void k_zero(int n) {
    int i = blockIdx.x * blockDim.x + threadIdx.x;
    if (i < n) { g_cnt[i] = 0; g_cur[i] = 0; }
}
__global__ void k_cnt(int E) {
    int e = blockIdx.x * blockDim.x + threadIdx.x;
    if (e < E) atomicAdd(&g_cnt[g_dst[e]], 1);
}
__global__ void k_deg_fin(int n) {
    int i = blockIdx.x * blockDim.x + threadIdx.x;
    if (i < n) {
        float d = (float)(g_cnt[i] + 1);
        g_dis[i]  = rsqrtf(d);
        g_dinv[i] = 1.0f / d;
    }
}
__global__ void k_scan1(int n) {
    __shared__ int sh[256];
    int base = blockIdx.x * SCAN_ELEMS;
    int t = threadIdx.x;
    int v[4]; int sum = 0;
#pragma unroll
    for (int i = 0; i < 4; i++) {
        int idx = base + t * 4 + i;
        int c = (idx < n) ? g_cnt[idx] : 0;
        v[i] = sum; sum += c;
    }
    sh[t] = sum; __syncthreads();
#pragma unroll
    for (int o = 1; o < 256; o <<= 1) {
        int x = 0;
        if (t >= o) x = sh[t - o];
        __syncthreads();
        if (t >= o) sh[t] += x;
        __syncthreads();
    }
    int excl = (t > 0) ? sh[t - 1] : 0;
#pragma unroll
    for (int i = 0; i < 4; i++) {
        int idx = base + t * 4 + i;
        if (idx < n) g_off[idx] = excl + v[i];
    }
    if (t == 255) g_bsum[blockIdx.x] = sh[255];
}
__global__ void k_scan2(int G, int n) {
    __shared__ int sh[512];
    int t = threadIdx.x;
    sh[t] = (t < G) ? g_bsum[t] : 0;
    __syncthreads();
#pragma unroll
    for (int o = 1; o < 512; o <<= 1) {
        int x = 0;
        if (t >= o) x = sh[t - o];
        __syncthreads();
        if (t >= o) sh[t] += x;
        __syncthreads();
    }
    if (t < G) g_bsumx[t] = (t > 0) ? sh[t - 1] : 0;
    if (t == 0) g_off[n] = sh[511];
}
__global__ void k_scan3(int n) {
    int idx = blockIdx.x * blockDim.x + threadIdx.x;
    if (idx < n) g_off[idx] += g_bsumx[idx / SCAN_ELEMS];
}
__global__ void k_fill(int E) {
    int e = blockIdx.x * blockDim.x + threadIdx.x;
    if (e >= E) return;
    int s = g_src[e], d = g_dst[e];
    int p = g_off[d] + atomicAdd(&g_cur[d], 1);
    g_csr[p] = make_int2(s, __float_as_int(g_dis[s] * g_dis[d]));
}

// ---------------------------------------------------------------------------
// fp32 -> bf16 hi/lo split + conversion kernels
// ---------------------------------------------------------------------------
__device__ __forceinline__ void bsplit(float v, __nv_bfloat16& h, __nv_bfloat16& l) {
    h = __float2bfloat16(v);
    l = __float2bfloat16(v - __bfloat162float(h));
}
__global__ void k_conv_x(const float* __restrict__ x, int tot) {
    int i = blockIdx.x * blockDim.x + threadIdx.x;
    if (i >= tot) return;
    __nv_bfloat16 h, l;
    bsplit(x[i], h, l);
    g_Ah[i] = h; g_Al[i] = l;
}
__global__ void k_conv_w(const float* __restrict__ W, int K, int M) {  // -> W^T [M,K]
    int idx = blockIdx.x * blockDim.x + threadIdx.x;
    if (idx >= K * M) return;
    int k = idx / M, m = idx - k * M;
    __nv_bfloat16 h, l;
    bsplit(W[idx], h, l);
    g_Bh[(size_t)m * K + k] = h;
    g_Bl[(size_t)m * K + k] = l;
}
__global__ void k_conv_wc(const float* __restrict__ Wc, const float* __restrict__ bc) {
    int idx = blockIdx.x * blockDim.x + threadIdx.x;
    if (idx < 128 * 128) {
        int k = idx >> 7, m = idx & 127;
        float v = (m < 100) ? Wc[k * 100 + m] : 0.0f;
        __nv_bfloat16 h, l;
        bsplit(v, h, l);
        g_Bh[m * 128 + k] = h;
        g_Bl[m * 128 + k] = l;
    }
    if (idx < 128) g_bcp[idx] = (idx < 100) ? bc[idx] : 0.0f;
}

// ---------------------------------------------------------------------------
// mma.sync bf16-split GEMM with ldmatrix operand loads.
// C[Nrows,M] = A @ B^T.  A: g_Ah/g_Al [Nrows,K].  B: g_Bh/g_Bl [M,K].
// CTA 256 thr (8 warps 2x4), tile 128x128, warp tile 64x32, K-chunk 32,
// cp.async double-buffered.  EPI 0 -> g_H fp32; EPI 1 -> sigmoid -> g_outpad.
// ---------------------------------------------------------------------------
#define SAH 40                    // smem stride in halves (80B; r*20%32 distinct banks)
#define MAT_B (128 * SAH * 2)     // 10240 B per matrix tile
#define BUF_B (4 * MAT_B)         // Ah, Al, Bh, Bl
#define GEMM_DSM (2 * BUF_B)      // 81920 B

template <int EPI>
__global__ __launch_bounds__(256) void gemm_tc(int Nrows, int K, int M) {
    extern __shared__ char dsm[];
    const uint32_t sb = smem_u32(dsm);

    const int tid  = threadIdx.x;
    const int lane = tid & 31;
    const int w    = tid >> 5;
    const int wr   = w >> 2;         // 0..1
    const int wc   = w & 3;          // 0..3
    const int cBase = blockIdx.x * 128;
    const int rBase = blockIdx.y * 128;

    float acc[4][4][4];
#pragma unroll
    for (int a = 0; a < 4; a++)
#pragma unroll
        for (int b = 0; b < 4; b++)
#pragma unroll
            for (int c = 0; c < 4; c++) acc[a][b][c] = 0.0f;

    const int nch = K / 32;

    // ldmatrix per-lane row/col selectors
    const int aRow = wr * 64 + (lane & 15);          // + mt*16
    const int aK   = (lane >> 4) * 8;                // + kk
    const int bRow = wc * 32 + (lane & 7) + ((lane & 16) ? 8 : 0);  // + pair*16
    const int bK   = ((lane & 8) ? 8 : 0);           // + kk

    auto load_chunk = [&](int c, int buf) {
        const int k0 = c * 32;
#pragma unroll
        for (int i = 0; i < 8; i++) {
            int seg = i * 256 + tid;            // 0..2047
            int mat = seg >> 9;                 // 0..3
            int s   = seg & 511;
            int row = s >> 2;                   // 0..127
            int part = s & 3;                   // 16B part
            uint32_t sa = sb + buf * BUF_B + mat * MAT_B + row * (SAH * 2) + part * 16;
            const __nv_bfloat16* gp;
            int size = 16;
            if (mat < 2) {
                int gr = rBase + row;
                int r2 = (gr < Nrows) ? gr : 0;
                size = (gr < Nrows) ? 16 : 0;
                gp = ((mat == 0) ? g_Ah : g_Al) + (size_t)r2 * K + k0 + part * 8;
            } else {
                int gc = cBase + row;
                gp = ((mat == 2) ? g_Bh : g_Bl) + (size_t)gc * K + k0 + part * 8;
            }
            cpasync16(sa, gp, size);
        }
        cpcommit();
    };

    load_chunk(0, 0);

    for (int c = 0; c < nch; c++) {
        const int buf = c & 1;
        if (c + 1 < nch) { load_chunk(c + 1, (c + 1) & 1); cpwait<1>(); }
        else             { cpwait<0>(); }
        __syncthreads();

        const uint32_t bA_h = sb + buf * BUF_B + 0 * MAT_B;
        const uint32_t bA_l = sb + buf * BUF_B + 1 * MAT_B;
        const uint32_t bB_h = sb + buf * BUF_B + 2 * MAT_B;
        const uint32_t bB_l = sb + buf * BUF_B + 3 * MAT_B;

#pragma unroll
        for (int ks = 0; ks < 2; ks++) {
            const int kk = ks * 16;
            // B fragments: 2 ldmatrix.x4 cover all 4 n8-tiles (hi), 2 more (lo)
            uint32_t bh[8], bl[8];
            ldsm_x4(&bh[0], bB_h + ((bRow)      * SAH + kk + bK) * 2);
            ldsm_x4(&bh[4], bB_h + ((bRow + 16) * SAH + kk + bK) * 2);
            ldsm_x4(&bl[0], bB_l + ((bRow)      * SAH + kk + bK) * 2);
            ldsm_x4(&bl[4], bB_l + ((bRow + 16) * SAH + kk + bK) * 2);
#pragma unroll
            for (int mt = 0; mt < 4; mt++) {
                uint32_t ah[4], al[4];
                ldsm_x4(ah, bA_h + ((aRow + mt * 16) * SAH + kk + aK) * 2);
                ldsm_x4(al, bA_l + ((aRow + mt * 16) * SAH + kk + aK) * 2);
#pragma unroll
                for (int nt = 0; nt < 4; nt++) {
                    mma16816(acc[mt][nt], ah, &bh[nt * 2]);
                    mma16816(acc[mt][nt], ah, &bl[nt * 2]);
                    mma16816(acc[mt][nt], al, &bh[nt * 2]);
                }
            }
        }
        __syncthreads();
    }

    // Epilogue: fragment -> global
#pragma unroll
    for (int mt = 0; mt < 4; mt++) {
#pragma unroll
        for (int nt = 0; nt < 4; nt++) {
            const int row0 = rBase + wr * 64 + mt * 16 + (lane >> 2);
            const int col  = cBase + wc * 32 + nt * 8 + (lane & 3) * 2;
            float* a = acc[mt][nt];
            if (EPI == 0) {
                if (row0 < Nrows)
                    *(float2*)&g_H[(size_t)row0 * M + col] = make_float2(a[0], a[1]);
                if (row0 + 8 < Nrows)
                    *(float2*)&g_H[(size_t)(row0 + 8) * M + col] = make_float2(a[2], a[3]);
            } else {
                float s0 = 1.0f / (1.0f + expf(-(a[0] + g_bcp[col])));
                float s1 = 1.0f / (1.0f + expf(-(a[1] + g_bcp[col + 1])));
                float s2 = 1.0f / (1.0f + expf(-(a[2] + g_bcp[col])));
                float s3 = 1.0f / (1.0f + expf(-(a[3] + g_bcp[col + 1])));
                if (row0 < Nrows)
                    *(float2*)&g_outpad[(size_t)row0 * 128 + col] = make_float2(s0, s1);
                if (row0 + 8 < Nrows)
                    *(float2*)&g_outpad[(size_t)(row0 + 8) * 128 + col] = make_float2(s2, s3);
            }
        }
    }
}

// ---------------------------------------------------------------------------
// Fused aggregate: one block per node, float4 per thread covers full row.
// v = tanh( sum_in H[s,f]*w + H[d,f]*dinv[d] + b[f] )
// Writes bf16 hi/lo (next GEMM input); optional fp32 to Oext (layer 3).
// ---------------------------------------------------------------------------
template <int WRITE_F32>
__global__ void k_aggregate(const float* __restrict__ bias, float* __restrict__ Oext,
                            int F) {
    const int d = blockIdx.x;
    const int f4 = threadIdx.x;          // 0..F/4-1
    const int f = f4 * 4;
    const int beg = g_off[d];
    const int end = g_off[d + 1];
    const int s4 = F >> 2;
    const float4* __restrict__ H4 = (const float4*)g_H;

    float4 acc = make_float4(0.f, 0.f, 0.f, 0.f);
    for (int p = beg; p < end; p++) {
        int2 sw = g_csr[p];
        float w = __int_as_float(sw.y);
        float4 h = H4[(size_t)sw.x * s4 + f4];
        acc.x = fmaf(h.x, w, acc.x);
        acc.y = fmaf(h.y, w, acc.y);
        acc.z = fmaf(h.z, w, acc.z);
        acc.w = fmaf(h.w, w, acc.w);
    }
    float dinv = g_dinv[d];
    float4 hd = H4[(size_t)d * s4 + f4];
    acc.x = fmaf(hd.x, dinv, acc.x);
    acc.y = fmaf(hd.y, dinv, acc.y);
    acc.z = fmaf(hd.z, dinv, acc.z);
    acc.w = fmaf(hd.w, dinv, acc.w);
    float4 b = *(const float4*)&bias[f];
    float4 v;
    v.x = tanhf(acc.x + b.x);
    v.y = tanhf(acc.y + b.y);
    v.z = tanhf(acc.z + b.z);
    v.w = tanhf(acc.w + b.w);

    __nv_bfloat16 h0, l0, h1, l1, h2, l2, h3, l3;
    bsplit(v.x, h0, l0); bsplit(v.y, h1, l1);
    bsplit(v.z, h2, l2); bsplit(v.w, h3, l3);
    __nv_bfloat162* Ah2 = (__nv_bfloat162*)(g_Ah + (size_t)d * F + f);
    __nv_bfloat162* Al2 = (__nv_bfloat162*)(g_Al + (size_t)d * F + f);
    Ah2[0] = __nv_bfloat162(h0, h1); Ah2[1] = __nv_bfloat162(h2, h3);
    Al2[0] = __nv_bfloat162(l0, l1); Al2[1] = __nv_bfloat162(l2, l3);
    if (WRITE_F32) *(float4*)&Oext[(size_t)d * F + f] = v;
}

// ---------------------------------------------------------------------------
// Strip padded classifier output
// ---------------------------------------------------------------------------
__global__ void k_strip(float* __restrict__ O, int N) {
    size_t idx = (size_t)blockIdx.x * blockDim.x + threadIdx.x;
    size_t tot = (size_t)N * 100;
    if (idx >= tot) return;
    int i = (int)(idx / 100);
    int j = (int)(idx - (size_t)i * 100);
    O[idx] = g_outpad[(size_t)i * 128 + j];
}

// ---------------------------------------------------------------------------
// Launch — pure kernel launches, graph-capturable
// ---------------------------------------------------------------------------
static inline int cdiv(int a, int b) { return (a + b - 1) / b; }

extern "C" void kernel_launch(void* const* d_in, const int* in_sizes, int n_in,
                              void* d_out, int out_size) {
    const float* x  = (const float*)d_in[0];
    const int*   ei = (const int*)d_in[1];
    const float* W1 = (const float*)d_in[2];
    const float* b1 = (const float*)d_in[3];
    const float* W2 = (const float*)d_in[4];
    const float* b2 = (const float*)d_in[5];
    const float* W3 = (const float*)d_in[6];
    const float* b3 = (const float*)d_in[7];
    const float* Wc = (const float*)d_in[8];
    const float* bc = (const float*)d_in[9];

    const int N = in_sizes[0] / 256;
    const int E = in_sizes[1] / 2;

    float* out  = (float*)d_out;                    // [N,100]
    float* hout = (float*)d_out + (size_t)N * 100;  // [N,128]

    const int T = 256;
    const int G = cdiv(N, SCAN_ELEMS);
    const int RT = cdiv(N, 128);

    cudaFuncSetAttribute(gemm_tc<0>, cudaFuncAttributeMaxDynamicSharedMemorySize, GEMM_DSM);
    cudaFuncSetAttribute(gemm_tc<1>, cudaFuncAttributeMaxDynamicSharedMemorySize, GEMM_DSM);

    // --- edges -> CSR, degrees ---
    k_sniff<<<1, 32>>>(ei);
    k_decode<<<cdiv(E, T), T>>>(ei, E);
    k_zero<<<cdiv(N, T), T>>>(N);
    k_cnt<<<cdiv(E, T), T>>>(E);
    k_deg_fin<<<cdiv(N, T), T>>>(N);
    k_scan1<<<G, 256>>>(N);
    k_scan2<<<1, 512>>>(G, N);
    k_scan3<<<cdiv(N, T), T>>>(N);
    k_fill<<<cdiv(E, T), T>>>(E);

    // --- layer 1: 256 -> 1024 ---
    k_conv_x<<<cdiv(N * 256, T), T>>>(x, N * 256);
    k_conv_w<<<cdiv(256 * 1024, T), T>>>(W1, 256, 1024);
    gemm_tc<0><<<dim3(1024 / 128, RT), 256, GEMM_DSM>>>(N, 256, 1024);
    k_aggregate<0><<<N, 256>>>(b1, nullptr, 1024);

    // --- layer 2: 1024 -> 512 ---
    k_conv_w<<<cdiv(1024 * 512, T), T>>>(W2, 1024, 512);
    gemm_tc<0><<<dim3(512 / 128, RT), 256, GEMM_DSM>>>(N, 1024, 512);
    k_aggregate<0><<<N, 128>>>(b2, nullptr, 512);

    // --- layer 3: 512 -> 128 ---
    k_conv_w<<<cdiv(512 * 128, T), T>>>(W3, 512, 128);
    gemm_tc<0><<<dim3(1, RT), 256, GEMM_DSM>>>(N, 512, 128);
    k_aggregate<1><<<N, 32>>>(b3, hout, 128);

    // --- classifier: 128 -> 100 (padded 128), sigmoid epilogue ---
    k_conv_wc<<<cdiv(128 * 128, T), T>>>(Wc, bc);
    gemm_tc<1><<<dim3(1, RT), 256, GEMM_DSM>>>(N, 128, 128);
    k_strip<<<cdiv(N * 100, T), T>>>(out, N);
}

// round 12
// speedup vs baseline: 3.2519x; 1.1420x over previous
#include <cuda_runtime.h>
#include <cuda_bf16.h>
#include <math.h>
#include <stdint.h>

// ---------------------------------------------------------------------------
// Problem constants
// ---------------------------------------------------------------------------
#define MAXN 100000
#define MAXE 400000
#define FMAX 1024
#define SCAN_ELEMS 1024
#define WMAXE (1024 * 1024)

// ---------------------------------------------------------------------------
// Device scratch
// ---------------------------------------------------------------------------
__device__ int   g_is64;
__device__ int   g_src[MAXE];
__device__ int   g_dst[MAXE];
__device__ int   g_cnt[MAXN];
__device__ int   g_cur[MAXN];
__device__ int   g_off[MAXN + 1];
__device__ int   g_bsum[512];
__device__ int   g_bsumx[512];
__device__ int2  g_csr[MAXE];                                   // {src, w bits}
__device__ float g_dis[MAXN];
__device__ float g_dinv[MAXN];
__device__ float g_H[MAXN * FMAX];                              // GEMM out fp32
__device__ __align__(16) __nv_bfloat16 g_Ah[MAXN * FMAX];       // operand pair A: hi
__device__ __align__(16) __nv_bfloat16 g_Al[MAXN * FMAX];       // operand pair A: lo
__device__ __align__(16) __nv_bfloat16 g_Ch[MAXN * FMAX];       // operand pair C: hi
__device__ __align__(16) __nv_bfloat16 g_Cl[MAXN * FMAX];       // operand pair C: lo
__device__ __align__(16) __nv_bfloat16 g_Bh[WMAXE];             // W^T hi [M,K]
__device__ __align__(16) __nv_bfloat16 g_Bl[WMAXE];             // W^T lo
__device__ float g_outpad[MAXN * 128];
__device__ float g_bcp[128];

// ---------------------------------------------------------------------------
// PTX helpers
// ---------------------------------------------------------------------------
__device__ __forceinline__ uint32_t smem_u32(const void* p) {
    uint32_t a;
    asm("{ .reg .u64 t; cvta.to.shared.u64 t, %1; cvt.u32.u64 %0, t; }"
        : "=r"(a) : "l"(p));
    return a;
}
template <int NW>
__device__ __forceinline__ void cpwait() {
    asm volatile("cp.async.wait_group %0;" :: "n"(NW) : "memory");
}
__device__ __forceinline__ void cpcommit() {
    asm volatile("cp.async.commit_group;" ::: "memory");
}
__device__ __forceinline__ void cpasync16(uint32_t sa, const void* gp, int size) {
    asm volatile("cp.async.cg.shared.global [%0], [%1], 16, %2;"
                 :: "r"(sa), "l"(gp), "r"(size) : "memory");
}
__device__ __forceinline__ void mma16816(float* d, const uint32_t* a, const uint32_t* b) {
    asm volatile(
        "mma.sync.aligned.m16n8k16.row.col.f32.bf16.bf16.f32 "
        "{%0,%1,%2,%3}, {%4,%5,%6,%7}, {%8,%9}, {%0,%1,%2,%3};"
        : "+f"(d[0]), "+f"(d[1]), "+f"(d[2]), "+f"(d[3])
        : "r"(a[0]), "r"(a[1]), "r"(a[2]), "r"(a[3]), "r"(b[0]), "r"(b[1]));
}
__device__ __forceinline__ void ldsm_x4(uint32_t* r, uint32_t addr) {
    asm volatile("ldmatrix.sync.aligned.m8n8.x4.shared.b16 {%0,%1,%2,%3}, [%4];"
                 : "=r"(r[0]), "=r"(r[1]), "=r"(r[2]), "=r"(r[3]) : "r"(addr));
}

// ---------------------------------------------------------------------------
// Edge-index sniff + decode (int32 OR int64)
// ---------------------------------------------------------------------------
__global__ void k_sniff(const int* __restrict__ ei) {
    if (threadIdx.x == 0 && blockIdx.x == 0) {
        int acc = 0;
#pragma unroll
        for (int i = 0; i < 64; i++) acc |= ei[2 * i + 1];
        g_is64 = (acc == 0) ? 1 : 0;
    }
}
__global__ void k_decode(const int* __restrict__ ei, int E) {
    int e = blockIdx.x * blockDim.x + threadIdx.x;
    if (e >= E) return;
    if (g_is64) { g_src[e] = ei[2 * e]; g_dst[e] = ei[2 * (E + e)]; }
    else        { g_src[e] = ei[e];     g_dst[e] = ei[E + e]; }
}

// ---------------------------------------------------------------------------
// Degree / CSR construction
// ---------------------------------------------------------------------------
__global__ void k_zero(int n) {
    int i = blockIdx.x * blockDim.x + threadIdx.x;
    if (i < n) { g_cnt[i] = 0; g_cur[i] = 0; }
}
__global__ void k_cnt(int E) {
    int e = blockIdx.x * blockDim.x + threadIdx.x;
    if (e < E) atomicAdd(&g_cnt[g_dst[e]], 1);
}
__global__ void k_deg_fin(int n) {
    int i = blockIdx.x * blockDim.x + threadIdx.x;
    if (i < n) {
        float d = (float)(g_cnt[i] + 1);
        g_dis[i]  = rsqrtf(d);
        g_dinv[i] = 1.0f / d;
    }
}
__global__ void k_scan1(int n) {
    __shared__ int sh[256];
    int base = blockIdx.x * SCAN_ELEMS;
    int t = threadIdx.x;
    int v[4]; int sum = 0;
#pragma unroll
    for (int i = 0; i < 4; i++) {
        int idx = base + t * 4 + i;
        int c = (idx < n) ? g_cnt[idx] : 0;
        v[i] = sum; sum += c;
    }
    sh[t] = sum; __syncthreads();
#pragma unroll
    for (int o = 1; o < 256; o <<= 1) {
        int x = 0;
        if (t >= o) x = sh[t - o];
        __syncthreads();
        if (t >= o) sh[t] += x;
        __syncthreads();
    }
    int excl = (t > 0) ? sh[t - 1] : 0;
#pragma unroll
    for (int i = 0; i < 4; i++) {
        int idx = base + t * 4 + i;
        if (idx < n) g_off[idx] = excl + v[i];
    }
    if (t == 255) g_bsum[blockIdx.x] = sh[255];
}
__global__ void k_scan2(int G, int n) {
    __shared__ int sh[512];
    int t = threadIdx.x;
    sh[t] = (t < G) ? g_bsum[t] : 0;
    __syncthreads();
#pragma unroll
    for (int o = 1; o < 512; o <<= 1) {
        int x = 0;
        if (t >= o) x = sh[t - o];
        __syncthreads();
        if (t >= o) sh[t] += x;
        __syncthreads();
    }
    if (t < G) g_bsumx[t] = (t > 0) ? sh[t - 1] : 0;
    if (t == 0) g_off[n] = sh[511];
}
__global__ void k_scan3(int n) {
    int idx = blockIdx.x * blockDim.x + threadIdx.x;
    if (idx < n) g_off[idx] += g_bsumx[idx / SCAN_ELEMS];
}
__global__ void k_fill(int E) {
    int e = blockIdx.x * blockDim.x + threadIdx.x;
    if (e >= E) return;
    int s = g_src[e], d = g_dst[e];
    int p = g_off[d] + atomicAdd(&g_cur[d], 1);
    g_csr[p] = make_int2(s, __float_as_int(g_dis[s] * g_dis[d]));
}

// ---------------------------------------------------------------------------
// fp32 -> bf16 hi/lo split + weight conversion
// ---------------------------------------------------------------------------
__device__ __forceinline__ void bsplit(float v, __nv_bfloat16& h, __nv_bfloat16& l) {
    h = __float2bfloat16(v);
    l = __float2bfloat16(v - __bfloat162float(h));
}
__global__ void k_conv_w(const float* __restrict__ W, int K, int M) {  // -> W^T [M,K]
    int idx = blockIdx.x * blockDim.x + threadIdx.x;
    if (idx >= K * M) return;
    int k = idx / M, m = idx - k * M;
    __nv_bfloat16 h, l;
    bsplit(W[idx], h, l);
    g_Bh[(size_t)m * K + k] = h;
    g_Bl[(size_t)m * K + k] = l;
}
__global__ void k_conv_wc(const float* __restrict__ Wc, const float* __restrict__ bc) {
    int idx = blockIdx.x * blockDim.x + threadIdx.x;
    if (idx < 128 * 128) {
        int k = idx >> 7, m = idx & 127;
        float v = (m < 100) ? Wc[k * 100 + m] : 0.0f;
        __nv_bfloat16 h, l;
        bsplit(v, h, l);
        g_Bh[m * 128 + k] = h;
        g_Bl[m * 128 + k] = l;
    }
    if (idx < 128) g_bcp[idx] = (idx < 100) ? bc[idx] : 0.0f;
}

// ---------------------------------------------------------------------------
// Layer-1 pre-aggregation on raw x (aggregation commutes with the GEMM):
// agg[d,f] = sum_in x[s,f]*w + x[d,f]*dinv[d]  -> bf16 split into A-pair
// ---------------------------------------------------------------------------
__global__ void k_aggX(const float* __restrict__ x, int F) {
    const int d = blockIdx.x;
    const int f4 = threadIdx.x;
    const int f = f4 * 4;
    const int beg = g_off[d];
    const int end = g_off[d + 1];
    const int s4 = F >> 2;
    const float4* __restrict__ X4 = (const float4*)x;

    float4 acc = make_float4(0.f, 0.f, 0.f, 0.f);
    for (int p = beg; p < end; p++) {
        int2 sw = g_csr[p];
        float w = __int_as_float(sw.y);
        float4 h = X4[(size_t)sw.x * s4 + f4];
        acc.x = fmaf(h.x, w, acc.x);
        acc.y = fmaf(h.y, w, acc.y);
        acc.z = fmaf(h.z, w, acc.z);
        acc.w = fmaf(h.w, w, acc.w);
    }
    float dinv = g_dinv[d];
    float4 hd = X4[(size_t)d * s4 + f4];
    acc.x = fmaf(hd.x, dinv, acc.x);
    acc.y = fmaf(hd.y, dinv, acc.y);
    acc.z = fmaf(hd.z, dinv, acc.z);
    acc.w = fmaf(hd.w, dinv, acc.w);

    __nv_bfloat16 h0, l0, h1, l1, h2, l2, h3, l3;
    bsplit(acc.x, h0, l0); bsplit(acc.y, h1, l1);
    bsplit(acc.z, h2, l2); bsplit(acc.w, h3, l3);
    __nv_bfloat162* Ah2 = (__nv_bfloat162*)(g_Ah + (size_t)d * F + f);
    __nv_bfloat162* Al2 = (__nv_bfloat162*)(g_Al + (size_t)d * F + f);
    Ah2[0] = __nv_bfloat162(h0, h1); Ah2[1] = __nv_bfloat162(h2, h3);
    Al2[0] = __nv_bfloat162(l0, l1); Al2[1] = __nv_bfloat162(l2, l3);
}

// ---------------------------------------------------------------------------
// mma.sync bf16-split GEMM with ldmatrix operand loads.
// C[Nrows,M] = A @ B^T.  ASEL 0: A = g_Ah/g_Al;  ASEL 1: A = g_Ch/g_Cl.
// EPI 0: C -> g_H fp32.
// EPI 1: sigmoid(C + g_bcp) -> g_outpad.
// EPI 2: tanh(C + bias) -> bf16 split into g_Ch/g_Cl (never aliases input A-pair).
// ---------------------------------------------------------------------------
#define SAH 40                    // smem stride in halves
#define MAT_B (128 * SAH * 2)
#define BUF_B (4 * MAT_B)
#define GEMM_DSM (2 * BUF_B)      // 81920 B

template <int ASEL, int EPI>
__global__ __launch_bounds__(256) void gemm_tc(const float* __restrict__ bias,
                                               int Nrows, int K, int M) {
    extern __shared__ char dsm[];
    const uint32_t sb = smem_u32(dsm);

    const __nv_bfloat16* __restrict__ Ah = (ASEL == 0) ? g_Ah : g_Ch;
    const __nv_bfloat16* __restrict__ Al = (ASEL == 0) ? g_Al : g_Cl;

    const int tid  = threadIdx.x;
    const int lane = tid & 31;
    const int w    = tid >> 5;
    const int wr   = w >> 2;
    const int wc   = w & 3;
    const int cBase = blockIdx.x * 128;
    const int rBase = blockIdx.y * 128;

    float acc[4][4][4];
#pragma unroll
    for (int a = 0; a < 4; a++)
#pragma unroll
        for (int b = 0; b < 4; b++)
#pragma unroll
            for (int c = 0; c < 4; c++) acc[a][b][c] = 0.0f;

    const int nch = K / 32;

    const int aRow = wr * 64 + (lane & 15);
    const int aK   = (lane >> 4) * 8;
    const int bRow = wc * 32 + (lane & 7) + ((lane & 16) ? 8 : 0);
    const int bK   = ((lane & 8) ? 8 : 0);

    auto load_chunk = [&](int c, int buf) {
        const int k0 = c * 32;
#pragma unroll
        for (int i = 0; i < 8; i++) {
            int seg = i * 256 + tid;
            int mat = seg >> 9;
            int s   = seg & 511;
            int row = s >> 2;
            int part = s & 3;
            uint32_t sa = sb + buf * BUF_B + mat * MAT_B + row * (SAH * 2) + part * 16;
            const __nv_bfloat16* gp;
            int size = 16;
            if (mat < 2) {
                int gr = rBase + row;
                int r2 = (gr < Nrows) ? gr : 0;
                size = (gr < Nrows) ? 16 : 0;
                gp = ((mat == 0) ? Ah : Al) + (size_t)r2 * K + k0 + part * 8;
            } else {
                int gc = cBase + row;
                gp = ((mat == 2) ? g_Bh : g_Bl) + (size_t)gc * K + k0 + part * 8;
            }
            cpasync16(sa, gp, size);
        }
        cpcommit();
    };

    load_chunk(0, 0);

    for (int c = 0; c < nch; c++) {
        const int buf = c & 1;
        if (c + 1 < nch) { load_chunk(c + 1, (c + 1) & 1); cpwait<1>(); }
        else             { cpwait<0>(); }
        __syncthreads();

        const uint32_t bA_h = sb + buf * BUF_B + 0 * MAT_B;
        const uint32_t bA_l = sb + buf * BUF_B + 1 * MAT_B;
        const uint32_t bB_h = sb + buf * BUF_B + 2 * MAT_B;
        const uint32_t bB_l = sb + buf * BUF_B + 3 * MAT_B;

#pragma unroll
        for (int ks = 0; ks < 2; ks++) {
            const int kk = ks * 16;
            uint32_t bh[8], bl[8];
            ldsm_x4(&bh[0], bB_h + ((bRow)      * SAH + kk + bK) * 2);
            ldsm_x4(&bh[4], bB_h + ((bRow + 16) * SAH + kk + bK) * 2);
            ldsm_x4(&bl[0], bB_l + ((bRow)      * SAH + kk + bK) * 2);
            ldsm_x4(&bl[4], bB_l + ((bRow + 16) * SAH + kk + bK) * 2);
#pragma unroll
            for (int mt = 0; mt < 4; mt++) {
                uint32_t ah[4], al[4];
                ldsm_x4(ah, bA_h + ((aRow + mt * 16) * SAH + kk + aK) * 2);
                ldsm_x4(al, bA_l + ((aRow + mt * 16) * SAH + kk + aK) * 2);
#pragma unroll
                for (int nt = 0; nt < 4; nt++) {
                    mma16816(acc[mt][nt], ah, &bh[nt * 2]);
                    mma16816(acc[mt][nt], ah, &bl[nt * 2]);
                    mma16816(acc[mt][nt], al, &bh[nt * 2]);
                }
            }
        }
        __syncthreads();
    }

    // Epilogue
#pragma unroll
    for (int mt = 0; mt < 4; mt++) {
#pragma unroll
        for (int nt = 0; nt < 4; nt++) {
            const int row0 = rBase + wr * 64 + mt * 16 + (lane >> 2);
            const int col  = cBase + wc * 32 + nt * 8 + (lane & 3) * 2;
            float* a = acc[mt][nt];
            if (EPI == 0) {
                if (row0 < Nrows)
                    *(float2*)&g_H[(size_t)row0 * M + col] = make_float2(a[0], a[1]);
                if (row0 + 8 < Nrows)
                    *(float2*)&g_H[(size_t)(row0 + 8) * M + col] = make_float2(a[2], a[3]);
            } else if (EPI == 1) {
                float s0 = 1.0f / (1.0f + expf(-(a[0] + g_bcp[col])));
                float s1 = 1.0f / (1.0f + expf(-(a[1] + g_bcp[col + 1])));
                float s2 = 1.0f / (1.0f + expf(-(a[2] + g_bcp[col])));
                float s3 = 1.0f / (1.0f + expf(-(a[3] + g_bcp[col + 1])));
                if (row0 < Nrows)
                    *(float2*)&g_outpad[(size_t)row0 * 128 + col] = make_float2(s0, s1);
                if (row0 + 8 < Nrows)
                    *(float2*)&g_outpad[(size_t)(row0 + 8) * 128 + col] = make_float2(s2, s3);
            } else {
                float b0 = bias[col], b1v = bias[col + 1];
                float v0 = tanhf(a[0] + b0);
                float v1 = tanhf(a[1] + b1v);
                float v2 = tanhf(a[2] + b0);
                float v3 = tanhf(a[3] + b1v);
                __nv_bfloat16 h0, l0, h1, l1, h2, l2, h3, l3;
                bsplit(v0, h0, l0); bsplit(v1, h1, l1);
                bsplit(v2, h2, l2); bsplit(v3, h3, l3);
                if (row0 < Nrows) {
                    *(__nv_bfloat162*)&g_Ch[(size_t)row0 * M + col] = __nv_bfloat162(h0, h1);
                    *(__nv_bfloat162*)&g_Cl[(size_t)row0 * M + col] = __nv_bfloat162(l0, l1);
                }
                if (row0 + 8 < Nrows) {
                    *(__nv_bfloat162*)&g_Ch[(size_t)(row0 + 8) * M + col] = __nv_bfloat162(h2, h3);
                    *(__nv_bfloat162*)&g_Cl[(size_t)(row0 + 8) * M + col] = __nv_bfloat162(l2, l3);
                }
            }
        }
    }
}

// ---------------------------------------------------------------------------
// Fused aggregate (layers 2/3): one block per node, float4 per thread.
// v = tanh( sum_in H[s,f]*w + H[d,f]*dinv[d] + b[f] )  -> A-pair (bf16 split)
// Optional fp32 to Oext (layer 3).  Reads only g_H — no alias with A-pair.
// ---------------------------------------------------------------------------
template <int WRITE_F32>
__global__ void k_aggregate(const float* __restrict__ bias, float* __restrict__ Oext,
                            int F) {
    const int d = blockIdx.x;
    const int f4 = threadIdx.x;
    const int f = f4 * 4;
    const int beg = g_off[d];
    const int end = g_off[d + 1];
    const int s4 = F >> 2;
    const float4* __restrict__ H4 = (const float4*)g_H;

    float4 acc = make_float4(0.f, 0.f, 0.f, 0.f);
    for (int p = beg; p < end; p++) {
        int2 sw = g_csr[p];
        float w = __int_as_float(sw.y);
        float4 h = H4[(size_t)sw.x * s4 + f4];
        acc.x = fmaf(h.x, w, acc.x);
        acc.y = fmaf(h.y, w, acc.y);
        acc.z = fmaf(h.z, w, acc.z);
        acc.w = fmaf(h.w, w, acc.w);
    }
    float dinv = g_dinv[d];
    float4 hd = H4[(size_t)d * s4 + f4];
    acc.x = fmaf(hd.x, dinv, acc.x);
    acc.y = fmaf(hd.y, dinv, acc.y);
    acc.z = fmaf(hd.z, dinv, acc.z);
    acc.w = fmaf(hd.w, dinv, acc.w);
    float4 b = *(const float4*)&bias[f];
    float4 v;
    v.x = tanhf(acc.x + b.x);
    v.y = tanhf(acc.y + b.y);
    v.z = tanhf(acc.z + b.z);
    v.w = tanhf(acc.w + b.w);

    __nv_bfloat16 h0, l0, h1, l1, h2, l2, h3, l3;
    bsplit(v.x, h0, l0); bsplit(v.y, h1, l1);
    bsplit(v.z, h2, l2); bsplit(v.w, h3, l3);
    __nv_bfloat162* Ah2 = (__nv_bfloat162*)(g_Ah + (size_t)d * F + f);
    __nv_bfloat162* Al2 = (__nv_bfloat162*)(g_Al + (size_t)d * F + f);
    Ah2[0] = __nv_bfloat162(h0, h1); Ah2[1] = __nv_bfloat162(h2, h3);
    Al2[0] = __nv_bfloat162(l0, l1); Al2[1] = __nv_bfloat162(l2, l3);
    if (WRITE_F32) *(float4*)&Oext[(size_t)d * F + f] = v;
}

// ---------------------------------------------------------------------------
// Strip padded classifier output
// ---------------------------------------------------------------------------
__global__ void k_strip(float* __restrict__ O, int N) {
    size_t idx = (size_t)blockIdx.x * blockDim.x + threadIdx.x;
    size_t tot = (size_t)N * 100;
    if (idx >= tot) return;
    int i = (int)(idx / 100);
    int j = (int)(idx - (size_t)i * 100);
    O[idx] = g_outpad[(size_t)i * 128 + j];
}

// ---------------------------------------------------------------------------
// Launch — pure kernel launches, graph-capturable
// ---------------------------------------------------------------------------
static inline int cdiv(int a, int b) { return (a + b - 1) / b; }

extern "C" void kernel_launch(void* const* d_in, const int* in_sizes, int n_in,
                              void* d_out, int out_size) {
    const float* x  = (const float*)d_in[0];
    const int*   ei = (const int*)d_in[1];
    const float* W1 = (const float*)d_in[2];
    const float* b1 = (const float*)d_in[3];
    const float* W2 = (const float*)d_in[4];
    const float* b2 = (const float*)d_in[5];
    const float* W3 = (const float*)d_in[6];
    const float* b3 = (const float*)d_in[7];
    const float* Wc = (const float*)d_in[8];
    const float* bc = (const float*)d_in[9];

    const int N = in_sizes[0] / 256;
    const int E = in_sizes[1] / 2;

    float* out  = (float*)d_out;                    // [N,100]
    float* hout = (float*)d_out + (size_t)N * 100;  // [N,128]

    const int T = 256;
    const int G = cdiv(N, SCAN_ELEMS);
    const int RT = cdiv(N, 128);

    cudaFuncSetAttribute((const void*)gemm_tc<0, 0>, cudaFuncAttributeMaxDynamicSharedMemorySize, GEMM_DSM);
    cudaFuncSetAttribute((const void*)gemm_tc<0, 1>, cudaFuncAttributeMaxDynamicSharedMemorySize, GEMM_DSM);
    cudaFuncSetAttribute((const void*)gemm_tc<0, 2>, cudaFuncAttributeMaxDynamicSharedMemorySize, GEMM_DSM);
    cudaFuncSetAttribute((const void*)gemm_tc<1, 0>, cudaFuncAttributeMaxDynamicSharedMemorySize, GEMM_DSM);

    // --- edges -> CSR, degrees ---
    k_sniff<<<1, 32>>>(ei);
    k_decode<<<cdiv(E, T), T>>>(ei, E);
    k_zero<<<cdiv(N, T), T>>>(N);
    k_cnt<<<cdiv(E, T), T>>>(E);
    k_deg_fin<<<cdiv(N, T), T>>>(N);
    k_scan1<<<G, 256>>>(N);
    k_scan2<<<1, 512>>>(G, N);
    k_scan3<<<cdiv(N, T), T>>>(N);
    k_fill<<<cdiv(E, T), T>>>(E);

    // --- layer 1: pre-aggregate x into A-pair, GEMM (A -> C-pair, fused tanh) ---
    k_aggX<<<N, 64>>>(x, 256);                               // A-pair = split(A_hat @ x)
    k_conv_w<<<cdiv(256 * 1024, T), T>>>(W1, 256, 1024);
    gemm_tc<0, 2><<<dim3(1024 / 128, RT), 256, GEMM_DSM>>>(b1, N, 256, 1024);  // -> C-pair

    // --- layer 2: GEMM (C-pair -> g_H), aggregate -> A-pair ---
    k_conv_w<<<cdiv(1024 * 512, T), T>>>(W2, 1024, 512);
    gemm_tc<1, 0><<<dim3(512 / 128, RT), 256, GEMM_DSM>>>(nullptr, N, 1024, 512);
    k_aggregate<0><<<N, 128>>>(b2, nullptr, 512);

    // --- layer 3: GEMM (A-pair -> g_H), aggregate -> A-pair + hout ---
    k_conv_w<<<cdiv(512 * 128, T), T>>>(W3, 512, 128);
    gemm_tc<0, 0><<<dim3(1, RT), 256, GEMM_DSM>>>(nullptr, N, 512, 128);
    k_aggregate<1><<<N, 32>>>(b3, hout, 128);

    // --- classifier: GEMM (A-pair), sigmoid epilogue -> g_outpad ---
    k_conv_wc<<<cdiv(128 * 128, T), T>>>(Wc, bc);
    gemm_tc<0, 1><<<dim3(1, RT), 256, GEMM_DSM>>>(nullptr, N, 128, 128);
    k_strip<<<cdiv(N * 100, T), T>>>(out, N);
}

// round 13
// speedup vs baseline: 3.4529x; 1.0618x over previous
#include <cuda_runtime.h>
#include <cuda_bf16.h>
#include <math.h>
#include <stdint.h>

// ---------------------------------------------------------------------------
// Problem constants
// ---------------------------------------------------------------------------
#define MAXN 100000
#define MAXE 400000
#define FMAX 1024
#define SCAN_ELEMS 1024
#define WMAXE (1024 * 1024)

// ---------------------------------------------------------------------------
// Device scratch
// ---------------------------------------------------------------------------
__device__ int   g_is64;
__device__ int   g_src[MAXE];
__device__ int   g_dst[MAXE];
__device__ int   g_cnt[MAXN];
__device__ int   g_cur[MAXN];
__device__ int   g_off[MAXN + 1];
__device__ int   g_bsum[512];
__device__ int   g_bsumx[512];
__device__ int2  g_csr[MAXE];                                   // {src, w bits}
__device__ float g_dis[MAXN];
__device__ float g_dinv[MAXN];
__device__ float g_H[MAXN * FMAX];                              // GEMM out fp32
__device__ __align__(16) __nv_bfloat16 g_Ah[MAXN * FMAX];       // operand pair A: hi
__device__ __align__(16) __nv_bfloat16 g_Al[MAXN * FMAX];       // operand pair A: lo
__device__ __align__(16) __nv_bfloat16 g_Ch[MAXN * FMAX];       // operand pair C: hi
__device__ __align__(16) __nv_bfloat16 g_Cl[MAXN * FMAX];       // operand pair C: lo
__device__ __align__(16) __nv_bfloat16 g_Bh[WMAXE];             // W^T hi [M,K]
__device__ __align__(16) __nv_bfloat16 g_Bl[WMAXE];             // W^T lo
__device__ float g_outpad[MAXN * 128];
__device__ float g_bcp[128];

// ---------------------------------------------------------------------------
// PTX helpers
// ---------------------------------------------------------------------------
__device__ __forceinline__ uint32_t smem_u32(const void* p) {
    uint32_t a;
    asm("{ .reg .u64 t; cvta.to.shared.u64 t, %1; cvt.u32.u64 %0, t; }"
        : "=r"(a) : "l"(p));
    return a;
}
template <int NW>
__device__ __forceinline__ void cpwait() {
    asm volatile("cp.async.wait_group %0;" :: "n"(NW) : "memory");
}
__device__ __forceinline__ void cpcommit() {
    asm volatile("cp.async.commit_group;" ::: "memory");
}
__device__ __forceinline__ void cpasync16(uint32_t sa, const void* gp, int size) {
    asm volatile("cp.async.cg.shared.global [%0], [%1], 16, %2;"
                 :: "r"(sa), "l"(gp), "r"(size) : "memory");
}
__device__ __forceinline__ void mma16816(float* d, const uint32_t* a, const uint32_t* b) {
    asm volatile(
        "mma.sync.aligned.m16n8k16.row.col.f32.bf16.bf16.f32 "
        "{%0,%1,%2,%3}, {%4,%5,%6,%7}, {%8,%9}, {%0,%1,%2,%3};"
        : "+f"(d[0]), "+f"(d[1]), "+f"(d[2]), "+f"(d[3])
        : "r"(a[0]), "r"(a[1]), "r"(a[2]), "r"(a[3]), "r"(b[0]), "r"(b[1]));
}
__device__ __forceinline__ void ldsm_x4(uint32_t* r, uint32_t addr) {
    asm volatile("ldmatrix.sync.aligned.m8n8.x4.shared.b16 {%0,%1,%2,%3}, [%4];"
                 : "=r"(r[0]), "=r"(r[1]), "=r"(r[2]), "=r"(r[3]) : "r"(addr));
}

// ---------------------------------------------------------------------------
// Edge-index sniff + decode (int32 OR int64)
// ---------------------------------------------------------------------------
__global__ void k_sniff(const int* __restrict__ ei) {
    if (threadIdx.x == 0 && blockIdx.x == 0) {
        int acc = 0;
#pragma unroll
        for (int i = 0; i < 64; i++) acc |= ei[2 * i + 1];
        g_is64 = (acc == 0) ? 1 : 0;
    }
}
__global__ void k_decode(const int* __restrict__ ei, int E) {
    int e = blockIdx.x * blockDim.x + threadIdx.x;
    if (e >= E) return;
    if (g_is64) { g_src[e] = ei[2 * e]; g_dst[e] = ei[2 * (E + e)]; }
    else        { g_src[e] = ei[e];     g_dst[e] = ei[E + e]; }
}

// ---------------------------------------------------------------------------
// Degree / CSR construction
// ---------------------------------------------------------------------------
__global__ void k_zero(int n) {
    int i = blockIdx.x * blockDim.x + threadIdx.x;
    if (i < n) { g_cnt[i] = 0; g_cur[i] = 0; }
}
__global__ void k_cnt(int E) {
    int e = blockIdx.x * blockDim.x + threadIdx.x;
    if (e < E) atomicAdd(&g_cnt[g_dst[e]], 1);
}
__global__ void k_deg_fin(int n) {
    int i = blockIdx.x * blockDim.x + threadIdx.x;
    if (i < n) {
        float d = (float)(g_cnt[i] + 1);
        g_dis[i]  = rsqrtf(d);
        g_dinv[i] = 1.0f / d;
    }
}
__global__ void k_scan1(int n) {
    __shared__ int sh[256];
    int base = blockIdx.x * SCAN_ELEMS;
    int t = threadIdx.x;
    int v[4]; int sum = 0;
#pragma unroll
    for (int i = 0; i < 4; i++) {
        int idx = base + t * 4 + i;
        int c = (idx < n) ? g_cnt[idx] : 0;
        v[i] = sum; sum += c;
    }
    sh[t] = sum; __syncthreads();
#pragma unroll
    for (int o = 1; o < 256; o <<= 1) {
        int x = 0;
        if (t >= o) x = sh[t - o];
        __syncthreads();
        if (t >= o) sh[t] += x;
        __syncthreads();
    }
    int excl = (t > 0) ? sh[t - 1] : 0;
#pragma unroll
    for (int i = 0; i < 4; i++) {
        int idx = base + t * 4 + i;
        if (idx < n) g_off[idx] = excl + v[i];
    }
    if (t == 255) g_bsum[blockIdx.x] = sh[255];
}
__global__ void k_scan2(int G, int n) {
    __shared__ int sh[512];
    int t = threadIdx.x;
    sh[t] = (t < G) ? g_bsum[t] : 0;
    __syncthreads();
#pragma unroll
    for (int o = 1; o < 512; o <<= 1) {
        int x = 0;
        if (t >= o) x = sh[t - o];
        __syncthreads();
        if (t >= o) sh[t] += x;
        __syncthreads();
    }
    if (t < G) g_bsumx[t] = (t > 0) ? sh[t - 1] : 0;
    if (t == 0) g_off[n] = sh[511];
}
__global__ void k_scan3(int n) {
    int idx = blockIdx.x * blockDim.x + threadIdx.x;
    if (idx < n) g_off[idx] += g_bsumx[idx / SCAN_ELEMS];
}
__global__ void k_fill(int E) {
    int e = blockIdx.x * blockDim.x + threadIdx.x;
    if (e >= E) return;
    int s = g_src[e], d = g_dst[e];
    int p = g_off[d] + atomicAdd(&g_cur[d], 1);
    g_csr[p] = make_int2(s, __float_as_int(g_dis[s] * g_dis[d]));
}

// ---------------------------------------------------------------------------
// fp32 -> bf16 hi/lo split + weight conversion
// ---------------------------------------------------------------------------
__device__ __forceinline__ void bsplit(float v, __nv_bfloat16& h, __nv_bfloat16& l) {
    h = __float2bfloat16(v);
    l = __float2bfloat16(v - __bfloat162float(h));
}
__global__ void k_conv_w(const float* __restrict__ W, int K, int M) {  // -> W^T [M,K]
    int idx = blockIdx.x * blockDim.x + threadIdx.x;
    if (idx >= K * M) return;
    int k = idx / M, m = idx - k * M;
    __nv_bfloat16 h, l;
    bsplit(W[idx], h, l);
    g_Bh[(size_t)m * K + k] = h;
    g_Bl[(size_t)m * K + k] = l;
}
__global__ void k_conv_wc(const float* __restrict__ Wc, const float* __restrict__ bc) {
    int idx = blockIdx.x * blockDim.x + threadIdx.x;
    if (idx < 128 * 128) {
        int k = idx >> 7, m = idx & 127;
        float v = (m < 100) ? Wc[k * 100 + m] : 0.0f;
        __nv_bfloat16 h, l;
        bsplit(v, h, l);
        g_Bh[m * 128 + k] = h;
        g_Bl[m * 128 + k] = l;
    }
    if (idx < 128) g_bcp[idx] = (idx < 100) ? bc[idx] : 0.0f;
}

// ---------------------------------------------------------------------------
// Layer-1 pre-aggregation on raw x (aggregation commutes with the GEMM):
// agg[d,f] = sum_in x[s,f]*w + x[d,f]*dinv[d]  -> bf16 split into A-pair
// ---------------------------------------------------------------------------
__global__ void k_aggX(const float* __restrict__ x, int F) {
    const int d = blockIdx.x;
    const int f4 = threadIdx.x;
    const int f = f4 * 4;
    const int beg = g_off[d];
    const int end = g_off[d + 1];
    const int s4 = F >> 2;
    const float4* __restrict__ X4 = (const float4*)x;

    float4 acc = make_float4(0.f, 0.f, 0.f, 0.f);
    for (int p = beg; p < end; p++) {
        int2 sw = g_csr[p];
        float w = __int_as_float(sw.y);
        float4 h = X4[(size_t)sw.x * s4 + f4];
        acc.x = fmaf(h.x, w, acc.x);
        acc.y = fmaf(h.y, w, acc.y);
        acc.z = fmaf(h.z, w, acc.z);
        acc.w = fmaf(h.w, w, acc.w);
    }
    float dinv = g_dinv[d];
    float4 hd = X4[(size_t)d * s4 + f4];
    acc.x = fmaf(hd.x, dinv, acc.x);
    acc.y = fmaf(hd.y, dinv, acc.y);
    acc.z = fmaf(hd.z, dinv, acc.z);
    acc.w = fmaf(hd.w, dinv, acc.w);

    __nv_bfloat16 h0, l0, h1, l1, h2, l2, h3, l3;
    bsplit(acc.x, h0, l0); bsplit(acc.y, h1, l1);
    bsplit(acc.z, h2, l2); bsplit(acc.w, h3, l3);
    __nv_bfloat162* Ah2 = (__nv_bfloat162*)(g_Ah + (size_t)d * F + f);
    __nv_bfloat162* Al2 = (__nv_bfloat162*)(g_Al + (size_t)d * F + f);
    Ah2[0] = __nv_bfloat162(h0, h1); Ah2[1] = __nv_bfloat162(h2, h3);
    Al2[0] = __nv_bfloat162(l0, l1); Al2[1] = __nv_bfloat162(l2, l3);
}

// ---------------------------------------------------------------------------
// mma.sync bf16-split GEMM with ldmatrix operand loads.
// C[Nrows,M] = A @ B^T.  ASEL 0: A = g_Ah/g_Al;  ASEL 1: A = g_Ch/g_Cl.
// EPI 0: C -> g_H fp32.
// EPI 1: sigmoid(C + g_bcp) -> g_outpad.
// EPI 2: tanh(C + bias) -> bf16 split into g_Ch/g_Cl (never aliases input A-pair).
// __launch_bounds__(256, 2): cap regs at 128 so 2 CTAs/SM co-reside
// (smem 2x80KB = 160KB <= 227KB) — latency hiding across syncs/cp.async waits.
// ---------------------------------------------------------------------------
#define SAH 40                    // smem stride in halves
#define MAT_B (128 * SAH * 2)
#define BUF_B (4 * MAT_B)
#define GEMM_DSM (2 * BUF_B)      // 81920 B

template <int ASEL, int EPI>
__global__ __launch_bounds__(256, 2) void gemm_tc(const float* __restrict__ bias,
                                                  int Nrows, int K, int M) {
    extern __shared__ char dsm[];
    const uint32_t sb = smem_u32(dsm);

    const __nv_bfloat16* __restrict__ Ah = (ASEL == 0) ? g_Ah : g_Ch;
    const __nv_bfloat16* __restrict__ Al = (ASEL == 0) ? g_Al : g_Cl;

    const int tid  = threadIdx.x;
    const int lane = tid & 31;
    const int w    = tid >> 5;
    const int wr   = w >> 2;
    const int wc   = w & 3;
    const int cBase = blockIdx.x * 128;
    const int rBase = blockIdx.y * 128;

    float acc[4][4][4];
#pragma unroll
    for (int a = 0; a < 4; a++)
#pragma unroll
        for (int b = 0; b < 4; b++)
#pragma unroll
            for (int c = 0; c < 4; c++) acc[a][b][c] = 0.0f;

    const int nch = K / 32;

    const int aRow = wr * 64 + (lane & 15);
    const int aK   = (lane >> 4) * 8;
    const int bRow = wc * 32 + (lane & 7) + ((lane & 16) ? 8 : 0);
    const int bK   = ((lane & 8) ? 8 : 0);

    auto load_chunk = [&](int c, int buf) {
        const int k0 = c * 32;
#pragma unroll
        for (int i = 0; i < 8; i++) {
            int seg = i * 256 + tid;
            int mat = seg >> 9;
            int s   = seg & 511;
            int row = s >> 2;
            int part = s & 3;
            uint32_t sa = sb + buf * BUF_B + mat * MAT_B + row * (SAH * 2) + part * 16;
            const __nv_bfloat16* gp;
            int size = 16;
            if (mat < 2) {
                int gr = rBase + row;
                int r2 = (gr < Nrows) ? gr : 0;
                size = (gr < Nrows) ? 16 : 0;
                gp = ((mat == 0) ? Ah : Al) + (size_t)r2 * K + k0 + part * 8;
            } else {
                int gc = cBase + row;
                gp = ((mat == 2) ? g_Bh : g_Bl) + (size_t)gc * K + k0 + part * 8;
            }
            cpasync16(sa, gp, size);
        }
        cpcommit();
    };

    load_chunk(0, 0);

    for (int c = 0; c < nch; c++) {
        const int buf = c & 1;
        if (c + 1 < nch) { load_chunk(c + 1, (c + 1) & 1); cpwait<1>(); }
        else             { cpwait<0>(); }
        __syncthreads();

        const uint32_t bA_h = sb + buf * BUF_B + 0 * MAT_B;
        const uint32_t bA_l = sb + buf * BUF_B + 1 * MAT_B;
        const uint32_t bB_h = sb + buf * BUF_B + 2 * MAT_B;
        const uint32_t bB_l = sb + buf * BUF_B + 3 * MAT_B;

#pragma unroll
        for (int ks = 0; ks < 2; ks++) {
            const int kk = ks * 16;
            uint32_t bh[8], bl[8];
            ldsm_x4(&bh[0], bB_h + ((bRow)      * SAH + kk + bK) * 2);
            ldsm_x4(&bh[4], bB_h + ((bRow + 16) * SAH + kk + bK) * 2);
            ldsm_x4(&bl[0], bB_l + ((bRow)      * SAH + kk + bK) * 2);
            ldsm_x4(&bl[4], bB_l + ((bRow + 16) * SAH + kk + bK) * 2);
#pragma unroll
            for (int mt = 0; mt < 4; mt++) {
                uint32_t ah[4], al[4];
                ldsm_x4(ah, bA_h + ((aRow + mt * 16) * SAH + kk + aK) * 2);
                ldsm_x4(al, bA_l + ((aRow + mt * 16) * SAH + kk + aK) * 2);
#pragma unroll
                for (int nt = 0; nt < 4; nt++) {
                    mma16816(acc[mt][nt], ah, &bh[nt * 2]);
                    mma16816(acc[mt][nt], ah, &bl[nt * 2]);
                    mma16816(acc[mt][nt], al, &bh[nt * 2]);
                }
            }
        }
        __syncthreads();
    }

    // Epilogue
#pragma unroll
    for (int mt = 0; mt < 4; mt++) {
#pragma unroll
        for (int nt = 0; nt < 4; nt++) {
            const int row0 = rBase + wr * 64 + mt * 16 + (lane >> 2);
            const int col  = cBase + wc * 32 + nt * 8 + (lane & 3) * 2;
            float* a = acc[mt][nt];
            if (EPI == 0) {
                if (row0 < Nrows)
                    *(float2*)&g_H[(size_t)row0 * M + col] = make_float2(a[0], a[1]);
                if (row0 + 8 < Nrows)
                    *(float2*)&g_H[(size_t)(row0 + 8) * M + col] = make_float2(a[2], a[3]);
            } else if (EPI == 1) {
                float s0 = 1.0f / (1.0f + expf(-(a[0] + g_bcp[col])));
                float s1 = 1.0f / (1.0f + expf(-(a[1] + g_bcp[col + 1])));
                float s2 = 1.0f / (1.0f + expf(-(a[2] + g_bcp[col])));
                float s3 = 1.0f / (1.0f + expf(-(a[3] + g_bcp[col + 1])));
                if (row0 < Nrows)
                    *(float2*)&g_outpad[(size_t)row0 * 128 + col] = make_float2(s0, s1);
                if (row0 + 8 < Nrows)
                    *(float2*)&g_outpad[(size_t)(row0 + 8) * 128 + col] = make_float2(s2, s3);
            } else {
                float b0 = bias[col], b1v = bias[col + 1];
                float v0 = tanhf(a[0] + b0);
                float v1 = tanhf(a[1] + b1v);
                float v2 = tanhf(a[2] + b0);
                float v3 = tanhf(a[3] + b1v);
                __nv_bfloat16 h0, l0, h1, l1, h2, l2, h3, l3;
                bsplit(v0, h0, l0); bsplit(v1, h1, l1);
                bsplit(v2, h2, l2); bsplit(v3, h3, l3);
                if (row0 < Nrows) {
                    *(__nv_bfloat162*)&g_Ch[(size_t)row0 * M + col] = __nv_bfloat162(h0, h1);
                    *(__nv_bfloat162*)&g_Cl[(size_t)row0 * M + col] = __nv_bfloat162(l0, l1);
                }
                if (row0 + 8 < Nrows) {
                    *(__nv_bfloat162*)&g_Ch[(size_t)(row0 + 8) * M + col] = __nv_bfloat162(h2, h3);
                    *(__nv_bfloat162*)&g_Cl[(size_t)(row0 + 8) * M + col] = __nv_bfloat162(l2, l3);
                }
            }
        }
    }
}

// ---------------------------------------------------------------------------
// Fused aggregate (layers 2/3): one block per node, float4 per thread.
// v = tanh( sum_in H[s,f]*w + H[d,f]*dinv[d] + b[f] )  -> A-pair (bf16 split)
// Optional fp32 to Oext (layer 3).  Reads only g_H — no alias with A-pair.
// ---------------------------------------------------------------------------
template <int WRITE_F32>
__global__ void k_aggregate(const float* __restrict__ bias, float* __restrict__ Oext,
                            int F) {
    const int d = blockIdx.x;
    const int f4 = threadIdx.x;
    const int f = f4 * 4;
    const int beg = g_off[d];
    const int end = g_off[d + 1];
    const int s4 = F >> 2;
    const float4* __restrict__ H4 = (const float4*)g_H;

    float4 acc = make_float4(0.f, 0.f, 0.f, 0.f);
    for (int p = beg; p < end; p++) {
        int2 sw = g_csr[p];
        float w = __int_as_float(sw.y);
        float4 h = H4[(size_t)sw.x * s4 + f4];
        acc.x = fmaf(h.x, w, acc.x);
        acc.y = fmaf(h.y, w, acc.y);
        acc.z = fmaf(h.z, w, acc.z);
        acc.w = fmaf(h.w, w, acc.w);
    }
    float dinv = g_dinv[d];
    float4 hd = H4[(size_t)d * s4 + f4];
    acc.x = fmaf(hd.x, dinv, acc.x);
    acc.y = fmaf(hd.y, dinv, acc.y);
    acc.z = fmaf(hd.z, dinv, acc.z);
    acc.w = fmaf(hd.w, dinv, acc.w);
    float4 b = *(const float4*)&bias[f];
    float4 v;
    v.x = tanhf(acc.x + b.x);
    v.y = tanhf(acc.y + b.y);
    v.z = tanhf(acc.z + b.z);
    v.w = tanhf(acc.w + b.w);

    __nv_bfloat16 h0, l0, h1, l1, h2, l2, h3, l3;
    bsplit(v.x, h0, l0); bsplit(v.y, h1, l1);
    bsplit(v.z, h2, l2); bsplit(v.w, h3, l3);
    __nv_bfloat162* Ah2 = (__nv_bfloat162*)(g_Ah + (size_t)d * F + f);
    __nv_bfloat162* Al2 = (__nv_bfloat162*)(g_Al + (size_t)d * F + f);
    Ah2[0] = __nv_bfloat162(h0, h1); Ah2[1] = __nv_bfloat162(h2, h3);
    Al2[0] = __nv_bfloat162(l0, l1); Al2[1] = __nv_bfloat162(l2, l3);
    if (WRITE_F32) *(float4*)&Oext[(size_t)d * F + f] = v;
}

// ---------------------------------------------------------------------------
// Strip padded classifier output
// ---------------------------------------------------------------------------
__global__ void k_strip(float* __restrict__ O, int N) {
    size_t idx = (size_t)blockIdx.x * blockDim.x + threadIdx.x;
    size_t tot = (size_t)N * 100;
    if (idx >= tot) return;
    int i = (int)(idx / 100);
    int j = (int)(idx - (size_t)i * 100);
    O[idx] = g_outpad[(size_t)i * 128 + j];
}

// ---------------------------------------------------------------------------
// Launch — pure kernel launches, graph-capturable
// ---------------------------------------------------------------------------
static inline int cdiv(int a, int b) { return (a + b - 1) / b; }

extern "C" void kernel_launch(void* const* d_in, const int* in_sizes, int n_in,
                              void* d_out, int out_size) {
    const float* x  = (const float*)d_in[0];
    const int*   ei = (const int*)d_in[1];
    const float* W1 = (const float*)d_in[2];
    const float* b1 = (const float*)d_in[3];
    const float* W2 = (const float*)d_in[4];
    const float* b2 = (const float*)d_in[5];
    const float* W3 = (const float*)d_in[6];
    const float* b3 = (const float*)d_in[7];
    const float* Wc = (const float*)d_in[8];
    const float* bc = (const float*)d_in[9];

    const int N = in_sizes[0] / 256;
    const int E = in_sizes[1] / 2;

    float* out  = (float*)d_out;                    // [N,100]
    float* hout = (float*)d_out + (size_t)N * 100;  // [N,128]

    const int T = 256;
    const int G = cdiv(N, SCAN_ELEMS);
    const int RT = cdiv(N, 128);

    cudaFuncSetAttribute((const void*)gemm_tc<0, 0>, cudaFuncAttributeMaxDynamicSharedMemorySize, GEMM_DSM);
    cudaFuncSetAttribute((const void*)gemm_tc<0, 1>, cudaFuncAttributeMaxDynamicSharedMemorySize, GEMM_DSM);
    cudaFuncSetAttribute((const void*)gemm_tc<0, 2>, cudaFuncAttributeMaxDynamicSharedMemorySize, GEMM_DSM);
    cudaFuncSetAttribute((const void*)gemm_tc<1, 0>, cudaFuncAttributeMaxDynamicSharedMemorySize, GEMM_DSM);

    // --- edges -> CSR, degrees ---
    k_sniff<<<1, 32>>>(ei);
    k_decode<<<cdiv(E, T), T>>>(ei, E);
    k_zero<<<cdiv(N, T), T>>>(N);
    k_cnt<<<cdiv(E, T), T>>>(E);
    k_deg_fin<<<cdiv(N, T), T>>>(N);
    k_scan1<<<G, 256>>>(N);
    k_scan2<<<1, 512>>>(G, N);
    k_scan3<<<cdiv(N, T), T>>>(N);
    k_fill<<<cdiv(E, T), T>>>(E);

    // --- layer 1: pre-aggregate x into A-pair, GEMM (A -> C-pair, fused tanh) ---
    k_aggX<<<N, 64>>>(x, 256);                               // A-pair = split(A_hat @ x)
    k_conv_w<<<cdiv(256 * 1024, T), T>>>(W1, 256, 1024);
    gemm_tc<0, 2><<<dim3(1024 / 128, RT), 256, GEMM_DSM>>>(b1, N, 256, 1024);  // -> C-pair

    // --- layer 2: GEMM (C-pair -> g_H), aggregate -> A-pair ---
    k_conv_w<<<cdiv(1024 * 512, T), T>>>(W2, 1024, 512);
    gemm_tc<1, 0><<<dim3(512 / 128, RT), 256, GEMM_DSM>>>(nullptr, N, 1024, 512);
    k_aggregate<0><<<N, 128>>>(b2, nullptr, 512);

    // --- layer 3: GEMM (A-pair -> g_H), aggregate -> A-pair + hout ---
    k_conv_w<<<cdiv(512 * 128, T), T>>>(W3, 512, 128);
    gemm_tc<0, 0><<<dim3(1, RT), 256, GEMM_DSM>>>(nullptr, N, 512, 128);
    k_aggregate<1><<<N, 32>>>(b3, hout, 128);

    // --- classifier: GEMM (A-pair), sigmoid epilogue -> g_outpad ---
    k_conv_wc<<<cdiv(128 * 128, T), T>>>(Wc, bc);
    gemm_tc<0, 1><<<dim3(1, RT), 256, GEMM_DSM>>>(nullptr, N, 128, 128);
    k_strip<<<cdiv(N * 100, T), T>>>(out, N);
}

// round 14
// speedup vs baseline: 4.3477x; 1.2591x over previous
#include <cuda_runtime.h>
#include <cuda_fp16.h>
#include <math.h>
#include <stdint.h>

// ---------------------------------------------------------------------------
// Problem constants
// ---------------------------------------------------------------------------
#define MAXN 100000
#define MAXE 400000
#define FMAX 1024
#define SCAN_ELEMS 1024
#define WMAXE (1024 * 1024)

// ---------------------------------------------------------------------------
// Device scratch
// ---------------------------------------------------------------------------
__device__ int   g_is64;
__device__ int   g_src[MAXE];
__device__ int   g_dst[MAXE];
__device__ int   g_cnt[MAXN];
__device__ int   g_cur[MAXN];
__device__ int   g_off[MAXN + 1];
__device__ int   g_bsum[512];
__device__ int   g_bsumx[512];
__device__ int2  g_csr[MAXE];                                   // {src, w bits}
__device__ float g_dis[MAXN];
__device__ float g_dinv[MAXN];
__device__ float g_H[MAXN * FMAX];                              // GEMM out fp32
__device__ __align__(16) __half g_Ah[MAXN * FMAX];              // operand pair A: hi
__device__ __align__(16) __half g_Al[MAXN * FMAX];              // operand pair A: lo
__device__ __align__(16) __half g_Ch[MAXN * FMAX];              // operand pair C: hi
__device__ __align__(16) __half g_Cl[MAXN * FMAX];              // operand pair C: lo
__device__ __align__(16) __half g_Bh[WMAXE];                    // W^T fp16 [M,K]
__device__ float g_outpad[MAXN * 128];
__device__ float g_bcp[128];

// ---------------------------------------------------------------------------
// PTX helpers
// ---------------------------------------------------------------------------
__device__ __forceinline__ uint32_t smem_u32(const void* p) {
    uint32_t a;
    asm("{ .reg .u64 t; cvta.to.shared.u64 t, %1; cvt.u32.u64 %0, t; }"
        : "=r"(a) : "l"(p));
    return a;
}
template <int NW>
__device__ __forceinline__ void cpwait() {
    asm volatile("cp.async.wait_group %0;" :: "n"(NW) : "memory");
}
__device__ __forceinline__ void cpcommit() {
    asm volatile("cp.async.commit_group;" ::: "memory");
}
__device__ __forceinline__ void cpasync16(uint32_t sa, const void* gp, int size) {
    asm volatile("cp.async.cg.shared.global [%0], [%1], 16, %2;"
                 :: "r"(sa), "l"(gp), "r"(size) : "memory");
}
__device__ __forceinline__ void mma16816(float* d, const uint32_t* a, const uint32_t* b) {
    asm volatile(
        "mma.sync.aligned.m16n8k16.row.col.f32.f16.f16.f32 "
        "{%0,%1,%2,%3}, {%4,%5,%6,%7}, {%8,%9}, {%0,%1,%2,%3};"
        : "+f"(d[0]), "+f"(d[1]), "+f"(d[2]), "+f"(d[3])
        : "r"(a[0]), "r"(a[1]), "r"(a[2]), "r"(a[3]), "r"(b[0]), "r"(b[1]));
}
__device__ __forceinline__ void ldsm_x4(uint32_t* r, uint32_t addr) {
    asm volatile("ldmatrix.sync.aligned.m8n8.x4.shared.b16 {%0,%1,%2,%3}, [%4];"
                 : "=r"(r[0]), "=r"(r[1]), "=r"(r[2]), "=r"(r[3]) : "r"(addr));
}

// ---------------------------------------------------------------------------
// Edge-index sniff + decode (int32 OR int64)
// ---------------------------------------------------------------------------
__global__ void k_sniff(const int* __restrict__ ei) {
    if (threadIdx.x == 0 && blockIdx.x == 0) {
        int acc = 0;
#pragma unroll
        for (int i = 0; i < 64; i++) acc |= ei[2 * i + 1];
        g_is64 = (acc == 0) ? 1 : 0;
    }
}
__global__ void k_decode(const int* __restrict__ ei, int E) {
    int e = blockIdx.x * blockDim.x + threadIdx.x;
    if (e >= E) return;
    if (g_is64) { g_src[e] = ei[2 * e]; g_dst[e] = ei[2 * (E + e)]; }
    else        { g_src[e] = ei[e];     g_dst[e] = ei[E + e]; }
}

// ---------------------------------------------------------------------------
// Degree / CSR construction
// ---------------------------------------------------------------------------
__global__ void k_zero(int n) {
    int i = blockIdx.x * blockDim.x + threadIdx.x;
    if (i < n) { g_cnt[i] = 0; g_cur[i] = 0; }
}
__global__ void k_cnt(int E) {
    int e = blockIdx.x * blockDim.x + threadIdx.x;
    if (e < E) atomicAdd(&g_cnt[g_dst[e]], 1);
}
__global__ void k_deg_fin(int n) {
    int i = blockIdx.x * blockDim.x + threadIdx.x;
    if (i < n) {
        float d = (float)(g_cnt[i] + 1);
        g_dis[i]  = rsqrtf(d);
        g_dinv[i] = 1.0f / d;
    }
}
__global__ void k_scan1(int n) {
    __shared__ int sh[256];
    int base = blockIdx.x * SCAN_ELEMS;
    int t = threadIdx.x;
    int v[4]; int sum = 0;
#pragma unroll
    for (int i = 0; i < 4; i++) {
        int idx = base + t * 4 + i;
        int c = (idx < n) ? g_cnt[idx] : 0;
        v[i] = sum; sum += c;
    }
    sh[t] = sum; __syncthreads();
#pragma unroll
    for (int o = 1; o < 256; o <<= 1) {
        int x = 0;
        if (t >= o) x = sh[t - o];
        __syncthreads();
        if (t >= o) sh[t] += x;
        __syncthreads();
    }
    int excl = (t > 0) ? sh[t - 1] : 0;
#pragma unroll
    for (int i = 0; i < 4; i++) {
        int idx = base + t * 4 + i;
        if (idx < n) g_off[idx] = excl + v[i];
    }
    if (t == 255) g_bsum[blockIdx.x] = sh[255];
}
__global__ void k_scan2(int G, int n) {
    __shared__ int sh[512];
    int t = threadIdx.x;
    sh[t] = (t < G) ? g_bsum[t] : 0;
    __syncthreads();
#pragma unroll
    for (int o = 1; o < 512; o <<= 1) {
        int x = 0;
        if (t >= o) x = sh[t - o];
        __syncthreads();
        if (t >= o) sh[t] += x;
        __syncthreads();
    }
    if (t < G) g_bsumx[t] = (t > 0) ? sh[t - 1] : 0;
    if (t == 0) g_off[n] = sh[511];
}
__global__ void k_scan3(int n) {
    int idx = blockIdx.x * blockDim.x + threadIdx.x;
    if (idx < n) g_off[idx] += g_bsumx[idx / SCAN_ELEMS];
}
__global__ void k_fill(int E) {
    int e = blockIdx.x * blockDim.x + threadIdx.x;
    if (e >= E) return;
    int s = g_src[e], d = g_dst[e];
    int p = g_off[d] + atomicAdd(&g_cur[d], 1);
    g_csr[p] = make_int2(s, __float_as_int(g_dis[s] * g_dis[d]));
}

// ---------------------------------------------------------------------------
// fp32 -> fp16 hi/lo split + weight conversion (weights: single fp16)
// ---------------------------------------------------------------------------
__device__ __forceinline__ void hsplit(float v, __half& h, __half& l) {
    h = __float2half(v);
    l = __float2half(v - __half2float(h));
}
__global__ void k_conv_w(const float* __restrict__ W, int K, int M) {  // -> W^T [M,K]
    int idx = blockIdx.x * blockDim.x + threadIdx.x;
    if (idx >= K * M) return;
    int k = idx / M, m = idx - k * M;
    g_Bh[(size_t)m * K + k] = __float2half(W[idx]);
}
__global__ void k_conv_wc(const float* __restrict__ Wc, const float* __restrict__ bc) {
    int idx = blockIdx.x * blockDim.x + threadIdx.x;
    if (idx < 128 * 128) {
        int k = idx >> 7, m = idx & 127;
        float v = (m < 100) ? Wc[k * 100 + m] : 0.0f;
        g_Bh[m * 128 + k] = __float2half(v);
    }
    if (idx < 128) g_bcp[idx] = (idx < 100) ? bc[idx] : 0.0f;
}

// ---------------------------------------------------------------------------
// Layer-1 pre-aggregation on raw x (aggregation commutes with the GEMM):
// agg[d,f] = sum_in x[s,f]*w + x[d,f]*dinv[d]  -> fp16 split into A-pair
// ---------------------------------------------------------------------------
__global__ void k_aggX(const float* __restrict__ x, int F) {
    const int d = blockIdx.x;
    const int f4 = threadIdx.x;
    const int f = f4 * 4;
    const int beg = g_off[d];
    const int end = g_off[d + 1];
    const int s4 = F >> 2;
    const float4* __restrict__ X4 = (const float4*)x;

    float4 acc = make_float4(0.f, 0.f, 0.f, 0.f);
    for (int p = beg; p < end; p++) {
        int2 sw = g_csr[p];
        float w = __int_as_float(sw.y);
        float4 h = X4[(size_t)sw.x * s4 + f4];
        acc.x = fmaf(h.x, w, acc.x);
        acc.y = fmaf(h.y, w, acc.y);
        acc.z = fmaf(h.z, w, acc.z);
        acc.w = fmaf(h.w, w, acc.w);
    }
    float dinv = g_dinv[d];
    float4 hd = X4[(size_t)d * s4 + f4];
    acc.x = fmaf(hd.x, dinv, acc.x);
    acc.y = fmaf(hd.y, dinv, acc.y);
    acc.z = fmaf(hd.z, dinv, acc.z);
    acc.w = fmaf(hd.w, dinv, acc.w);

    __half h0, l0, h1, l1, h2, l2, h3, l3;
    hsplit(acc.x, h0, l0); hsplit(acc.y, h1, l1);
    hsplit(acc.z, h2, l2); hsplit(acc.w, h3, l3);
    __half2* Ah2 = (__half2*)(g_Ah + (size_t)d * F + f);
    __half2* Al2 = (__half2*)(g_Al + (size_t)d * F + f);
    Ah2[0] = __halves2half2(h0, h1); Ah2[1] = __halves2half2(h2, h3);
    Al2[0] = __halves2half2(l0, l1); Al2[1] = __halves2half2(l2, l3);
}

// ---------------------------------------------------------------------------
// mma.sync fp16-split GEMM with ldmatrix operand loads.
// C[Nrows,M] = A @ B^T.  ASEL 0: A = g_Ah/g_Al;  ASEL 1: A = g_Ch/g_Cl.
// A: activations split hi/lo fp16 (error 2^-22).  B: weights fp16 (err ~7e-5 RMS).
// 2 MMAs per product: D = Ah*B + Al*B.
// EPI 0: C -> g_H fp32.  EPI 1: sigmoid -> g_outpad.  EPI 2: tanh -> C-pair.
// ---------------------------------------------------------------------------
#define SAH 40                    // smem stride in halves
#define MAT_B (128 * SAH * 2)     // 10240 B per matrix tile
#define BUF_B (3 * MAT_B)         // Ah, Al, Bh
#define GEMM_DSM (2 * BUF_B)      // 61440 B

template <int ASEL, int EPI>
__global__ __launch_bounds__(256, 2) void gemm_tc(const float* __restrict__ bias,
                                                  int Nrows, int K, int M) {
    extern __shared__ char dsm[];
    const uint32_t sb = smem_u32(dsm);

    const __half* __restrict__ Ah = (ASEL == 0) ? g_Ah : g_Ch;
    const __half* __restrict__ Al = (ASEL == 0) ? g_Al : g_Cl;

    const int tid  = threadIdx.x;
    const int lane = tid & 31;
    const int w    = tid >> 5;
    const int wr   = w >> 2;
    const int wc   = w & 3;
    const int cBase = blockIdx.x * 128;
    const int rBase = blockIdx.y * 128;

    float acc[4][4][4];
#pragma unroll
    for (int a = 0; a < 4; a++)
#pragma unroll
        for (int b = 0; b < 4; b++)
#pragma unroll
            for (int c = 0; c < 4; c++) acc[a][b][c] = 0.0f;

    const int nch = K / 32;

    const int aRow = wr * 64 + (lane & 15);
    const int aK   = (lane >> 4) * 8;
    const int bRow = wc * 32 + (lane & 7) + ((lane & 16) ? 8 : 0);
    const int bK   = ((lane & 8) ? 8 : 0);

    auto load_chunk = [&](int c, int buf) {
        const int k0 = c * 32;
#pragma unroll
        for (int i = 0; i < 6; i++) {
            int seg = i * 256 + tid;            // 0..1535
            int mat = seg >> 9;                 // 0..2
            int s   = seg & 511;
            int row = s >> 2;
            int part = s & 3;
            uint32_t sa = sb + buf * BUF_B + mat * MAT_B + row * (SAH * 2) + part * 16;
            const __half* gp;
            int size = 16;
            if (mat < 2) {
                int gr = rBase + row;
                int r2 = (gr < Nrows) ? gr : 0;
                size = (gr < Nrows) ? 16 : 0;
                gp = ((mat == 0) ? Ah : Al) + (size_t)r2 * K + k0 + part * 8;
            } else {
                int gc = cBase + row;
                gp = g_Bh + (size_t)gc * K + k0 + part * 8;
            }
            cpasync16(sa, gp, size);
        }
        cpcommit();
    };

    load_chunk(0, 0);

    for (int c = 0; c < nch; c++) {
        const int buf = c & 1;
        if (c + 1 < nch) { load_chunk(c + 1, (c + 1) & 1); cpwait<1>(); }
        else             { cpwait<0>(); }
        __syncthreads();

        const uint32_t bA_h = sb + buf * BUF_B + 0 * MAT_B;
        const uint32_t bA_l = sb + buf * BUF_B + 1 * MAT_B;
        const uint32_t bB_h = sb + buf * BUF_B + 2 * MAT_B;

#pragma unroll
        for (int ks = 0; ks < 2; ks++) {
            const int kk = ks * 16;
            uint32_t bh[8];
            ldsm_x4(&bh[0], bB_h + ((bRow)      * SAH + kk + bK) * 2);
            ldsm_x4(&bh[4], bB_h + ((bRow + 16) * SAH + kk + bK) * 2);
#pragma unroll
            for (int mt = 0; mt < 4; mt++) {
                uint32_t ah[4], al[4];
                ldsm_x4(ah, bA_h + ((aRow + mt * 16) * SAH + kk + aK) * 2);
                ldsm_x4(al, bA_l + ((aRow + mt * 16) * SAH + kk + aK) * 2);
#pragma unroll
                for (int nt = 0; nt < 4; nt++) {
                    mma16816(acc[mt][nt], ah, &bh[nt * 2]);
                    mma16816(acc[mt][nt], al, &bh[nt * 2]);
                }
            }
        }
        __syncthreads();
    }

    // Epilogue
#pragma unroll
    for (int mt = 0; mt < 4; mt++) {
#pragma unroll
        for (int nt = 0; nt < 4; nt++) {
            const int row0 = rBase + wr * 64 + mt * 16 + (lane >> 2);
            const int col  = cBase + wc * 32 + nt * 8 + (lane & 3) * 2;
            float* a = acc[mt][nt];
            if (EPI == 0) {
                if (row0 < Nrows)
                    *(float2*)&g_H[(size_t)row0 * M + col] = make_float2(a[0], a[1]);
                if (row0 + 8 < Nrows)
                    *(float2*)&g_H[(size_t)(row0 + 8) * M + col] = make_float2(a[2], a[3]);
            } else if (EPI == 1) {
                float s0 = 1.0f / (1.0f + expf(-(a[0] + g_bcp[col])));
                float s1 = 1.0f / (1.0f + expf(-(a[1] + g_bcp[col + 1])));
                float s2 = 1.0f / (1.0f + expf(-(a[2] + g_bcp[col])));
                float s3 = 1.0f / (1.0f + expf(-(a[3] + g_bcp[col + 1])));
                if (row0 < Nrows)
                    *(float2*)&g_outpad[(size_t)row0 * 128 + col] = make_float2(s0, s1);
                if (row0 + 8 < Nrows)
                    *(float2*)&g_outpad[(size_t)(row0 + 8) * 128 + col] = make_float2(s2, s3);
            } else {
                float b0 = bias[col], b1v = bias[col + 1];
                float v0 = tanhf(a[0] + b0);
                float v1 = tanhf(a[1] + b1v);
                float v2 = tanhf(a[2] + b0);
                float v3 = tanhf(a[3] + b1v);
                __half h0, l0, h1, l1, h2, l2, h3, l3;
                hsplit(v0, h0, l0); hsplit(v1, h1, l1);
                hsplit(v2, h2, l2); hsplit(v3, h3, l3);
                if (row0 < Nrows) {
                    *(__half2*)&g_Ch[(size_t)row0 * M + col] = __halves2half2(h0, h1);
                    *(__half2*)&g_Cl[(size_t)row0 * M + col] = __halves2half2(l0, l1);
                }
                if (row0 + 8 < Nrows) {
                    *(__half2*)&g_Ch[(size_t)(row0 + 8) * M + col] = __halves2half2(h2, h3);
                    *(__half2*)&g_Cl[(size_t)(row0 + 8) * M + col] = __halves2half2(l2, l3);
                }
            }
        }
    }
}

// ---------------------------------------------------------------------------
// Fused aggregate (layers 2/3): one block per node, float4 per thread.
// v = tanh( sum_in H[s,f]*w + H[d,f]*dinv[d] + b[f] )  -> A-pair (fp16 split)
// Optional fp32 to Oext (layer 3).
// ---------------------------------------------------------------------------
template <int WRITE_F32>
__global__ void k_aggregate(const float* __restrict__ bias, float* __restrict__ Oext,
                            int F) {
    const int d = blockIdx.x;
    const int f4 = threadIdx.x;
    const int f = f4 * 4;
    const int beg = g_off[d];
    const int end = g_off[d + 1];
    const int s4 = F >> 2;
    const float4* __restrict__ H4 = (const float4*)g_H;

    float4 acc = make_float4(0.f, 0.f, 0.f, 0.f);
    for (int p = beg; p < end; p++) {
        int2 sw = g_csr[p];
        float w = __int_as_float(sw.y);
        float4 h = H4[(size_t)sw.x * s4 + f4];
        acc.x = fmaf(h.x, w, acc.x);
        acc.y = fmaf(h.y, w, acc.y);
        acc.z = fmaf(h.z, w, acc.z);
        acc.w = fmaf(h.w, w, acc.w);
    }
    float dinv = g_dinv[d];
    float4 hd = H4[(size_t)d * s4 + f4];
    acc.x = fmaf(hd.x, dinv, acc.x);
    acc.y = fmaf(hd.y, dinv, acc.y);
    acc.z = fmaf(hd.z, dinv, acc.z);
    acc.w = fmaf(hd.w, dinv, acc.w);
    float4 b = *(const float4*)&bias[f];
    float4 v;
    v.x = tanhf(acc.x + b.x);
    v.y = tanhf(acc.y + b.y);
    v.z = tanhf(acc.z + b.z);
    v.w = tanhf(acc.w + b.w);

    __half h0, l0, h1, l1, h2, l2, h3, l3;
    hsplit(v.x, h0, l0); hsplit(v.y, h1, l1);
    hsplit(v.z, h2, l2); hsplit(v.w, h3, l3);
    __half2* Ah2 = (__half2*)(g_Ah + (size_t)d * F + f);
    __half2* Al2 = (__half2*)(g_Al + (size_t)d * F + f);
    Ah2[0] = __halves2half2(h0, h1); Ah2[1] = __halves2half2(h2, h3);
    Al2[0] = __halves2half2(l0, l1); Al2[1] = __halves2half2(l2, l3);
    if (WRITE_F32) *(float4*)&Oext[(size_t)d * F + f] = v;
}

// ---------------------------------------------------------------------------
// Strip padded classifier output
// ---------------------------------------------------------------------------
__global__ void k_strip(float* __restrict__ O, int N) {
    size_t idx = (size_t)blockIdx.x * blockDim.x + threadIdx.x;
    size_t tot = (size_t)N * 100;
    if (idx >= tot) return;
    int i = (int)(idx / 100);
    int j = (int)(idx - (size_t)i * 100);
    O[idx] = g_outpad[(size_t)i * 128 + j];
}

// ---------------------------------------------------------------------------
// Launch — pure kernel launches, graph-capturable
// ---------------------------------------------------------------------------
static inline int cdiv(int a, int b) { return (a + b - 1) / b; }

extern "C" void kernel_launch(void* const* d_in, const int* in_sizes, int n_in,
                              void* d_out, int out_size) {
    const float* x  = (const float*)d_in[0];
    const int*   ei = (const int*)d_in[1];
    const float* W1 = (const float*)d_in[2];
    const float* b1 = (const float*)d_in[3];
    const float* W2 = (const float*)d_in[4];
    const float* b2 = (const float*)d_in[5];
    const float* W3 = (const float*)d_in[6];
    const float* b3 = (const float*)d_in[7];
    const float* Wc = (const float*)d_in[8];
    const float* bc = (const float*)d_in[9];

    const int N = in_sizes[0] / 256;
    const int E = in_sizes[1] / 2;

    float* out  = (float*)d_out;                    // [N,100]
    float* hout = (float*)d_out + (size_t)N * 100;  // [N,128]

    const int T = 256;
    const int G = cdiv(N, SCAN_ELEMS);
    const int RT = cdiv(N, 128);

    cudaFuncSetAttribute((const void*)gemm_tc<0, 0>, cudaFuncAttributeMaxDynamicSharedMemorySize, GEMM_DSM);
    cudaFuncSetAttribute((const void*)gemm_tc<0, 1>, cudaFuncAttributeMaxDynamicSharedMemorySize, GEMM_DSM);
    cudaFuncSetAttribute((const void*)gemm_tc<0, 2>, cudaFuncAttributeMaxDynamicSharedMemorySize, GEMM_DSM);
    cudaFuncSetAttribute((const void*)gemm_tc<1, 0>, cudaFuncAttributeMaxDynamicSharedMemorySize, GEMM_DSM);

    // --- edges -> CSR, degrees ---
    k_sniff<<<1, 32>>>(ei);
    k_decode<<<cdiv(E, T), T>>>(ei, E);
    k_zero<<<cdiv(N, T), T>>>(N);
    k_cnt<<<cdiv(E, T), T>>>(E);
    k_deg_fin<<<cdiv(N, T), T>>>(N);
    k_scan1<<<G, 256>>>(N);
    k_scan2<<<1, 512>>>(G, N);
    k_scan3<<<cdiv(N, T), T>>>(N);
    k_fill<<<cdiv(E, T), T>>>(E);

    // --- layer 1: pre-aggregate x into A-pair, GEMM (A -> C-pair, fused tanh) ---
    k_aggX<<<N, 64>>>(x, 256);                               // A-pair = split(A_hat @ x)
    k_conv_w<<<cdiv(256 * 1024, T), T>>>(W1, 256, 1024);
    gemm_tc<0, 2><<<dim3(1024 / 128, RT), 256, GEMM_DSM>>>(b1, N, 256, 1024);  // -> C-pair

    // --- layer 2: GEMM (C-pair -> g_H), aggregate -> A-pair ---
    k_conv_w<<<cdiv(1024 * 512, T), T>>>(W2, 1024, 512);
    gemm_tc<1, 0><<<dim3(512 / 128, RT), 256, GEMM_DSM>>>(nullptr, N, 1024, 512);
    k_aggregate<0><<<N, 128>>>(b2, nullptr, 512);

    // --- layer 3: GEMM (A-pair -> g_H), aggregate -> A-pair + hout ---
    k_conv_w<<<cdiv(512 * 128, T), T>>>(W3, 512, 128);
    gemm_tc<0, 0><<<dim3(1, RT), 256, GEMM_DSM>>>(nullptr, N, 512, 128);
    k_aggregate<1><<<N, 32>>>(b3, hout, 128);

    // --- classifier: GEMM (A-pair), sigmoid epilogue -> g_outpad ---
    k_conv_wc<<<cdiv(128 * 128, T), T>>>(Wc, bc);
    gemm_tc<0, 1><<<dim3(1, RT), 256, GEMM_DSM>>>(nullptr, N, 128, 128);
    k_strip<<<cdiv(N * 100, T), T>>>(out, N);
}

// round 15
// speedup vs baseline: 5.5604x; 1.2789x over previous
#include <cuda_runtime.h>
#include <cuda_fp16.h>
#include <math.h>
#include <stdint.h>

// ---------------------------------------------------------------------------
// Problem constants
// ---------------------------------------------------------------------------
#define MAXN 100000
#define MAXE 400000
#define FMAX 1024
#define SCAN_ELEMS 1024
#define WMAXE (1024 * 1024)

// ---------------------------------------------------------------------------
// Device scratch
// ---------------------------------------------------------------------------
__device__ int   g_is64;
__device__ int   g_src[MAXE];
__device__ int   g_dst[MAXE];
__device__ int   g_cnt[MAXN];
__device__ int   g_cur[MAXN];
__device__ int   g_off[MAXN + 1];
__device__ int   g_bsum[512];
__device__ int   g_bsumx[512];
__device__ int2  g_csr[MAXE];                                   // {src, w bits}
__device__ float g_dis[MAXN];
__device__ float g_dinv[MAXN];
__device__ float g_H[MAXN * FMAX];                              // GEMM out fp32
__device__ __align__(16) __half g_Ah[MAXN * FMAX];              // operand pair A: hi
__device__ __align__(16) __half g_Al[MAXN * FMAX];              // operand pair A: lo
__device__ __align__(16) __half g_Ch[MAXN * FMAX];              // operand C: hi (L1 out)
__device__ __align__(16) __half g_Cl[MAXN * FMAX];              // operand C: lo (unused path)
__device__ __align__(16) __half g_Bh[WMAXE];                    // W^T fp16 [M,K]
__device__ float g_bcp[128];

// ---------------------------------------------------------------------------
// PTX helpers
// ---------------------------------------------------------------------------
__device__ __forceinline__ uint32_t smem_u32(const void* p) {
    uint32_t a;
    asm("{ .reg .u64 t; cvta.to.shared.u64 t, %1; cvt.u32.u64 %0, t; }"
        : "=r"(a) : "l"(p));
    return a;
}
template <int NW>
__device__ __forceinline__ void cpwait() {
    asm volatile("cp.async.wait_group %0;" :: "n"(NW) : "memory");
}
__device__ __forceinline__ void cpcommit() {
    asm volatile("cp.async.commit_group;" ::: "memory");
}
__device__ __forceinline__ void cpasync16(uint32_t sa, const void* gp, int size) {
    asm volatile("cp.async.cg.shared.global [%0], [%1], 16, %2;"
                 :: "r"(sa), "l"(gp), "r"(size) : "memory");
}
__device__ __forceinline__ void mma16816(float* d, const uint32_t* a, const uint32_t* b) {
    asm volatile(
        "mma.sync.aligned.m16n8k16.row.col.f32.f16.f16.f32 "
        "{%0,%1,%2,%3}, {%4,%5,%6,%7}, {%8,%9}, {%0,%1,%2,%3};"
        : "+f"(d[0]), "+f"(d[1]), "+f"(d[2]), "+f"(d[3])
        : "r"(a[0]), "r"(a[1]), "r"(a[2]), "r"(a[3]), "r"(b[0]), "r"(b[1]));
}
__device__ __forceinline__ void ldsm_x4(uint32_t* r, uint32_t addr) {
    asm volatile("ldmatrix.sync.aligned.m8n8.x4.shared.b16 {%0,%1,%2,%3}, [%4];"
                 : "=r"(r[0]), "=r"(r[1]), "=r"(r[2]), "=r"(r[3]) : "r"(addr));
}

// ---------------------------------------------------------------------------
// Edge-index sniff + decode (int32 OR int64)
// ---------------------------------------------------------------------------
__global__ void k_sniff(const int* __restrict__ ei) {
    if (threadIdx.x == 0 && blockIdx.x == 0) {
        int acc = 0;
#pragma unroll
        for (int i = 0; i < 64; i++) acc |= ei[2 * i + 1];
        g_is64 = (acc == 0) ? 1 : 0;
    }
}
__global__ void k_decode(const int* __restrict__ ei, int E) {
    int e = blockIdx.x * blockDim.x + threadIdx.x;
    if (e >= E) return;
    if (g_is64) { g_src[e] = ei[2 * e]; g_dst[e] = ei[2 * (E + e)]; }
    else        { g_src[e] = ei[e];     g_dst[e] = ei[E + e]; }
}

// ---------------------------------------------------------------------------
// Degree / CSR construction
// ---------------------------------------------------------------------------
__global__ void k_zero(int n) {
    int i = blockIdx.x * blockDim.x + threadIdx.x;
    if (i < n) { g_cnt[i] = 0; g_cur[i] = 0; }
}
__global__ void k_cnt(int E) {
    int e = blockIdx.x * blockDim.x + threadIdx.x;
    if (e < E) atomicAdd(&g_cnt[g_dst[e]], 1);
}
__global__ void k_deg_fin(int n) {
    int i = blockIdx.x * blockDim.x + threadIdx.x;
    if (i < n) {
        float d = (float)(g_cnt[i] + 1);
        g_dis[i]  = rsqrtf(d);
        g_dinv[i] = 1.0f / d;
    }
}
__global__ void k_scan1(int n) {
    __shared__ int sh[256];
    int base = blockIdx.x * SCAN_ELEMS;
    int t = threadIdx.x;
    int v[4]; int sum = 0;
#pragma unroll
    for (int i = 0; i < 4; i++) {
        int idx = base + t * 4 + i;
        int c = (idx < n) ? g_cnt[idx] : 0;
        v[i] = sum; sum += c;
    }
    sh[t] = sum; __syncthreads();
#pragma unroll
    for (int o = 1; o < 256; o <<= 1) {
        int x = 0;
        if (t >= o) x = sh[t - o];
        __syncthreads();
        if (t >= o) sh[t] += x;
        __syncthreads();
    }
    int excl = (t > 0) ? sh[t - 1] : 0;
#pragma unroll
    for (int i = 0; i < 4; i++) {
        int idx = base + t * 4 + i;
        if (idx < n) g_off[idx] = excl + v[i];
    }
    if (t == 255) g_bsum[blockIdx.x] = sh[255];
}
__global__ void k_scan2(int G, int n) {
    __shared__ int sh[512];
    int t = threadIdx.x;
    sh[t] = (t < G) ? g_bsum[t] : 0;
    __syncthreads();
#pragma unroll
    for (int o = 1; o < 512; o <<= 1) {
        int x = 0;
        if (t >= o) x = sh[t - o];
        __syncthreads();
        if (t >= o) sh[t] += x;
        __syncthreads();
    }
    if (t < G) g_bsumx[t] = (t > 0) ? sh[t - 1] : 0;
    if (t == 0) g_off[n] = sh[511];
}
__global__ void k_scan3(int n) {
    int idx = blockIdx.x * blockDim.x + threadIdx.x;
    if (idx < n) g_off[idx] += g_bsumx[idx / SCAN_ELEMS];
}
__global__ void k_fill(int E) {
    int e = blockIdx.x * blockDim.x + threadIdx.x;
    if (e >= E) return;
    int s = g_src[e], d = g_dst[e];
    int p = g_off[d] + atomicAdd(&g_cur[d], 1);
    g_csr[p] = make_int2(s, __float_as_int(g_dis[s] * g_dis[d]));
}

// ---------------------------------------------------------------------------
// fp32 -> fp16 hi/lo split + weight conversion (weights: single fp16)
// ---------------------------------------------------------------------------
__device__ __forceinline__ void hsplit(float v, __half& h, __half& l) {
    h = __float2half(v);
    l = __float2half(v - __half2float(h));
}
__global__ void k_conv_w(const float* __restrict__ W, int K, int M) {  // -> W^T [M,K]
    int idx = blockIdx.x * blockDim.x + threadIdx.x;
    if (idx >= K * M) return;
    int k = idx / M, m = idx - k * M;
    g_Bh[(size_t)m * K + k] = __float2half(W[idx]);
}
__global__ void k_conv_wc(const float* __restrict__ Wc, const float* __restrict__ bc) {
    int idx = blockIdx.x * blockDim.x + threadIdx.x;
    if (idx < 128 * 128) {
        int k = idx >> 7, m = idx & 127;
        float v = (m < 100) ? Wc[k * 100 + m] : 0.0f;
        g_Bh[m * 128 + k] = __float2half(v);
    }
    if (idx < 128) g_bcp[idx] = (idx < 100) ? bc[idx] : 0.0f;
}

// ---------------------------------------------------------------------------
// Layer-1 pre-aggregation on raw x (aggregation commutes with the GEMM):
// agg[d,f] = sum_in x[s,f]*w + x[d,f]*dinv[d]  -> fp16 split into A-pair
// ---------------------------------------------------------------------------
__global__ void k_aggX(const float* __restrict__ x, int F) {
    const int d = blockIdx.x;
    const int f4 = threadIdx.x;
    const int f = f4 * 4;
    const int beg = g_off[d];
    const int end = g_off[d + 1];
    const int s4 = F >> 2;
    const float4* __restrict__ X4 = (const float4*)x;

    float4 acc = make_float4(0.f, 0.f, 0.f, 0.f);
    for (int p = beg; p < end; p++) {
        int2 sw = g_csr[p];
        float w = __int_as_float(sw.y);
        float4 h = X4[(size_t)sw.x * s4 + f4];
        acc.x = fmaf(h.x, w, acc.x);
        acc.y = fmaf(h.y, w, acc.y);
        acc.z = fmaf(h.z, w, acc.z);
        acc.w = fmaf(h.w, w, acc.w);
    }
    float dinv = g_dinv[d];
    float4 hd = X4[(size_t)d * s4 + f4];
    acc.x = fmaf(hd.x, dinv, acc.x);
    acc.y = fmaf(hd.y, dinv, acc.y);
    acc.z = fmaf(hd.z, dinv, acc.z);
    acc.w = fmaf(hd.w, dinv, acc.w);

    __half h0, l0, h1, l1, h2, l2, h3, l3;
    hsplit(acc.x, h0, l0); hsplit(acc.y, h1, l1);
    hsplit(acc.z, h2, l2); hsplit(acc.w, h3, l3);
    __half2* Ah2 = (__half2*)(g_Ah + (size_t)d * F + f);
    __half2* Al2 = (__half2*)(g_Al + (size_t)d * F + f);
    Ah2[0] = __halves2half2(h0, h1); Ah2[1] = __halves2half2(h2, h3);
    Al2[0] = __halves2half2(l0, l1); Al2[1] = __halves2half2(l2, l3);
}

// ---------------------------------------------------------------------------
// mma.sync fp16 GEMM with ldmatrix operand loads.
// C[Nrows,M] = A @ B^T.  ASEL 0: A = g_Ah/g_Al;  ASEL 1: A = g_Ch/g_Cl.
// NTERM 2: A split hi/lo (2 MMAs); NTERM 1: single fp16 A (1 MMA).
// EPI 0: C -> g_H fp32.
// EPI 1: sigmoid(C + g_bcp) -> Oext[N,100] direct (col<100 predicate).
// EPI 3: tanh(C + bias) -> g_Ch only (layer-1 output; consumer uses NTERM=1).
// ---------------------------------------------------------------------------
#define SAH 40                    // smem stride in halves
#define MAT_B (128 * SAH * 2)     // 10240 B per matrix tile
#define GEMM_DSM_MAX (2 * 3 * MAT_B)   // 61440 B (3-matrix variant)

template <int ASEL, int EPI, int NTERM>
__global__ __launch_bounds__(256, 2) void gemm_tc(const float* __restrict__ bias,
                                                  float* __restrict__ Oext,
                                                  int Nrows, int K, int M) {
    extern __shared__ char dsm[];
    const uint32_t sb = smem_u32(dsm);
    constexpr int NMAT  = NTERM + 1;
    constexpr int BUFB  = NMAT * MAT_B;

    const __half* __restrict__ Ah = (ASEL == 0) ? g_Ah : g_Ch;
    const __half* __restrict__ Al = (ASEL == 0) ? g_Al : g_Cl;

    const int tid  = threadIdx.x;
    const int lane = tid & 31;
    const int w    = tid >> 5;
    const int wr   = w >> 2;
    const int wc   = w & 3;
    const int cBase = blockIdx.x * 128;
    const int rBase = blockIdx.y * 128;

    float acc[4][4][4];
#pragma unroll
    for (int a = 0; a < 4; a++)
#pragma unroll
        for (int b = 0; b < 4; b++)
#pragma unroll
            for (int c = 0; c < 4; c++) acc[a][b][c] = 0.0f;

    const int nch = K / 32;

    const int aRow = wr * 64 + (lane & 15);
    const int aK   = (lane >> 4) * 8;
    const int bRow = wc * 32 + (lane & 7) + ((lane & 16) ? 8 : 0);
    const int bK   = ((lane & 8) ? 8 : 0);

    auto load_chunk = [&](int c, int buf) {
        const int k0 = c * 32;
#pragma unroll
        for (int i = 0; i < 2 * NMAT; i++) {
            int seg = i * 256 + tid;
            int mat = seg >> 9;                 // 0..NMAT-1
            int s   = seg & 511;
            int row = s >> 2;
            int part = s & 3;
            uint32_t sa = sb + buf * BUFB + mat * MAT_B + row * (SAH * 2) + part * 16;
            const __half* gp;
            int size = 16;
            if (mat < NTERM) {
                int gr = rBase + row;
                int r2 = (gr < Nrows) ? gr : 0;
                size = (gr < Nrows) ? 16 : 0;
                gp = ((mat == 0) ? Ah : Al) + (size_t)r2 * K + k0 + part * 8;
            } else {
                int gc = cBase + row;
                gp = g_Bh + (size_t)gc * K + k0 + part * 8;
            }
            cpasync16(sa, gp, size);
        }
        cpcommit();
    };

    load_chunk(0, 0);

    for (int c = 0; c < nch; c++) {
        const int buf = c & 1;
        if (c + 1 < nch) { load_chunk(c + 1, (c + 1) & 1); cpwait<1>(); }
        else             { cpwait<0>(); }
        __syncthreads();

        const uint32_t bA_h = sb + buf * BUFB + 0 * MAT_B;
        const uint32_t bA_l = sb + buf * BUFB + 1 * MAT_B;
        const uint32_t bB_h = sb + buf * BUFB + NTERM * MAT_B;

#pragma unroll
        for (int ks = 0; ks < 2; ks++) {
            const int kk = ks * 16;
            uint32_t bh[8];
            ldsm_x4(&bh[0], bB_h + ((bRow)      * SAH + kk + bK) * 2);
            ldsm_x4(&bh[4], bB_h + ((bRow + 16) * SAH + kk + bK) * 2);
#pragma unroll
            for (int mt = 0; mt < 4; mt++) {
                uint32_t ah[4];
                ldsm_x4(ah, bA_h + ((aRow + mt * 16) * SAH + kk + aK) * 2);
                uint32_t al[4];
                if (NTERM == 2)
                    ldsm_x4(al, bA_l + ((aRow + mt * 16) * SAH + kk + aK) * 2);
#pragma unroll
                for (int nt = 0; nt < 4; nt++) {
                    mma16816(acc[mt][nt], ah, &bh[nt * 2]);
                    if (NTERM == 2)
                        mma16816(acc[mt][nt], al, &bh[nt * 2]);
                }
            }
        }
        __syncthreads();
    }

    // Epilogue
#pragma unroll
    for (int mt = 0; mt < 4; mt++) {
#pragma unroll
        for (int nt = 0; nt < 4; nt++) {
            const int row0 = rBase + wr * 64 + mt * 16 + (lane >> 2);
            const int col  = cBase + wc * 32 + nt * 8 + (lane & 3) * 2;
            float* a = acc[mt][nt];
            if (EPI == 0) {
                if (row0 < Nrows)
                    *(float2*)&g_H[(size_t)row0 * M + col] = make_float2(a[0], a[1]);
                if (row0 + 8 < Nrows)
                    *(float2*)&g_H[(size_t)(row0 + 8) * M + col] = make_float2(a[2], a[3]);
            } else if (EPI == 1) {
                if (col < 100) {
                    float s0 = 1.0f / (1.0f + expf(-(a[0] + g_bcp[col])));
                    float s1 = 1.0f / (1.0f + expf(-(a[1] + g_bcp[col + 1])));
                    float s2 = 1.0f / (1.0f + expf(-(a[2] + g_bcp[col])));
                    float s3 = 1.0f / (1.0f + expf(-(a[3] + g_bcp[col + 1])));
                    if (row0 < Nrows)
                        *(float2*)&Oext[(size_t)row0 * 100 + col] = make_float2(s0, s1);
                    if (row0 + 8 < Nrows)
                        *(float2*)&Oext[(size_t)(row0 + 8) * 100 + col] = make_float2(s2, s3);
                }
            } else {
                float b0 = bias[col], b1v = bias[col + 1];
                float v0 = tanhf(a[0] + b0);
                float v1 = tanhf(a[1] + b1v);
                float v2 = tanhf(a[2] + b0);
                float v3 = tanhf(a[3] + b1v);
                if (row0 < Nrows)
                    *(__half2*)&g_Ch[(size_t)row0 * M + col] =
                        __halves2half2(__float2half(v0), __float2half(v1));
                if (row0 + 8 < Nrows)
                    *(__half2*)&g_Ch[(size_t)(row0 + 8) * M + col] =
                        __halves2half2(__float2half(v2), __float2half(v3));
            }
        }
    }
}

// ---------------------------------------------------------------------------
// Fused aggregate (layers 2/3): one block per node, float4 per thread.
// v = tanh( sum_in H[s,f]*w + H[d,f]*dinv[d] + b[f] )  -> A-pair (fp16 split)
// Optional fp32 to Oext (layer 3).
// ---------------------------------------------------------------------------
template <int WRITE_F32>
__global__ void k_aggregate(const float* __restrict__ bias, float* __restrict__ Oext,
                            int F) {
    const int d = blockIdx.x;
    const int f4 = threadIdx.x;
    const int f = f4 * 4;
    const int beg = g_off[d];
    const int end = g_off[d + 1];
    const int s4 = F >> 2;
    const float4* __restrict__ H4 = (const float4*)g_H;

    float4 acc = make_float4(0.f, 0.f, 0.f, 0.f);
    for (int p = beg; p < end; p++) {
        int2 sw = g_csr[p];
        float w = __int_as_float(sw.y);
        float4 h = H4[(size_t)sw.x * s4 + f4];
        acc.x = fmaf(h.x, w, acc.x);
        acc.y = fmaf(h.y, w, acc.y);
        acc.z = fmaf(h.z, w, acc.z);
        acc.w = fmaf(h.w, w, acc.w);
    }
    float dinv = g_dinv[d];
    float4 hd = H4[(size_t)d * s4 + f4];
    acc.x = fmaf(hd.x, dinv, acc.x);
    acc.y = fmaf(hd.y, dinv, acc.y);
    acc.z = fmaf(hd.z, dinv, acc.z);
    acc.w = fmaf(hd.w, dinv, acc.w);
    float4 b = *(const float4*)&bias[f];
    float4 v;
    v.x = tanhf(acc.x + b.x);
    v.y = tanhf(acc.y + b.y);
    v.z = tanhf(acc.z + b.z);
    v.w = tanhf(acc.w + b.w);

    __half h0, l0, h1, l1, h2, l2, h3, l3;
    hsplit(v.x, h0, l0); hsplit(v.y, h1, l1);
    hsplit(v.z, h2, l2); hsplit(v.w, h3, l3);
    __half2* Ah2 = (__half2*)(g_Ah + (size_t)d * F + f);
    __half2* Al2 = (__half2*)(g_Al + (size_t)d * F + f);
    Ah2[0] = __halves2half2(h0, h1); Ah2[1] = __halves2half2(h2, h3);
    Al2[0] = __halves2half2(l0, l1); Al2[1] = __halves2half2(l2, l3);
    if (WRITE_F32) *(float4*)&Oext[(size_t)d * F + f] = v;
}

// ---------------------------------------------------------------------------
// Launch — pure kernel launches, graph-capturable
// ---------------------------------------------------------------------------
static inline int cdiv(int a, int b) { return (a + b - 1) / b; }

extern "C" void kernel_launch(void* const* d_in, const int* in_sizes, int n_in,
                              void* d_out, int out_size) {
    const float* x  = (const float*)d_in[0];
    const int*   ei = (const int*)d_in[1];
    const float* W1 = (const float*)d_in[2];
    const float* b1 = (const float*)d_in[3];
    const float* W2 = (const float*)d_in[4];
    const float* b2 = (const float*)d_in[5];
    const float* W3 = (const float*)d_in[6];
    const float* b3 = (const float*)d_in[7];
    const float* Wc = (const float*)d_in[8];
    const float* bc = (const float*)d_in[9];

    const int N = in_sizes[0] / 256;
    const int E = in_sizes[1] / 2;

    float* out  = (float*)d_out;                    // [N,100]
    float* hout = (float*)d_out + (size_t)N * 100;  // [N,128]

    const int T = 256;
    const int G = cdiv(N, SCAN_ELEMS);
    const int RT = cdiv(N, 128);

    cudaFuncSetAttribute((const void*)gemm_tc<0, 3, 2>, cudaFuncAttributeMaxDynamicSharedMemorySize, GEMM_DSM_MAX);
    cudaFuncSetAttribute((const void*)gemm_tc<1, 0, 1>, cudaFuncAttributeMaxDynamicSharedMemorySize, GEMM_DSM_MAX);
    cudaFuncSetAttribute((const void*)gemm_tc<0, 0, 2>, cudaFuncAttributeMaxDynamicSharedMemorySize, GEMM_DSM_MAX);
    cudaFuncSetAttribute((const void*)gemm_tc<0, 1, 2>, cudaFuncAttributeMaxDynamicSharedMemorySize, GEMM_DSM_MAX);

    // --- edges -> CSR, degrees ---
    k_sniff<<<1, 32>>>(ei);
    k_decode<<<cdiv(E, T), T>>>(ei, E);
    k_zero<<<cdiv(N, T), T>>>(N);
    k_cnt<<<cdiv(E, T), T>>>(E);
    k_deg_fin<<<cdiv(N, T), T>>>(N);
    k_scan1<<<G, 256>>>(N);
    k_scan2<<<1, 512>>>(G, N);
    k_scan3<<<cdiv(N, T), T>>>(N);
    k_fill<<<cdiv(E, T), T>>>(E);

    // --- layer 1: pre-aggregate x into A-pair, GEMM (2-term, tanh -> g_Ch) ---
    k_aggX<<<N, 64>>>(x, 256);
    k_conv_w<<<cdiv(256 * 1024, T), T>>>(W1, 256, 1024);
    gemm_tc<0, 3, 2><<<dim3(1024 / 128, RT), 256, 2 * 3 * MAT_B>>>(b1, nullptr, N, 256, 1024);

    // --- layer 2: single-fp16 GEMM (g_Ch -> g_H), aggregate -> A-pair ---
    k_conv_w<<<cdiv(1024 * 512, T), T>>>(W2, 1024, 512);
    gemm_tc<1, 0, 1><<<dim3(512 / 128, RT), 256, 2 * 2 * MAT_B>>>(nullptr, nullptr, N, 1024, 512);
    k_aggregate<0><<<N, 128>>>(b2, nullptr, 512);

    // --- layer 3: 2-term GEMM (A-pair -> g_H), aggregate -> A-pair + hout ---
    k_conv_w<<<cdiv(512 * 128, T), T>>>(W3, 512, 128);
    gemm_tc<0, 0, 2><<<dim3(1, RT), 256, 2 * 3 * MAT_B>>>(nullptr, nullptr, N, 512, 128);
    k_aggregate<1><<<N, 32>>>(b3, hout, 128);

    // --- classifier: 2-term GEMM (A-pair), sigmoid -> out[N,100] direct ---
    k_conv_wc<<<cdiv(128 * 128, T), T>>>(Wc, bc);
    gemm_tc<0, 1, 2><<<dim3(1, RT), 256, 2 * 3 * MAT_B>>>(nullptr, out, N, 128, 128);
}

// round 16
// speedup vs baseline: 6.4888x; 1.1670x over previous
#include <cuda_runtime.h>
#include <cuda_fp16.h>
#include <math.h>
#include <stdint.h>

// ---------------------------------------------------------------------------
// Problem constants
// ---------------------------------------------------------------------------
#define MAXN 100000
#define MAXE 400000
#define FMAX 1024
#define SCAN_ELEMS 1024
#define WMAXE (1024 * 1024)

// ---------------------------------------------------------------------------
// Device scratch
// ---------------------------------------------------------------------------
__device__ int   g_is64;
__device__ int   g_src[MAXE];
__device__ int   g_dst[MAXE];
__device__ int   g_cnt[MAXN];
__device__ int   g_cur[MAXN];
__device__ int   g_off[MAXN + 1];
__device__ int   g_bsum[512];
__device__ int   g_bsumx[512];
__device__ int2  g_csr[MAXE];                                   // {src, w bits}
__device__ float g_dis[MAXN];
__device__ float g_dinv[MAXN];
__device__ __align__(16) __half g_Hh[MAXN * FMAX];              // GEMM out (fp16)
__device__ __align__(16) __half g_Ah[MAXN * FMAX];              // operand pair A: hi
__device__ __align__(16) __half g_Al[MAXN * FMAX];              // operand pair A: lo
__device__ __align__(16) __half g_Ch[MAXN * FMAX];              // L1 output (fp16)
__device__ __align__(16) __half g_Bh[WMAXE];                    // W^T fp16 [M,K]
__device__ float g_bcp[128];

// ---------------------------------------------------------------------------
// PTX helpers
// ---------------------------------------------------------------------------
__device__ __forceinline__ uint32_t smem_u32(const void* p) {
    uint32_t a;
    asm("{ .reg .u64 t; cvta.to.shared.u64 t, %1; cvt.u32.u64 %0, t; }"
        : "=r"(a) : "l"(p));
    return a;
}
template <int NW>
__device__ __forceinline__ void cpwait() {
    asm volatile("cp.async.wait_group %0;" :: "n"(NW) : "memory");
}
__device__ __forceinline__ void cpcommit() {
    asm volatile("cp.async.commit_group;" ::: "memory");
}
__device__ __forceinline__ void cpasync16(uint32_t sa, const void* gp, int size) {
    asm volatile("cp.async.cg.shared.global [%0], [%1], 16, %2;"
                 :: "r"(sa), "l"(gp), "r"(size) : "memory");
}
__device__ __forceinline__ void mma16816(float* d, const uint32_t* a, const uint32_t* b) {
    asm volatile(
        "mma.sync.aligned.m16n8k16.row.col.f32.f16.f16.f32 "
        "{%0,%1,%2,%3}, {%4,%5,%6,%7}, {%8,%9}, {%0,%1,%2,%3};"
        : "+f"(d[0]), "+f"(d[1]), "+f"(d[2]), "+f"(d[3])
        : "r"(a[0]), "r"(a[1]), "r"(a[2]), "r"(a[3]), "r"(b[0]), "r"(b[1]));
}
__device__ __forceinline__ void ldsm_x4(uint32_t* r, uint32_t addr) {
    asm volatile("ldmatrix.sync.aligned.m8n8.x4.shared.b16 {%0,%1,%2,%3}, [%4];"
                 : "=r"(r[0]), "=r"(r[1]), "=r"(r[2]), "=r"(r[3]) : "r"(addr));
}

// ---------------------------------------------------------------------------
// Edge-index sniff + decode (int32 OR int64)
// ---------------------------------------------------------------------------
__global__ void k_sniff(const int* __restrict__ ei) {
    if (threadIdx.x == 0 && blockIdx.x == 0) {
        int acc = 0;
#pragma unroll
        for (int i = 0; i < 64; i++) acc |= ei[2 * i + 1];
        g_is64 = (acc == 0) ? 1 : 0;
    }
}
__global__ void k_decode(const int* __restrict__ ei, int E) {
    int e = blockIdx.x * blockDim.x + threadIdx.x;
    if (e >= E) return;
    if (g_is64) { g_src[e] = ei[2 * e]; g_dst[e] = ei[2 * (E + e)]; }
    else        { g_src[e] = ei[e];     g_dst[e] = ei[E + e]; }
}

// ---------------------------------------------------------------------------
// Degree / CSR construction
// ---------------------------------------------------------------------------
__global__ void k_zero(int n) {
    int i = blockIdx.x * blockDim.x + threadIdx.x;
    if (i < n) { g_cnt[i] = 0; g_cur[i] = 0; }
}
__global__ void k_cnt(int E) {
    int e = blockIdx.x * blockDim.x + threadIdx.x;
    if (e < E) atomicAdd(&g_cnt[g_dst[e]], 1);
}
__global__ void k_deg_fin(int n) {
    int i = blockIdx.x * blockDim.x + threadIdx.x;
    if (i < n) {
        float d = (float)(g_cnt[i] + 1);
        g_dis[i]  = rsqrtf(d);
        g_dinv[i] = 1.0f / d;
    }
}
__global__ void k_scan1(int n) {
    __shared__ int sh[256];
    int base = blockIdx.x * SCAN_ELEMS;
    int t = threadIdx.x;
    int v[4]; int sum = 0;
#pragma unroll
    for (int i = 0; i < 4; i++) {
        int idx = base + t * 4 + i;
        int c = (idx < n) ? g_cnt[idx] : 0;
        v[i] = sum; sum += c;
    }
    sh[t] = sum; __syncthreads();
#pragma unroll
    for (int o = 1; o < 256; o <<= 1) {
        int x = 0;
        if (t >= o) x = sh[t - o];
        __syncthreads();
        if (t >= o) sh[t] += x;
        __syncthreads();
    }
    int excl = (t > 0) ? sh[t - 1] : 0;
#pragma unroll
    for (int i = 0; i < 4; i++) {
        int idx = base + t * 4 + i;
        if (idx < n) g_off[idx] = excl + v[i];
    }
    if (t == 255) g_bsum[blockIdx.x] = sh[255];
}
__global__ void k_scan2(int G, int n) {
    __shared__ int sh[512];
    int t = threadIdx.x;
    sh[t] = (t < G) ? g_bsum[t] : 0;
    __syncthreads();
#pragma unroll
    for (int o = 1; o < 512; o <<= 1) {
        int x = 0;
        if (t >= o) x = sh[t - o];
        __syncthreads();
        if (t >= o) sh[t] += x;
        __syncthreads();
    }
    if (t < G) g_bsumx[t] = (t > 0) ? sh[t - 1] : 0;
    if (t == 0) g_off[n] = sh[511];
}
__global__ void k_scan3(int n) {
    int idx = blockIdx.x * blockDim.x + threadIdx.x;
    if (idx < n) g_off[idx] += g_bsumx[idx / SCAN_ELEMS];
}
__global__ void k_fill(int E) {
    int e = blockIdx.x * blockDim.x + threadIdx.x;
    if (e >= E) return;
    int s = g_src[e], d = g_dst[e];
    int p = g_off[d] + atomicAdd(&g_cur[d], 1);
    g_csr[p] = make_int2(s, __float_as_int(g_dis[s] * g_dis[d]));
}

// ---------------------------------------------------------------------------
// fp32 -> fp16 hi/lo split + weight conversion (weights: single fp16)
// ---------------------------------------------------------------------------
__device__ __forceinline__ void hsplit(float v, __half& h, __half& l) {
    h = __float2half(v);
    l = __float2half(v - __half2float(h));
}
__global__ void k_conv_w(const float* __restrict__ W, int K, int M) {  // -> W^T [M,K]
    int idx = blockIdx.x * blockDim.x + threadIdx.x;
    if (idx >= K * M) return;
    int k = idx / M, m = idx - k * M;
    g_Bh[(size_t)m * K + k] = __float2half(W[idx]);
}
__global__ void k_conv_wc(const float* __restrict__ Wc, const float* __restrict__ bc) {
    int idx = blockIdx.x * blockDim.x + threadIdx.x;
    if (idx < 128 * 128) {
        int k = idx >> 7, m = idx & 127;
        float v = (m < 100) ? Wc[k * 100 + m] : 0.0f;
        g_Bh[m * 128 + k] = __float2half(v);
    }
    if (idx < 128) g_bcp[idx] = (idx < 100) ? bc[idx] : 0.0f;
}

// ---------------------------------------------------------------------------
// Layer-1 pre-aggregation on raw x (aggregation commutes with the GEMM):
// agg[d,f] = sum_in x[s,f]*w + x[d,f]*dinv[d]  -> single fp16 into g_Ah
// ---------------------------------------------------------------------------
__global__ void k_aggX(const float* __restrict__ x, int F) {
    const int d = blockIdx.x;
    const int f4 = threadIdx.x;
    const int f = f4 * 4;
    const int beg = g_off[d];
    const int end = g_off[d + 1];
    const int s4 = F >> 2;
    const float4* __restrict__ X4 = (const float4*)x;

    float4 acc = make_float4(0.f, 0.f, 0.f, 0.f);
    for (int p = beg; p < end; p++) {
        int2 sw = g_csr[p];
        float w = __int_as_float(sw.y);
        float4 h = X4[(size_t)sw.x * s4 + f4];
        acc.x = fmaf(h.x, w, acc.x);
        acc.y = fmaf(h.y, w, acc.y);
        acc.z = fmaf(h.z, w, acc.z);
        acc.w = fmaf(h.w, w, acc.w);
    }
    float dinv = g_dinv[d];
    float4 hd = X4[(size_t)d * s4 + f4];
    acc.x = fmaf(hd.x, dinv, acc.x);
    acc.y = fmaf(hd.y, dinv, acc.y);
    acc.z = fmaf(hd.z, dinv, acc.z);
    acc.w = fmaf(hd.w, dinv, acc.w);

    __half2* Ah2 = (__half2*)(g_Ah + (size_t)d * F + f);
    Ah2[0] = __halves2half2(__float2half(acc.x), __float2half(acc.y));
    Ah2[1] = __halves2half2(__float2half(acc.z), __float2half(acc.w));
}

// ---------------------------------------------------------------------------
// mma.sync fp16 GEMM with ldmatrix operand loads.
// C[Nrows,M] = A @ B^T.  ASEL 0: A = g_Ah/g_Al;  ASEL 1: A = g_Ch (1-term only).
// NTERM 2: A split hi/lo (2 MMAs); NTERM 1: single fp16 A (1 MMA).
// EPI 0: C -> g_Hh (fp16).
// EPI 1: sigmoid(C + g_bcp) -> Oext[N,100] direct (col<100 predicate).
// EPI 3: tanh(C + bias) -> g_Ch (fp16, layer-1 output; consumer NTERM=1).
// ---------------------------------------------------------------------------
#define SAH 40                    // smem stride in halves
#define MAT_B (128 * SAH * 2)     // 10240 B per matrix tile
#define GEMM_DSM_MAX (2 * 3 * MAT_B)   // 61440 B (3-matrix variant)

template <int ASEL, int EPI, int NTERM>
__global__ __launch_bounds__(256, 2) void gemm_tc(const float* __restrict__ bias,
                                                  float* __restrict__ Oext,
                                                  int Nrows, int K, int M) {
    extern __shared__ char dsm[];
    const uint32_t sb = smem_u32(dsm);
    constexpr int NMAT  = NTERM + 1;
    constexpr int BUFB  = NMAT * MAT_B;

    const __half* __restrict__ Ah = (ASEL == 0) ? g_Ah : g_Ch;
    const __half* __restrict__ Al = g_Al;   // only read when NTERM == 2 (ASEL 0)

    const int tid  = threadIdx.x;
    const int lane = tid & 31;
    const int w    = tid >> 5;
    const int wr   = w >> 2;
    const int wc   = w & 3;
    const int cBase = blockIdx.x * 128;
    const int rBase = blockIdx.y * 128;

    float acc[4][4][4];
#pragma unroll
    for (int a = 0; a < 4; a++)
#pragma unroll
        for (int b = 0; b < 4; b++)
#pragma unroll
            for (int c = 0; c < 4; c++) acc[a][b][c] = 0.0f;

    const int nch = K / 32;

    const int aRow = wr * 64 + (lane & 15);
    const int aK   = (lane >> 4) * 8;
    const int bRow = wc * 32 + (lane & 7) + ((lane & 16) ? 8 : 0);
    const int bK   = ((lane & 8) ? 8 : 0);

    auto load_chunk = [&](int c, int buf) {
        const int k0 = c * 32;
#pragma unroll
        for (int i = 0; i < 2 * NMAT; i++) {
            int seg = i * 256 + tid;
            int mat = seg >> 9;                 // 0..NMAT-1
            int s   = seg & 511;
            int row = s >> 2;
            int part = s & 3;
            uint32_t sa = sb + buf * BUFB + mat * MAT_B + row * (SAH * 2) + part * 16;
            const __half* gp;
            int size = 16;
            if (mat < NTERM) {
                int gr = rBase + row;
                int r2 = (gr < Nrows) ? gr : 0;
                size = (gr < Nrows) ? 16 : 0;
                gp = ((mat == 0) ? Ah : Al) + (size_t)r2 * K + k0 + part * 8;
            } else {
                int gc = cBase + row;
                gp = g_Bh + (size_t)gc * K + k0 + part * 8;
            }
            cpasync16(sa, gp, size);
        }
        cpcommit();
    };

    load_chunk(0, 0);

    for (int c = 0; c < nch; c++) {
        const int buf = c & 1;
        if (c + 1 < nch) { load_chunk(c + 1, (c + 1) & 1); cpwait<1>(); }
        else             { cpwait<0>(); }
        __syncthreads();

        const uint32_t bA_h = sb + buf * BUFB + 0 * MAT_B;
        const uint32_t bA_l = sb + buf * BUFB + 1 * MAT_B;
        const uint32_t bB_h = sb + buf * BUFB + NTERM * MAT_B;

#pragma unroll
        for (int ks = 0; ks < 2; ks++) {
            const int kk = ks * 16;
            uint32_t bh[8];
            ldsm_x4(&bh[0], bB_h + ((bRow)      * SAH + kk + bK) * 2);
            ldsm_x4(&bh[4], bB_h + ((bRow + 16) * SAH + kk + bK) * 2);
#pragma unroll
            for (int mt = 0; mt < 4; mt++) {
                uint32_t ah[4];
                ldsm_x4(ah, bA_h + ((aRow + mt * 16) * SAH + kk + aK) * 2);
                uint32_t al[4];
                if (NTERM == 2)
                    ldsm_x4(al, bA_l + ((aRow + mt * 16) * SAH + kk + aK) * 2);
#pragma unroll
                for (int nt = 0; nt < 4; nt++) {
                    mma16816(acc[mt][nt], ah, &bh[nt * 2]);
                    if (NTERM == 2)
                        mma16816(acc[mt][nt], al, &bh[nt * 2]);
                }
            }
        }
        __syncthreads();
    }

    // Epilogue
#pragma unroll
    for (int mt = 0; mt < 4; mt++) {
#pragma unroll
        for (int nt = 0; nt < 4; nt++) {
            const int row0 = rBase + wr * 64 + mt * 16 + (lane >> 2);
            const int col  = cBase + wc * 32 + nt * 8 + (lane & 3) * 2;
            float* a = acc[mt][nt];
            if (EPI == 0) {
                if (row0 < Nrows)
                    *(__half2*)&g_Hh[(size_t)row0 * M + col] =
                        __halves2half2(__float2half(a[0]), __float2half(a[1]));
                if (row0 + 8 < Nrows)
                    *(__half2*)&g_Hh[(size_t)(row0 + 8) * M + col] =
                        __halves2half2(__float2half(a[2]), __float2half(a[3]));
            } else if (EPI == 1) {
                if (col < 100) {
                    float s0 = 1.0f / (1.0f + expf(-(a[0] + g_bcp[col])));
                    float s1 = 1.0f / (1.0f + expf(-(a[1] + g_bcp[col + 1])));
                    float s2 = 1.0f / (1.0f + expf(-(a[2] + g_bcp[col])));
                    float s3 = 1.0f / (1.0f + expf(-(a[3] + g_bcp[col + 1])));
                    if (row0 < Nrows)
                        *(float2*)&Oext[(size_t)row0 * 100 + col] = make_float2(s0, s1);
                    if (row0 + 8 < Nrows)
                        *(float2*)&Oext[(size_t)(row0 + 8) * 100 + col] = make_float2(s2, s3);
                }
            } else {
                float b0 = bias[col], b1v = bias[col + 1];
                float v0 = tanhf(a[0] + b0);
                float v1 = tanhf(a[1] + b1v);
                float v2 = tanhf(a[2] + b0);
                float v3 = tanhf(a[3] + b1v);
                if (row0 < Nrows)
                    *(__half2*)&g_Ch[(size_t)row0 * M + col] =
                        __halves2half2(__float2half(v0), __float2half(v1));
                if (row0 + 8 < Nrows)
                    *(__half2*)&g_Ch[(size_t)(row0 + 8) * M + col] =
                        __halves2half2(__float2half(v2), __float2half(v3));
            }
        }
    }
}

// ---------------------------------------------------------------------------
// Fused aggregate (layers 2/3): one block per node, 4 cols per thread.
// Reads fp16 H (g_Hh), fp32 accumulation:
// v = tanh( sum_in H[s,f]*w + H[d,f]*dinv[d] + b[f] )  -> A-pair (fp16 split)
// Optional fp32 to Oext (layer 3).
// ---------------------------------------------------------------------------
template <int WRITE_F32>
__global__ void k_aggregate(const float* __restrict__ bias, float* __restrict__ Oext,
                            int F) {
    const int d = blockIdx.x;
    const int f4 = threadIdx.x;
    const int f = f4 * 4;
    const int beg = g_off[d];
    const int end = g_off[d + 1];

    float4 acc = make_float4(0.f, 0.f, 0.f, 0.f);
    for (int p = beg; p < end; p++) {
        int2 sw = g_csr[p];
        float w = __int_as_float(sw.y);
        uint2 raw = *(const uint2*)(g_Hh + (size_t)sw.x * F + f);
        float2 p0 = __half22float2(*(__half2*)&raw.x);
        float2 p1 = __half22float2(*(__half2*)&raw.y);
        acc.x = fmaf(p0.x, w, acc.x);
        acc.y = fmaf(p0.y, w, acc.y);
        acc.z = fmaf(p1.x, w, acc.z);
        acc.w = fmaf(p1.y, w, acc.w);
    }
    float dinv = g_dinv[d];
    {
        uint2 raw = *(const uint2*)(g_Hh + (size_t)d * F + f);
        float2 p0 = __half22float2(*(__half2*)&raw.x);
        float2 p1 = __half22float2(*(__half2*)&raw.y);
        acc.x = fmaf(p0.x, dinv, acc.x);
        acc.y = fmaf(p0.y, dinv, acc.y);
        acc.z = fmaf(p1.x, dinv, acc.z);
        acc.w = fmaf(p1.y, dinv, acc.w);
    }
    float4 b = *(const float4*)&bias[f];
    float4 v;
    v.x = tanhf(acc.x + b.x);
    v.y = tanhf(acc.y + b.y);
    v.z = tanhf(acc.z + b.z);
    v.w = tanhf(acc.w + b.w);

    __half h0, l0, h1, l1, h2, l2, h3, l3;
    hsplit(v.x, h0, l0); hsplit(v.y, h1, l1);
    hsplit(v.z, h2, l2); hsplit(v.w, h3, l3);
    __half2* Ah2 = (__half2*)(g_Ah + (size_t)d * F + f);
    __half2* Al2 = (__half2*)(g_Al + (size_t)d * F + f);
    Ah2[0] = __halves2half2(h0, h1); Ah2[1] = __halves2half2(h2, h3);
    Al2[0] = __halves2half2(l0, l1); Al2[1] = __halves2half2(l2, l3);
    if (WRITE_F32) *(float4*)&Oext[(size_t)d * F + f] = v;
}

// ---------------------------------------------------------------------------
// Launch — pure kernel launches, graph-capturable
// ---------------------------------------------------------------------------
static inline int cdiv(int a, int b) { return (a + b - 1) / b; }

extern "C" void kernel_launch(void* const* d_in, const int* in_sizes, int n_in,
                              void* d_out, int out_size) {
    const float* x  = (const float*)d_in[0];
    const int*   ei = (const int*)d_in[1];
    const float* W1 = (const float*)d_in[2];
    const float* b1 = (const float*)d_in[3];
    const float* W2 = (const float*)d_in[4];
    const float* b2 = (const float*)d_in[5];
    const float* W3 = (const float*)d_in[6];
    const float* b3 = (const float*)d_in[7];
    const float* Wc = (const float*)d_in[8];
    const float* bc = (const float*)d_in[9];

    const int N = in_sizes[0] / 256;
    const int E = in_sizes[1] / 2;

    float* out  = (float*)d_out;                    // [N,100]
    float* hout = (float*)d_out + (size_t)N * 100;  // [N,128]

    const int T = 256;
    const int G = cdiv(N, SCAN_ELEMS);
    const int RT = cdiv(N, 128);

    cudaFuncSetAttribute((const void*)gemm_tc<0, 3, 1>, cudaFuncAttributeMaxDynamicSharedMemorySize, GEMM_DSM_MAX);
    cudaFuncSetAttribute((const void*)gemm_tc<1, 0, 1>, cudaFuncAttributeMaxDynamicSharedMemorySize, GEMM_DSM_MAX);
    cudaFuncSetAttribute((const void*)gemm_tc<0, 0, 2>, cudaFuncAttributeMaxDynamicSharedMemorySize, GEMM_DSM_MAX);
    cudaFuncSetAttribute((const void*)gemm_tc<0, 1, 2>, cudaFuncAttributeMaxDynamicSharedMemorySize, GEMM_DSM_MAX);

    // --- edges -> CSR, degrees ---
    k_sniff<<<1, 32>>>(ei);
    k_decode<<<cdiv(E, T), T>>>(ei, E);
    k_zero<<<cdiv(N, T), T>>>(N);
    k_cnt<<<cdiv(E, T), T>>>(E);
    k_deg_fin<<<cdiv(N, T), T>>>(N);
    k_scan1<<<G, 256>>>(N);
    k_scan2<<<1, 512>>>(G, N);
    k_scan3<<<cdiv(N, T), T>>>(N);
    k_fill<<<cdiv(E, T), T>>>(E);

    // --- layer 1: pre-aggregate x -> g_Ah (fp16), 1-term GEMM (tanh -> g_Ch) ---
    k_aggX<<<N, 64>>>(x, 256);
    k_conv_w<<<cdiv(256 * 1024, T), T>>>(W1, 256, 1024);
    gemm_tc<0, 3, 1><<<dim3(1024 / 128, RT), 256, 2 * 2 * MAT_B>>>(b1, nullptr, N, 256, 1024);

    // --- layer 2: 1-term GEMM (g_Ch -> g_Hh), aggregate -> A-pair ---
    k_conv_w<<<cdiv(1024 * 512, T), T>>>(W2, 1024, 512);
    gemm_tc<1, 0, 1><<<dim3(512 / 128, RT), 256, 2 * 2 * MAT_B>>>(nullptr, nullptr, N, 1024, 512);
    k_aggregate<0><<<N, 128>>>(b2, nullptr, 512);

    // --- layer 3: 2-term GEMM (A-pair -> g_Hh), aggregate -> A-pair + hout ---
    k_conv_w<<<cdiv(512 * 128, T), T>>>(W3, 512, 128);
    gemm_tc<0, 0, 2><<<dim3(1, RT), 256, 2 * 3 * MAT_B>>>(nullptr, nullptr, N, 512, 128);
    k_aggregate<1><<<N, 32>>>(b3, hout, 128);

    // --- classifier: 2-term GEMM (A-pair), sigmoid -> out[N,100] direct ---
    k_conv_wc<<<cdiv(128 * 128, T), T>>>(Wc, bc);
    gemm_tc<0, 1, 2><<<dim3(1, RT), 256, 2 * 3 * MAT_B>>>(nullptr, out, N, 128, 128);
}

// round 17
// speedup vs baseline: 6.8826x; 1.0607x over previous
#include <cuda_runtime.h>
#include <cuda_fp16.h>
#include <math.h>
#include <stdint.h>

// ---------------------------------------------------------------------------
// Problem constants
// ---------------------------------------------------------------------------
#define MAXN 100000
#define MAXE 400000
#define FMAX 1024
#define SCAN_ELEMS 1024
#define WMAXE (1024 * 1024)

// ---------------------------------------------------------------------------
// Device scratch
// ---------------------------------------------------------------------------
__device__ int   g_is64;
__device__ int   g_src[MAXE];
__device__ int   g_dst[MAXE];
__device__ int   g_cnt[MAXN];
__device__ int   g_cur[MAXN];
__device__ int   g_off[MAXN + 1];
__device__ int   g_bsum[512];
__device__ int   g_bsumx[512];
__device__ int2  g_csr[MAXE];                                   // {src, w bits}
__device__ float g_dis[MAXN];
__device__ float g_dinv[MAXN];
__device__ __align__(16) __half g_Hh[MAXN * FMAX];              // GEMM out (fp16)
__device__ __align__(16) __half g_Ah[MAXN * FMAX];              // GEMM operand A
__device__ __align__(16) __half g_Ch[MAXN * FMAX];              // L1 output (fp16)
__device__ __align__(16) __half g_Bh[WMAXE];                    // W^T fp16 [M,K]
__device__ float g_bcp[128];

// ---------------------------------------------------------------------------
// PTX helpers
// ---------------------------------------------------------------------------
__device__ __forceinline__ uint32_t smem_u32(const void* p) {
    uint32_t a;
    asm("{ .reg .u64 t; cvta.to.shared.u64 t, %1; cvt.u32.u64 %0, t; }"
        : "=r"(a) : "l"(p));
    return a;
}
template <int NW>
__device__ __forceinline__ void cpwait() {
    asm volatile("cp.async.wait_group %0;" :: "n"(NW) : "memory");
}
__device__ __forceinline__ void cpcommit() {
    asm volatile("cp.async.commit_group;" ::: "memory");
}
__device__ __forceinline__ void cpasync16(uint32_t sa, const void* gp, int size) {
    asm volatile("cp.async.cg.shared.global [%0], [%1], 16, %2;"
                 :: "r"(sa), "l"(gp), "r"(size) : "memory");
}
__device__ __forceinline__ void mma16816(float* d, const uint32_t* a, const uint32_t* b) {
    asm volatile(
        "mma.sync.aligned.m16n8k16.row.col.f32.f16.f16.f32 "
        "{%0,%1,%2,%3}, {%4,%5,%6,%7}, {%8,%9}, {%0,%1,%2,%3};"
        : "+f"(d[0]), "+f"(d[1]), "+f"(d[2]), "+f"(d[3])
        : "r"(a[0]), "r"(a[1]), "r"(a[2]), "r"(a[3]), "r"(b[0]), "r"(b[1]));
}
__device__ __forceinline__ void ldsm_x4(uint32_t* r, uint32_t addr) {
    asm volatile("ldmatrix.sync.aligned.m8n8.x4.shared.b16 {%0,%1,%2,%3}, [%4];"
                 : "=r"(r[0]), "=r"(r[1]), "=r"(r[2]), "=r"(r[3]) : "r"(addr));
}

// ---------------------------------------------------------------------------
// Edge-index sniff + decode (int32 OR int64)
// ---------------------------------------------------------------------------
__global__ void k_sniff(const int* __restrict__ ei) {
    if (threadIdx.x == 0 && blockIdx.x == 0) {
        int acc = 0;
#pragma unroll
        for (int i = 0; i < 64; i++) acc |= ei[2 * i + 1];
        g_is64 = (acc == 0) ? 1 : 0;
    }
}
__global__ void k_decode(const int* __restrict__ ei, int E) {
    int e = blockIdx.x * blockDim.x + threadIdx.x;
    if (e >= E) return;
    if (g_is64) { g_src[e] = ei[2 * e]; g_dst[e] = ei[2 * (E + e)]; }
    else        { g_src[e] = ei[e];     g_dst[e] = ei[E + e]; }
}

// ---------------------------------------------------------------------------
// Degree / CSR construction
// ---------------------------------------------------------------------------
__global__ void k_zero(int n) {
    int i = blockIdx.x * blockDim.x + threadIdx.x;
    if (i < n) { g_cnt[i] = 0; g_cur[i] = 0; }
}
__global__ void k_cnt(int E) {
    int e = blockIdx.x * blockDim.x + threadIdx.x;
    if (e < E) atomicAdd(&g_cnt[g_dst[e]], 1);
}
__global__ void k_deg_fin(int n) {
    int i = blockIdx.x * blockDim.x + threadIdx.x;
    if (i < n) {
        float d = (float)(g_cnt[i] + 1);
        g_dis[i]  = rsqrtf(d);
        g_dinv[i] = 1.0f / d;
    }
}
__global__ void k_scan1(int n) {
    __shared__ int sh[256];
    int base = blockIdx.x * SCAN_ELEMS;
    int t = threadIdx.x;
    int v[4]; int sum = 0;
#pragma unroll
    for (int i = 0; i < 4; i++) {
        int idx = base + t * 4 + i;
        int c = (idx < n) ? g_cnt[idx] : 0;
        v[i] = sum; sum += c;
    }
    sh[t] = sum; __syncthreads();
#pragma unroll
    for (int o = 1; o < 256; o <<= 1) {
        int x = 0;
        if (t >= o) x = sh[t - o];
        __syncthreads();
        if (t >= o) sh[t] += x;
        __syncthreads();
    }
    int excl = (t > 0) ? sh[t - 1] : 0;
#pragma unroll
    for (int i = 0; i < 4; i++) {
        int idx = base + t * 4 + i;
        if (idx < n) g_off[idx] = excl + v[i];
    }
    if (t == 255) g_bsum[blockIdx.x] = sh[255];
}
__global__ void k_scan2(int G, int n) {
    __shared__ int sh[512];
    int t = threadIdx.x;
    sh[t] = (t < G) ? g_bsum[t] : 0;
    __syncthreads();
#pragma unroll
    for (int o = 1; o < 512; o <<= 1) {
        int x = 0;
        if (t >= o) x = sh[t - o];
        __syncthreads();
        if (t >= o) sh[t] += x;
        __syncthreads();
    }
    if (t < G) g_bsumx[t] = (t > 0) ? sh[t - 1] : 0;
    if (t == 0) g_off[n] = sh[511];
}
__global__ void k_scan3(int n) {
    int idx = blockIdx.x * blockDim.x + threadIdx.x;
    if (idx < n) g_off[idx] += g_bsumx[idx / SCAN_ELEMS];
}
__global__ void k_fill(int E) {
    int e = blockIdx.x * blockDim.x + threadIdx.x;
    if (e >= E) return;
    int s = g_src[e], d = g_dst[e];
    int p = g_off[d] + atomicAdd(&g_cur[d], 1);
    g_csr[p] = make_int2(s, __float_as_int(g_dis[s] * g_dis[d]));
}

// ---------------------------------------------------------------------------
// Weight conversion (single fp16, transposed)
// ---------------------------------------------------------------------------
__global__ void k_conv_w(const float* __restrict__ W, int K, int M) {  // -> W^T [M,K]
    int idx = blockIdx.x * blockDim.x + threadIdx.x;
    if (idx >= K * M) return;
    int k = idx / M, m = idx - k * M;
    g_Bh[(size_t)m * K + k] = __float2half(W[idx]);
}
__global__ void k_conv_wc(const float* __restrict__ Wc, const float* __restrict__ bc) {
    int idx = blockIdx.x * blockDim.x + threadIdx.x;
    if (idx < 128 * 128) {
        int k = idx >> 7, m = idx & 127;
        float v = (m < 100) ? Wc[k * 100 + m] : 0.0f;
        g_Bh[m * 128 + k] = __float2half(v);
    }
    if (idx < 128) g_bcp[idx] = (idx < 100) ? bc[idx] : 0.0f;
}

// ---------------------------------------------------------------------------
// Layer-1 pre-aggregation on raw x (aggregation commutes with the GEMM):
// agg[d,f] = sum_in x[s,f]*w + x[d,f]*dinv[d]  -> single fp16 into g_Ah
// ---------------------------------------------------------------------------
__global__ void k_aggX(const float* __restrict__ x, int F) {
    const int d = blockIdx.x;
    const int f4 = threadIdx.x;
    const int f = f4 * 4;
    const int beg = g_off[d];
    const int end = g_off[d + 1];
    const int s4 = F >> 2;
    const float4* __restrict__ X4 = (const float4*)x;

    float4 acc = make_float4(0.f, 0.f, 0.f, 0.f);
    for (int p = beg; p < end; p++) {
        int2 sw = g_csr[p];
        float w = __int_as_float(sw.y);
        float4 h = X4[(size_t)sw.x * s4 + f4];
        acc.x = fmaf(h.x, w, acc.x);
        acc.y = fmaf(h.y, w, acc.y);
        acc.z = fmaf(h.z, w, acc.z);
        acc.w = fmaf(h.w, w, acc.w);
    }
    float dinv = g_dinv[d];
    float4 hd = X4[(size_t)d * s4 + f4];
    acc.x = fmaf(hd.x, dinv, acc.x);
    acc.y = fmaf(hd.y, dinv, acc.y);
    acc.z = fmaf(hd.z, dinv, acc.z);
    acc.w = fmaf(hd.w, dinv, acc.w);

    __half2* Ah2 = (__half2*)(g_Ah + (size_t)d * F + f);
    Ah2[0] = __halves2half2(__float2half(acc.x), __float2half(acc.y));
    Ah2[1] = __halves2half2(__float2half(acc.z), __float2half(acc.w));
}

// ---------------------------------------------------------------------------
// mma.sync fp16 GEMM (single-term A) with ldmatrix operand loads.
// C[Nrows,M] = A @ B^T.  ASEL 0: A = g_Ah;  ASEL 1: A = g_Ch.
// EPI 0: C -> g_Hh (fp16).
// EPI 1: sigmoid(C + g_bcp) -> Oext[N,100] direct (col<100 predicate).
// EPI 3: tanh(C + bias) -> g_Ch (fp16, layer-1 output).
// ---------------------------------------------------------------------------
#define SAH 40                    // smem stride in halves
#define MAT_B (128 * SAH * 2)     // 10240 B per matrix tile
#define BUFB  (2 * MAT_B)         // A, B
#define GEMM_DSM (2 * BUFB)       // 40960 B (double-buffered)

template <int ASEL, int EPI>
__global__ __launch_bounds__(256, 2) void gemm_tc(const float* __restrict__ bias,
                                                  float* __restrict__ Oext,
                                                  int Nrows, int K, int M) {
    extern __shared__ char dsm[];
    const uint32_t sb = smem_u32(dsm);

    const __half* __restrict__ Ah = (ASEL == 0) ? g_Ah : g_Ch;

    const int tid  = threadIdx.x;
    const int lane = tid & 31;
    const int w    = tid >> 5;
    const int wr   = w >> 2;
    const int wc   = w & 3;
    const int cBase = blockIdx.x * 128;
    const int rBase = blockIdx.y * 128;

    float acc[4][4][4];
#pragma unroll
    for (int a = 0; a < 4; a++)
#pragma unroll
        for (int b = 0; b < 4; b++)
#pragma unroll
            for (int c = 0; c < 4; c++) acc[a][b][c] = 0.0f;

    const int nch = K / 32;

    const int aRow = wr * 64 + (lane & 15);
    const int aK   = (lane >> 4) * 8;
    const int bRow = wc * 32 + (lane & 7) + ((lane & 16) ? 8 : 0);
    const int bK   = ((lane & 8) ? 8 : 0);

    auto load_chunk = [&](int c, int buf) {
        const int k0 = c * 32;
#pragma unroll
        for (int i = 0; i < 4; i++) {
            int seg = i * 256 + tid;            // 0..1023
            int mat = seg >> 9;                 // 0..1
            int s   = seg & 511;
            int row = s >> 2;
            int part = s & 3;
            uint32_t sa = sb + buf * BUFB + mat * MAT_B + row * (SAH * 2) + part * 16;
            const __half* gp;
            int size = 16;
            if (mat == 0) {
                int gr = rBase + row;
                int r2 = (gr < Nrows) ? gr : 0;
                size = (gr < Nrows) ? 16 : 0;
                gp = Ah + (size_t)r2 * K + k0 + part * 8;
            } else {
                int gc = cBase + row;
                gp = g_Bh + (size_t)gc * K + k0 + part * 8;
            }
            cpasync16(sa, gp, size);
        }
        cpcommit();
    };

    load_chunk(0, 0);

    for (int c = 0; c < nch; c++) {
        const int buf = c & 1;
        if (c + 1 < nch) { load_chunk(c + 1, (c + 1) & 1); cpwait<1>(); }
        else             { cpwait<0>(); }
        __syncthreads();

        const uint32_t bA_h = sb + buf * BUFB + 0 * MAT_B;
        const uint32_t bB_h = sb + buf * BUFB + 1 * MAT_B;

#pragma unroll
        for (int ks = 0; ks < 2; ks++) {
            const int kk = ks * 16;
            uint32_t bh[8];
            ldsm_x4(&bh[0], bB_h + ((bRow)      * SAH + kk + bK) * 2);
            ldsm_x4(&bh[4], bB_h + ((bRow + 16) * SAH + kk + bK) * 2);
#pragma unroll
            for (int mt = 0; mt < 4; mt++) {
                uint32_t ah[4];
                ldsm_x4(ah, bA_h + ((aRow + mt * 16) * SAH + kk + aK) * 2);
#pragma unroll
                for (int nt = 0; nt < 4; nt++)
                    mma16816(acc[mt][nt], ah, &bh[nt * 2]);
            }
        }
        __syncthreads();
    }

    // Epilogue
#pragma unroll
    for (int mt = 0; mt < 4; mt++) {
#pragma unroll
        for (int nt = 0; nt < 4; nt++) {
            const int row0 = rBase + wr * 64 + mt * 16 + (lane >> 2);
            const int col  = cBase + wc * 32 + nt * 8 + (lane & 3) * 2;
            float* a = acc[mt][nt];
            if (EPI == 0) {
                if (row0 < Nrows)
                    *(__half2*)&g_Hh[(size_t)row0 * M + col] =
                        __halves2half2(__float2half(a[0]), __float2half(a[1]));
                if (row0 + 8 < Nrows)
                    *(__half2*)&g_Hh[(size_t)(row0 + 8) * M + col] =
                        __halves2half2(__float2half(a[2]), __float2half(a[3]));
            } else if (EPI == 1) {
                if (col < 100) {
                    float s0 = 1.0f / (1.0f + expf(-(a[0] + g_bcp[col])));
                    float s1 = 1.0f / (1.0f + expf(-(a[1] + g_bcp[col + 1])));
                    float s2 = 1.0f / (1.0f + expf(-(a[2] + g_bcp[col])));
                    float s3 = 1.0f / (1.0f + expf(-(a[3] + g_bcp[col + 1])));
                    if (row0 < Nrows)
                        *(float2*)&Oext[(size_t)row0 * 100 + col] = make_float2(s0, s1);
                    if (row0 + 8 < Nrows)
                        *(float2*)&Oext[(size_t)(row0 + 8) * 100 + col] = make_float2(s2, s3);
                }
            } else {
                float b0 = bias[col], b1v = bias[col + 1];
                float v0 = tanhf(a[0] + b0);
                float v1 = tanhf(a[1] + b1v);
                float v2 = tanhf(a[2] + b0);
                float v3 = tanhf(a[3] + b1v);
                if (row0 < Nrows)
                    *(__half2*)&g_Ch[(size_t)row0 * M + col] =
                        __halves2half2(__float2half(v0), __float2half(v1));
                if (row0 + 8 < Nrows)
                    *(__half2*)&g_Ch[(size_t)(row0 + 8) * M + col] =
                        __halves2half2(__float2half(v2), __float2half(v3));
            }
        }
    }
}

// ---------------------------------------------------------------------------
// Fused aggregate (layers 2/3): one block per node, 4 cols per thread.
// Reads fp16 H (g_Hh), fp32 accumulation:
// v = tanh( sum_in H[s,f]*w + H[d,f]*dinv[d] + b[f] )  -> g_Ah (single fp16)
// Optional fp32 to Oext (layer 3 h output).
// ---------------------------------------------------------------------------
template <int WRITE_F32>
__global__ void k_aggregate(const float* __restrict__ bias, float* __restrict__ Oext,
                            int F) {
    const int d = blockIdx.x;
    const int f4 = threadIdx.x;
    const int f = f4 * 4;
    const int beg = g_off[d];
    const int end = g_off[d + 1];

    float4 acc = make_float4(0.f, 0.f, 0.f, 0.f);
    for (int p = beg; p < end; p++) {
        int2 sw = g_csr[p];
        float w = __int_as_float(sw.y);
        uint2 raw = *(const uint2*)(g_Hh + (size_t)sw.x * F + f);
        float2 p0 = __half22float2(*(__half2*)&raw.x);
        float2 p1 = __half22float2(*(__half2*)&raw.y);
        acc.x = fmaf(p0.x, w, acc.x);
        acc.y = fmaf(p0.y, w, acc.y);
        acc.z = fmaf(p1.x, w, acc.z);
        acc.w = fmaf(p1.y, w, acc.w);
    }
    float dinv = g_dinv[d];
    {
        uint2 raw = *(const uint2*)(g_Hh + (size_t)d * F + f);
        float2 p0 = __half22float2(*(__half2*)&raw.x);
        float2 p1 = __half22float2(*(__half2*)&raw.y);
        acc.x = fmaf(p0.x, dinv, acc.x);
        acc.y = fmaf(p0.y, dinv, acc.y);
        acc.z = fmaf(p1.x, dinv, acc.z);
        acc.w = fmaf(p1.y, dinv, acc.w);
    }
    float4 b = *(const float4*)&bias[f];
    float4 v;
    v.x = tanhf(acc.x + b.x);
    v.y = tanhf(acc.y + b.y);
    v.z = tanhf(acc.z + b.z);
    v.w = tanhf(acc.w + b.w);

    __half2* Ah2 = (__half2*)(g_Ah + (size_t)d * F + f);
    Ah2[0] = __halves2half2(__float2half(v.x), __float2half(v.y));
    Ah2[1] = __halves2half2(__float2half(v.z), __float2half(v.w));
    if (WRITE_F32) *(float4*)&Oext[(size_t)d * F + f] = v;
}

// ---------------------------------------------------------------------------
// Launch — pure kernel launches, graph-capturable
// ---------------------------------------------------------------------------
static inline int cdiv(int a, int b) { return (a + b - 1) / b; }

extern "C" void kernel_launch(void* const* d_in, const int* in_sizes, int n_in,
                              void* d_out, int out_size) {
    const float* x  = (const float*)d_in[0];
    const int*   ei = (const int*)d_in[1];
    const float* W1 = (const float*)d_in[2];
    const float* b1 = (const float*)d_in[3];
    const float* W2 = (const float*)d_in[4];
    const float* b2 = (const float*)d_in[5];
    const float* W3 = (const float*)d_in[6];
    const float* b3 = (const float*)d_in[7];
    const float* Wc = (const float*)d_in[8];
    const float* bc = (const float*)d_in[9];

    const int N = in_sizes[0] / 256;
    const int E = in_sizes[1] / 2;

    float* out  = (float*)d_out;                    // [N,100]
    float* hout = (float*)d_out + (size_t)N * 100;  // [N,128]

    const int T = 256;
    const int G = cdiv(N, SCAN_ELEMS);
    const int RT = cdiv(N, 128);

    cudaFuncSetAttribute((const void*)gemm_tc<0, 3>, cudaFuncAttributeMaxDynamicSharedMemorySize, GEMM_DSM);
    cudaFuncSetAttribute((const void*)gemm_tc<1, 0>, cudaFuncAttributeMaxDynamicSharedMemorySize, GEMM_DSM);
    cudaFuncSetAttribute((const void*)gemm_tc<0, 0>, cudaFuncAttributeMaxDynamicSharedMemorySize, GEMM_DSM);
    cudaFuncSetAttribute((const void*)gemm_tc<0, 1>, cudaFuncAttributeMaxDynamicSharedMemorySize, GEMM_DSM);

    // --- edges -> CSR, degrees ---
    k_sniff<<<1, 32>>>(ei);
    k_decode<<<cdiv(E, T), T>>>(ei, E);
    k_zero<<<cdiv(N, T), T>>>(N);
    k_cnt<<<cdiv(E, T), T>>>(E);
    k_deg_fin<<<cdiv(N, T), T>>>(N);
    k_scan1<<<G, 256>>>(N);
    k_scan2<<<1, 512>>>(G, N);
    k_scan3<<<cdiv(N, T), T>>>(N);
    k_fill<<<cdiv(E, T), T>>>(E);

    // --- layer 1: pre-aggregate x -> g_Ah (fp16), GEMM (tanh -> g_Ch) ---
    k_aggX<<<N, 64>>>(x, 256);
    k_conv_w<<<cdiv(256 * 1024, T), T>>>(W1, 256, 1024);
    gemm_tc<0, 3><<<dim3(1024 / 128, RT), 256, GEMM_DSM>>>(b1, nullptr, N, 256, 1024);

    // --- layer 2: GEMM (g_Ch -> g_Hh), aggregate -> g_Ah ---
    k_conv_w<<<cdiv(1024 * 512, T), T>>>(W2, 1024, 512);
    gemm_tc<1, 0><<<dim3(512 / 128, RT), 256, GEMM_DSM>>>(nullptr, nullptr, N, 1024, 512);
    k_aggregate<0><<<N, 128>>>(b2, nullptr, 512);

    // --- layer 3: GEMM (g_Ah -> g_Hh), aggregate -> g_Ah + hout ---
    k_conv_w<<<cdiv(512 * 128, T), T>>>(W3, 512, 128);
    gemm_tc<0, 0><<<dim3(1, RT), 256, GEMM_DSM>>>(nullptr, nullptr, N, 512, 128);
    k_aggregate<1><<<N, 32>>>(b3, hout, 128);

    // --- classifier: GEMM (g_Ah), sigmoid -> out[N,100] direct ---
    k_conv_wc<<<cdiv(128 * 128, T), T>>>(Wc, bc);
    gemm_tc<0, 1><<<dim3(1, RT), 256, GEMM_DSM>>>(nullptr, out, N, 128, 128);
}